// round 1
// baseline (speedup 1.0000x reference)
#include <cuda_runtime.h>
#include <cstdint>

// ---------------------------------------------------------------------------
// StockMixer fused kernel, GB300 sm_103a
//
// Pipeline:
//   kW : pre-transpose conv weights cw[o,i,kk] -> Wt[kk][i][o]   (tiny)
//   kA : per-stock fused (conv -> LN -> tri-matmul x2 -> fc) -> g_h (N,224)
//   kB1/kB2 : deterministic global mean/var of g_h  (the (N,MIX) LayerNorm
//             in the reference normalizes over BOTH dims -> scalar stats)
//   kC1/kC2 : gw[m] = sum_j w2[j]*hardswish( (M1 @ hn)[m,j] )   (two-stage,
//             deterministic; avoids materializing z)
//   kD : out[n] = sum_j h[n,j]*(w1[j]+w2[j]) + sum_m M2[n,m]*gw[m] + b
// ---------------------------------------------------------------------------

#define PITCH 132              // 128 + 4 float pad (528B rows: 16B aligned)
#define SBUF (128 * PITCH)     // one smem buffer (floats)

__device__ float g_Wt[7 * 16384];       // transposed conv weights (7 kk-slots)
__device__ float g_h[4096 * 224];       // mixed features h
__device__ float g_bpart[512];          // stage-1 LN partials (sum, sumsq)
__device__ float g_stats[2];            // mu, rinv of global LN
__device__ float g_cpart[128 * 64 * 224]; // stage-1 partials of M1@hn
__device__ float g_gw[64];              // gw[m]

typedef unsigned long long u64t;

__device__ __forceinline__ u64t pk2(float x, float y) {
    u64t r; asm("mov.b64 %0, {%1, %2};" : "=l"(r) : "f"(x), "f"(y)); return r;
}
__device__ __forceinline__ void upk2(u64t v, float& x, float& y) {
    asm("mov.b64 {%0, %1}, %2;" : "=f"(x), "=f"(y) : "l"(v));
}
// packed dual fp32 FMA (sm_100+): d = a*b + d
__device__ __forceinline__ void fma2(u64t& d, u64t a, u64t b) {
    asm("fma.rn.f32x2 %0, %1, %2, %0;" : "+l"(d) : "l"(a), "l"(b));
}
__device__ __forceinline__ float hswf(float v) {
    return v * fminf(fmaxf(v + 3.0f, 0.0f), 6.0f) * (1.0f / 6.0f);
}

// block reduce (sum, sumsq). scr needs >= 64 floats. All threads must call.
__device__ __forceinline__ void bred2(float& s, float& s2, float* scr) {
#pragma unroll
    for (int o = 16; o > 0; o >>= 1) {
        s  += __shfl_down_sync(0xffffffffu, s, o);
        s2 += __shfl_down_sync(0xffffffffu, s2, o);
    }
    int w = threadIdx.x >> 5, l = threadIdx.x & 31;
    if (l == 0) { scr[w] = s; scr[32 + w] = s2; }
    __syncthreads();
    if (threadIdx.x == 0) {
        float a = 0.f, b = 0.f;
        int nw = (blockDim.x + 31) >> 5;
        for (int i = 0; i < nw; i++) { a += scr[i]; b += scr[32 + i]; }
        scr[0] = a; scr[32] = b;
    }
    __syncthreads();
    s = scr[0]; s2 = scr[32];
}

// ---------------------------------------------------------------------------
// kW: transpose cw (F,F,k) -> per-kk [i][o] layout so staging is coalesced
// ---------------------------------------------------------------------------
__global__ void kW(const float* __restrict__ cw0,
                   const float* __restrict__ cw1,
                   const float* __restrict__ cw2) {
    int slot = blockIdx.x; // 0 | 1,2 | 3..6
    int si, kk;
    if (slot == 0)      { si = 0; kk = 0; }
    else if (slot < 3)  { si = 1; kk = slot - 1; }
    else                { si = 2; kk = slot - 3; }
    const float* cw = (si == 0) ? cw0 : (si == 1) ? cw1 : cw2;
    int k = 1 << si;
    float* dst = g_Wt + slot * 16384;
    for (int idx = threadIdx.x; idx < 16384; idx += blockDim.x) {
        int i = idx >> 7, o = idx & 127;
        dst[idx] = cw[(o * 128 + i) * k + kk];
    }
}

// ---------------------------------------------------------------------------
// kA helper: one scale, fully in shared memory.
// smem buffers: sXT (xt), sH (x then h), sWU (W staging then u)
// ---------------------------------------------------------------------------
template <int TK>
__device__ void process_scale(
    int n, const float* __restrict__ x, const float* __restrict__ Wt,
    const float* __restrict__ cb, const float* __restrict__ lg,
    const float* __restrict__ lb, const float* __restrict__ L1,
    const float* __restrict__ L2, const float* __restrict__ fcw, float fcb,
    float* __restrict__ hout, float* sXT, float* sH, float* sWU) {

    constexpr int K  = 128 / TK;   // conv kernel/stride
    constexpr int TM = TK / 16;    // rows per thread
    const int tid = threadIdx.x;
    const int ty = tid >> 4, tx = tid & 15;
    const int t0 = ty * TM, c0 = tx * 8;

    // ---- load x[n] (128x128) into sH ----
    for (int idx = tid; idx < 16384; idx += 256) {
        int t = idx >> 7, f = idx & 127;
        sH[t * PITCH + f] = x[(size_t)n * 16384 + idx];
    }

    // ---- conv: xt[t][o] = sum_{kk,i} x[t*K+kk][i] * W[kk][i][o] + cb[o] ----
    u64t acc[TM][4];
#pragma unroll
    for (int a = 0; a < TM; a++)
#pragma unroll
        for (int b = 0; b < 4; b++) acc[a][b] = 0ull;

    for (int kk = 0; kk < K; kk++) {
        __syncthreads();                       // prev users of sWU / x load done
        const float* Wk = Wt + kk * 16384;
        for (int idx = tid; idx < 16384; idx += 256) {
            int i = idx >> 7, o = idx & 127;
            sWU[i * PITCH + o] = Wk[idx];
        }
        __syncthreads();
#pragma unroll 2
        for (int i = 0; i < 128; i++) {
            const ulonglong2* wr = (const ulonglong2*)(sWU + i * PITCH + c0);
            ulonglong2 w01 = wr[0], w23 = wr[1];
            u64t wv[4] = { w01.x, w01.y, w23.x, w23.y };
#pragma unroll
            for (int a = 0; a < TM; a++) {
                float av = sH[((t0 + a) * K + kk) * PITCH + i];
                u64t a2 = pk2(av, av);
#pragma unroll
                for (int b = 0; b < 4; b++) fma2(acc[a][b], a2, wv[b]);
            }
        }
    }
    // bias + store xt
    {
        float2 bb[4];
#pragma unroll
        for (int b = 0; b < 4; b++) bb[b] = ((const float2*)(cb + c0))[b];
#pragma unroll
        for (int a = 0; a < TM; a++)
#pragma unroll
            for (int b = 0; b < 4; b++) {
                float lo, hi; upk2(acc[a][b], lo, hi);
                *(float2*)(sXT + (t0 + a) * PITCH + c0 + 2 * b) =
                    make_float2(lo + bb[b].x, hi + bb[b].y);
            }
    }
    __syncthreads();

    // ---- LayerNorm over (TK,128) ----
    float s = 0.f, s2 = 0.f;
    for (int idx = tid; idx < TK * 128; idx += 256) {
        float v = sXT[(idx >> 7) * PITCH + (idx & 127)];
        s += v; s2 += v * v;
    }
    bred2(s, s2, sWU);
    const float invc = 1.0f / (float)(TK * 128);
    float mu = s * invc;
    float var = s2 * invc - mu * mu;
    float rinv = rsqrtf(var + 1e-5f);
    for (int idx = tid; idx < TK * 128; idx += 256) {
        int t = idx >> 7, f = idx & 127;
        float v = sXT[t * PITCH + f];
        sH[t * PITCH + f] = (v - mu) * rinv * lg[idx] + lb[idx];
    }
    __syncthreads();

    // ---- GEMM1: u = hardswish( tril(L1) @ h ) -> sWU ----
#pragma unroll
    for (int a = 0; a < TM; a++)
#pragma unroll
        for (int b = 0; b < 4; b++) acc[a][b] = 0ull;
    const int tmax = t0 + TM - 1;
#pragma unroll 2
    for (int si = 0; si <= tmax; si++) {
        const ulonglong2* hr = (const ulonglong2*)(sH + si * PITCH + c0);
        ulonglong2 h01 = hr[0], h23 = hr[1];
        u64t hv[4] = { h01.x, h01.y, h23.x, h23.y };
#pragma unroll
        for (int a = 0; a < TM; a++) {
            float lv = (si <= t0 + a) ? L1[(t0 + a) * TK + si] : 0.f;
            u64t l2v = pk2(lv, lv);
#pragma unroll
            for (int b = 0; b < 4; b++) fma2(acc[a][b], l2v, hv[b]);
        }
    }
#pragma unroll
    for (int a = 0; a < TM; a++)
#pragma unroll
        for (int b = 0; b < 4; b++) {
            float lo, hi; upk2(acc[a][b], lo, hi);
            *(float2*)(sWU + (t0 + a) * PITCH + c0 + 2 * b) =
                make_float2(hswf(lo), hswf(hi));
        }
    __syncthreads();

    // ---- GEMM2: xt += tril(L2) @ u ----
#pragma unroll
    for (int a = 0; a < TM; a++)
#pragma unroll
        for (int b = 0; b < 4; b++) acc[a][b] = 0ull;
#pragma unroll 2
    for (int si = 0; si <= tmax; si++) {
        const ulonglong2* ur = (const ulonglong2*)(sWU + si * PITCH + c0);
        ulonglong2 u01 = ur[0], u23 = ur[1];
        u64t uv[4] = { u01.x, u01.y, u23.x, u23.y };
#pragma unroll
        for (int a = 0; a < TM; a++) {
            float lv = (si <= t0 + a) ? L2[(t0 + a) * TK + si] : 0.f;
            u64t l2v = pk2(lv, lv);
#pragma unroll
            for (int b = 0; b < 4; b++) fma2(acc[a][b], l2v, uv[b]);
        }
    }
#pragma unroll
    for (int a = 0; a < TM; a++)
#pragma unroll
        for (int b = 0; b < 4; b++) {
            float lo, hi; upk2(acc[a][b], lo, hi);
            float2* p = (float2*)(sXT + (t0 + a) * PITCH + c0 + 2 * b);
            float2 o = *p;
            *p = make_float2(o.x + lo, o.y + hi);
        }
    __syncthreads();

    // ---- fc: part[t] = xt[t][:] . fcw + fcb ----
    if (tid < TK) {
        float d = 0.f;
#pragma unroll 4
        for (int f = 0; f < 128; f++) d += sXT[tid * PITCH + f] * fcw[f];
        hout[tid] = d + fcb;
    }
    __syncthreads();
}

__global__ void __launch_bounds__(256) kA(
    const float* __restrict__ x,
    const float* __restrict__ cb0, const float* __restrict__ lg0,
    const float* __restrict__ lb0, const float* __restrict__ L10,
    const float* __restrict__ L20,
    const float* __restrict__ cb1, const float* __restrict__ lg1,
    const float* __restrict__ lb1, const float* __restrict__ L11,
    const float* __restrict__ L21,
    const float* __restrict__ cb2, const float* __restrict__ lg2,
    const float* __restrict__ lb2, const float* __restrict__ L12,
    const float* __restrict__ L22,
    const float* __restrict__ fcw, const float* __restrict__ fcb) {
    extern __shared__ float sm[];
    float* sXT = sm;
    float* sH  = sm + SBUF;
    float* sWU = sm + 2 * SBUF;
    int n = blockIdx.x;
    float fcbv = fcb[0];
    float* hrow = g_h + (size_t)n * 224;
    process_scale<128>(n, x, g_Wt + 0 * 16384, cb0, lg0, lb0, L10, L20,
                       fcw, fcbv, hrow + 0,   sXT, sH, sWU);
    process_scale<64>(n, x, g_Wt + 1 * 16384, cb1, lg1, lb1, L11, L21,
                      fcw, fcbv, hrow + 128, sXT, sH, sWU);
    process_scale<32>(n, x, g_Wt + 3 * 16384, cb2, lg2, lb2, L12, L22,
                      fcw, fcbv, hrow + 192, sXT, sH, sWU);
}

// ---------------------------------------------------------------------------
// kB1/kB2: deterministic global mean/var of g_h (4096x224)
// ---------------------------------------------------------------------------
__global__ void kB1() {
    float s = 0.f, s2 = 0.f;
    int base = blockIdx.x * 16 * 224;       // 16 rows per block, 256 blocks
    for (int idx = threadIdx.x; idx < 16 * 224; idx += 256) {
        float v = g_h[base + idx];
        s += v; s2 += v * v;
    }
    __shared__ float scr[64];
    bred2(s, s2, scr);
    if (threadIdx.x == 0) { g_bpart[blockIdx.x] = s; g_bpart[256 + blockIdx.x] = s2; }
}

__global__ void kB2() {
    float s = g_bpart[threadIdx.x];
    float s2 = g_bpart[256 + threadIdx.x];
    __shared__ float scr[64];
    bred2(s, s2, scr);
    if (threadIdx.x == 0) {
        const float inv = 1.0f / (4096.0f * 224.0f);
        float mu = s * inv;
        float var = s2 * inv - mu * mu;
        g_stats[0] = mu;
        g_stats[1] = rsqrtf(var + 1e-5f);
    }
}

// ---------------------------------------------------------------------------
// kC1: partial (M1 @ hn) over n-chunks of 32. grid=128, block=224 (j)
// ---------------------------------------------------------------------------
__global__ void kC1(const float* __restrict__ M1,
                    const float* __restrict__ slg,
                    const float* __restrict__ slb) {
    int j = threadIdx.x;           // 0..223
    int b = blockIdx.x;            // 0..127
    float mu = g_stats[0], rinv = g_stats[1];
    float acc[64];
#pragma unroll
    for (int m = 0; m < 64; m++) acc[m] = 0.f;
    int n0 = b * 32;
    for (int n = n0; n < n0 + 32; n++) {
        int off = n * 224 + j;
        float hn = (g_h[off] - mu) * rinv * slg[off] + slb[off];
#pragma unroll
        for (int m = 0; m < 64; m++) acc[m] += M1[m * 4096 + n] * hn;
    }
#pragma unroll
    for (int m = 0; m < 64; m++) g_cpart[(b * 64 + m) * 224 + j] = acc[m];
}

// kC2: reduce partials, hardswish, contract with w2 -> gw[m]. grid=64, block=224
__global__ void kC2(const float* __restrict__ smw) {
    int m = blockIdx.x, j = threadIdx.x;
    float g = 0.f;
    for (int b = 0; b < 128; b++) g += g_cpart[(b * 64 + m) * 224 + j];
    float v = hswf(g) * smw[224 + j];
    float dummy = 0.f;
    __shared__ float scr[64];
    bred2(v, dummy, scr);
    if (threadIdx.x == 0) g_gw[m] = v;
}

// ---------------------------------------------------------------------------
// kD: out[n] = h[n,:].(w1+w2) + M2[n,:].gw + b  -- one warp per row
// ---------------------------------------------------------------------------
__global__ void kD(const float* __restrict__ M2,
                   const float* __restrict__ smw,
                   const float* __restrict__ smb,
                   float* __restrict__ out) {
    int warp = threadIdx.x >> 5, lane = threadIdx.x & 31;
    int n = blockIdx.x * 8 + warp;
    float acc = 0.f;
    for (int j = lane; j < 224; j += 32)
        acc += g_h[n * 224 + j] * (smw[j] + smw[224 + j]);
    for (int m = lane; m < 64; m += 32)
        acc += M2[n * 64 + m] * g_gw[m];
#pragma unroll
    for (int o = 16; o > 0; o >>= 1)
        acc += __shfl_down_sync(0xffffffffu, acc, o);
    if (lane == 0) out[n] = acc + smb[0];
}

// ---------------------------------------------------------------------------
extern "C" void kernel_launch(void* const* d_in, const int* in_sizes, int n_in,
                              void* d_out, int out_size) {
    const float* x   = (const float*)d_in[0];
    const float* cw0 = (const float*)d_in[1];
    const float* cb0 = (const float*)d_in[2];
    const float* lg0 = (const float*)d_in[3];
    const float* lb0 = (const float*)d_in[4];
    const float* L10 = (const float*)d_in[5];
    const float* L20 = (const float*)d_in[6];
    const float* cw1 = (const float*)d_in[7];
    const float* cb1 = (const float*)d_in[8];
    const float* lg1 = (const float*)d_in[9];
    const float* lb1 = (const float*)d_in[10];
    const float* L11 = (const float*)d_in[11];
    const float* L21 = (const float*)d_in[12];
    const float* cw2 = (const float*)d_in[13];
    const float* cb2 = (const float*)d_in[14];
    const float* lg2 = (const float*)d_in[15];
    const float* lb2 = (const float*)d_in[16];
    const float* L12 = (const float*)d_in[17];
    const float* L22 = (const float*)d_in[18];
    const float* fcw = (const float*)d_in[19];
    const float* fcb = (const float*)d_in[20];
    const float* slg = (const float*)d_in[21];
    const float* slb = (const float*)d_in[22];
    const float* M1  = (const float*)d_in[23];
    const float* M2  = (const float*)d_in[24];
    const float* smw = (const float*)d_in[25];
    const float* smb = (const float*)d_in[26];
    float* out = (float*)d_out;

    cudaFuncSetAttribute(kA, cudaFuncAttributeMaxDynamicSharedMemorySize,
                         3 * SBUF * 4);

    kW<<<7, 256>>>(cw0, cw1, cw2);
    kA<<<4096, 256, 3 * SBUF * 4>>>(x,
        cb0, lg0, lb0, L10, L20,
        cb1, lg1, lb1, L11, L21,
        cb2, lg2, lb2, L12, L22,
        fcw, fcb);
    kB1<<<256, 256>>>();
    kB2<<<1, 256>>>();
    kC1<<<128, 224>>>(M1, slg, slb);
    kC2<<<64, 224>>>(smw);
    kD<<<512, 256>>>(M2, smw, smb, out);
}

// round 3
// speedup vs baseline: 1.8651x; 1.8651x over previous
#include <cuda_runtime.h>
#include <cuda_bf16.h>
#include <cstdint>

// ============================================================================
// StockMixer on GB300 — mma.sync (HMMA bf16, hi/lo 3-term) implementation.
// tcgen05 is unavailable: harness PTX target is compute_103 (no 'a' features).
//
//  kW  : precompute conv-weight chunks + masked block-diagonal L tiles as
//        hi/lo-interleaved, slot-permuted bf16 images (fragment-load layout).
//  kA3 : per 4 stocks: conv GEMM -> LN -> L1 GEMM -> hsw -> L2 GEMM -> fc,
//        all via warp-level m16n8k16 bf16 MMAs with register accumulators.
//  kB/kC/kD : phase-2 stock mixing (unchanged, passed in R1).
// ============================================================================

#define PW 144                        // image row pitch, 32-bit words
#define IMG_WORDS (128 * PW)          // 18432 words = 73728 B
#define IMG_A_OFF 0
#define IMG_B_OFF (IMG_WORDS * 4)     // 73728
#define BUF_X_OFF (2 * IMG_WORDS * 4) // 147456
#define XPITCH 129                    // fp32 buffer pitch (odd words: no bank dup)
#define SCR_OFF (BUF_X_OFF + 128 * XPITCH * 4)  // 213504
#define SMEM_SZ (SCR_OFF + 1280)      // 214784 bytes

// -------------------- device globals --------------------
__device__ __align__(16) uint32_t g_Wimg[7][IMG_WORDS];
__device__ __align__(16) uint32_t g_Limg[6][IMG_WORDS];

__device__ float g_h[4096 * 224];
__device__ float g_bpart[512];
__device__ float g_stats[2];
__device__ float g_cpart[128 * 64 * 224];
__device__ float g_gw[64];

// -------------------- helpers --------------------
__device__ __forceinline__ float hswf(float v) {
    return v * fminf(fmaxf(v + 3.0f, 0.0f), 6.0f) * (1.0f / 6.0f);
}

// word offset within an image row for even k: chunk*16 + slot*2.
// slot permutation groups k-pairs (c, c+4) adjacently so a 16B load yields
// {hi(k=2c), lo(k=2c), hi(k=2c+8), lo(k=2c+8)} = the a0/a2 (or b0/b1) frags.
__device__ __forceinline__ int wslot(int k) {
    int q = (k >> 1) & 7;
    int slot = ((q & 3) << 1) | (q >> 2);
    return ((k >> 4) << 4) + (slot << 1);
}

__device__ __forceinline__ void split2(float v0, float v1,
                                       uint32_t& hi, uint32_t& lo) {
    __nv_bfloat162 h, l;
    h.x = __float2bfloat16(v0);
    h.y = __float2bfloat16(v1);
    l.x = __float2bfloat16(v0 - __bfloat162float(h.x));
    l.y = __float2bfloat16(v1 - __bfloat162float(h.y));
    hi = *(uint32_t*)&h;
    lo = *(uint32_t*)&l;
}

// scalar hi/lo write of one element (row, k) into an image
__device__ __forceinline__ void wr16(uint32_t* img, int row, int k, float v) {
    __nv_bfloat16 h = __float2bfloat16(v);
    __nv_bfloat16 l = __float2bfloat16(v - __bfloat162float(h));
    int w = row * PW + wslot(k);
    char* p = (char*)(img + w) + ((k & 1) << 1);
    *(__nv_bfloat16*)p = h;        // hi word
    *(__nv_bfloat16*)(p + 4) = l;  // lo word (w+1)
}

__device__ __forceinline__ void mma16816(float* d, uint32_t a0, uint32_t a1,
                                         uint32_t a2, uint32_t a3,
                                         uint32_t b0, uint32_t b1) {
    asm volatile(
        "mma.sync.aligned.m16n8k16.row.col.f32.bf16.bf16.f32 "
        "{%0,%1,%2,%3}, {%4,%5,%6,%7}, {%8,%9}, {%0,%1,%2,%3};"
        : "+f"(d[0]), "+f"(d[1]), "+f"(d[2]), "+f"(d[3])
        : "r"(a0), "r"(a1), "r"(a2), "r"(a3), "r"(b0), "r"(b1));
}

// one m16-tile x 64-col GEMM slice over k-chunks [ks0, ks1), 3-term hi/lo
__device__ __forceinline__ void gemm_tile(const uint32_t* __restrict__ sA,
                                          const uint32_t* __restrict__ sB,
                                          float (&acc)[8][4], int mt, int c0,
                                          int ks0, int ks1, int g, int c) {
    for (int ks = ks0; ks < ks1; ks++) {
        int kb = (ks << 4) + (c << 2);
        const uint32_t* ap = sA + (mt * 16 + g) * PW + kb;
        uint4 va0 = *(const uint4*)ap;            // a0hi,a0lo,a2hi,a2lo
        uint4 va1 = *(const uint4*)(ap + 8 * PW); // a1hi,a1lo,a3hi,a3lo
#pragma unroll
        for (int nt = 0; nt < 8; nt++) {
            uint4 vb = *(const uint4*)(sB + (c0 + nt * 8 + g) * PW + kb);
            mma16816(acc[nt], va0.x, va1.x, va0.z, va1.z, vb.x, vb.z); // hh
            mma16816(acc[nt], va0.x, va1.x, va0.z, va1.z, vb.y, vb.w); // hl
            mma16816(acc[nt], va0.y, va1.y, va0.w, va1.w, vb.x, vb.z); // lh
        }
    }
}

// ============================================================================
// kW: precompute operand images in gmem
// ============================================================================
__global__ void kW(const float* __restrict__ cw0, const float* __restrict__ cw1,
                   const float* __restrict__ cw2,
                   const float* __restrict__ L10, const float* __restrict__ L20,
                   const float* __restrict__ L11, const float* __restrict__ L21,
                   const float* __restrict__ L12, const float* __restrict__ L22) {
    int b = blockIdx.x;
    if (b < 7) {
        int s, kk;
        if (b == 0)      { s = 0; kk = 0; }
        else if (b < 3)  { s = 1; kk = b - 1; }
        else             { s = 2; kk = b - 3; }
        const float* cw = (s == 0) ? cw0 : (s == 1) ? cw1 : cw2;
        int k = 1 << s;
        uint32_t* dst = g_Wimg[b];
        for (int idx = threadIdx.x; idx < 128 * 64; idx += blockDim.x) {
            int o = idx >> 6, i = (idx & 63) << 1;   // img row = o, k = i
            float v0 = cw[(o * 128 + i) * k + kk];
            float v1 = cw[(o * 128 + i + 1) * k + kk];
            uint32_t hi, lo;
            split2(v0, v1, hi, lo);
            int wd = o * PW + wslot(i);
            dst[wd] = hi; dst[wd + 1] = lo;
        }
    } else {
        int j = b - 7;                 // 0..5: [scale*2 + {L1,L2}]
        int s = j >> 1, m = j & 1;
        const float* L = (s == 0) ? (m ? L20 : L10)
                       : (s == 1) ? (m ? L21 : L11)
                                  : (m ? L22 : L12);
        int tk = 128 >> s;
        uint32_t* dst = g_Limg[j];
        for (int idx = threadIdx.x; idx < 128 * 64; idx += blockDim.x) {
            int t = idx >> 6, sc = (idx & 63) << 1;  // img row = t, k = s-index
            float v[2];
#pragma unroll
            for (int e = 0; e < 2; e++) {
                int scc = sc + e;
                float vv = 0.0f;
                if ((t / tk) == (scc / tk)) {
                    int tp = t % tk, sp = scc % tk;
                    if (sp <= tp) vv = L[tp * tk + sp];
                }
                v[e] = vv;
            }
            uint32_t hi, lo;
            split2(v[0], v[1], hi, lo);
            int wd = t * PW + wslot(sc);
            dst[wd] = hi; dst[wd + 1] = lo;
        }
    }
}

// ============================================================================
// kA3: fused per-4-stock pipeline
// ============================================================================
template <int TK>
__device__ void run_scale(const float* __restrict__ x, int n0,
                          const float* __restrict__ cb,
                          const float* __restrict__ lg,
                          const float* __restrict__ lb, int q0,
                          const uint32_t* __restrict__ L1img,
                          const uint32_t* __restrict__ L2img, int hoff,
                          float fcb, char* sm) {
    constexpr int K = 128 / TK;           // conv chunks (= scale factor)
    const int tid = threadIdx.x;
    const int w = tid >> 5, lane = tid & 31;
    const int w3 = w & 3;
    const int g = lane >> 2, c = lane & 3;
    const int c0 = (w >> 2) * 64;

    // balanced triangular tile pairing
    int mta, mtb;
    if (TK == 128)     { mta = w3;                          mtb = 7 - w3; }
    else if (TK == 64) { mta = ((w3 >> 1) << 2) + (w3 & 1); mtb = ((w3 >> 1) << 2) + 3 - (w3 & 1); }
    else               { mta = w3 << 1;                     mtb = (w3 << 1) + 1; }
    const int myg = (TK == 128) ? 0 : (TK == 64 ? (w3 >> 1) : w3);

    uint32_t* imgA = (uint32_t*)(sm + IMG_A_OFF);
    uint32_t* imgB = (uint32_t*)(sm + IMG_B_OFF);
    float* bufX = (float*)(sm + BUF_X_OFF);
    float* scr = (float*)(sm + SCR_OFF);
    float* s_fcw = scr + 16;
    float* s_cb = scr + 144;

    if (tid < 128) s_cb[tid] = cb[tid];   // first sync below covers this

    float acc[2][8][4];
#pragma unroll
    for (int a = 0; a < 2; a++)
#pragma unroll
        for (int b = 0; b < 8; b++)
#pragma unroll
            for (int e = 0; e < 4; e++) acc[a][b][e] = 0.0f;

    // ---------------- conv: accumulate over K chunks ----------------
    for (int kk = 0; kk < K; kk++) {
        // build A image from x (coalesced gmem float4 reads)
#pragma unroll 2
        for (int it = 0; it < 16; it++) {
            int idx = it * 256 + tid;          // float4 id over 128 rows x 32
            int r = idx >> 5, f4 = idx & 31;
            int stock = n0 + r / TK;
            int srcrow = (r % TK) * K + kk;
            float4 v = ((const float4*)(x + ((size_t)stock * 128 + srcrow) * 128))[f4];
            int kbase = f4 << 2;
            uint32_t hi, lo;
            split2(v.x, v.y, hi, lo);
            int wd = r * PW + wslot(kbase);
            imgA[wd] = hi; imgA[wd + 1] = lo;
            split2(v.z, v.w, hi, lo);
            wd = r * PW + wslot(kbase + 2);
            imgA[wd] = hi; imgA[wd + 1] = lo;
        }
        // copy W chunk image (L2-resident)
        {
            const uint4* src = (const uint4*)g_Wimg[q0 + kk];
            uint4* dst = (uint4*)imgB;
#pragma unroll
            for (int j = 0; j < 18; j++) dst[tid + 256 * j] = src[tid + 256 * j];
        }
        __syncthreads();
        gemm_tile(imgA, imgB, acc[0], mta, c0, 0, 8, g, c);
        gemm_tile(imgA, imgB, acc[1], mtb, c0, 0, 8, g, c);
        __syncthreads();
    }

    // ---------------- xt = acc + cb -> bufX; LN partial sums ----------------
    float s = 0.0f, s2 = 0.0f;
#pragma unroll
    for (int ti = 0; ti < 2; ti++) {
        int mt = ti ? mtb : mta;
#pragma unroll
        for (int nt = 0; nt < 8; nt++)
#pragma unroll
            for (int e = 0; e < 4; e++) {
                int t = mt * 16 + g + ((e >> 1) << 3);
                int f = c0 + nt * 8 + (c << 1) + (e & 1);
                float v = acc[ti][nt][e] + s_cb[f];
                bufX[t * XPITCH + f] = v;
                s += v; s2 += v * v;
            }
    }
#pragma unroll
    for (int o = 16; o; o >>= 1) {
        s  += __shfl_down_sync(0xffffffffu, s, o);
        s2 += __shfl_down_sync(0xffffffffu, s2, o);
    }
    if (lane == 0) { scr[w] = s; scr[8 + w] = s2; }
    __syncthreads();

    // group stats for this warp's stock group
    float gs = 0.0f, gs2 = 0.0f;
#pragma unroll
    for (int p = 0; p < 4; p++) {
        int pg = (TK == 128) ? 0 : (TK == 64 ? (p >> 1) : p);
        if (pg == myg) { gs += scr[p] + scr[p + 4]; gs2 += scr[8 + p] + scr[12 + p]; }
    }
    const float inv = 1.0f / (float)(TK * 128);
    float mu = gs * inv;
    float var = gs2 * inv - mu * mu;
    float rinv = rsqrtf(var + 1e-5f);

    // ---------------- h^T (rows=f, k=t) into imgB; copy L1 into imgA --------
#pragma unroll
    for (int ti = 0; ti < 2; ti++) {
        int mt = ti ? mtb : mta;
#pragma unroll
        for (int nt = 0; nt < 8; nt++)
#pragma unroll
            for (int e = 0; e < 4; e++) {
                int t = mt * 16 + g + ((e >> 1) << 3);
                int f = c0 + nt * 8 + (c << 1) + (e & 1);
                int tl = t % TK;
                float v = acc[ti][nt][e] + s_cb[f];
                float hh = (v - mu) * rinv * lg[tl * 128 + f] + lb[tl * 128 + f];
                wr16(imgB, f, t, hh);
            }
    }
    {
        const uint4* src = (const uint4*)L1img;
        uint4* dst = (uint4*)imgA;
#pragma unroll
        for (int j = 0; j < 18; j++) dst[tid + 256 * j] = src[tid + 256 * j];
    }
    __syncthreads();

    // ---------------- GEMM1: u = L1m @ h (triangular bounds) ----------------
#pragma unroll
    for (int a = 0; a < 2; a++)
#pragma unroll
        for (int b = 0; b < 8; b++)
#pragma unroll
            for (int e = 0; e < 4; e++) acc[a][b][e] = 0.0f;
    gemm_tile(imgA, imgB, acc[0], mta, c0, (myg * TK) >> 4, mta + 1, g, c);
    gemm_tile(imgA, imgB, acc[1], mtb, c0, (myg * TK) >> 4, mtb + 1, g, c);
    __syncthreads();

    // ---------------- u^T = hsw(u) into imgB; copy L2 into imgA -------------
#pragma unroll
    for (int ti = 0; ti < 2; ti++) {
        int mt = ti ? mtb : mta;
#pragma unroll
        for (int nt = 0; nt < 8; nt++)
#pragma unroll
            for (int e = 0; e < 4; e++) {
                int t = mt * 16 + g + ((e >> 1) << 3);
                int f = c0 + nt * 8 + (c << 1) + (e & 1);
                wr16(imgB, f, t, hswf(acc[ti][nt][e]));
            }
    }
    {
        const uint4* src = (const uint4*)L2img;
        uint4* dst = (uint4*)imgA;
#pragma unroll
        for (int j = 0; j < 18; j++) dst[tid + 256 * j] = src[tid + 256 * j];
    }
    __syncthreads();

    // ---------------- GEMM2: v = L2m @ u; xt += v ---------------------------
#pragma unroll
    for (int a = 0; a < 2; a++)
#pragma unroll
        for (int b = 0; b < 8; b++)
#pragma unroll
            for (int e = 0; e < 4; e++) acc[a][b][e] = 0.0f;
    gemm_tile(imgA, imgB, acc[0], mta, c0, (myg * TK) >> 4, mta + 1, g, c);
    gemm_tile(imgA, imgB, acc[1], mtb, c0, (myg * TK) >> 4, mtb + 1, g, c);
#pragma unroll
    for (int ti = 0; ti < 2; ti++) {
        int mt = ti ? mtb : mta;
#pragma unroll
        for (int nt = 0; nt < 8; nt++)
#pragma unroll
            for (int e = 0; e < 4; e++) {
                int t = mt * 16 + g + ((e >> 1) << 3);
                int f = c0 + nt * 8 + (c << 1) + (e & 1);
                bufX[t * XPITCH + f] += acc[ti][nt][e];
            }
    }
    __syncthreads();

    // ---------------- fc dot -> g_h ----------------
    {
        int t = tid >> 1, fh = (tid & 1) << 6;
        float d = 0.0f;
#pragma unroll 4
        for (int f = 0; f < 64; f++)
            d += bufX[t * XPITCH + fh + f] * s_fcw[fh + f];
        d += __shfl_xor_sync(0xffffffffu, d, 1);
        if ((tid & 1) == 0)
            g_h[(n0 + t / TK) * 224 + hoff + (t % TK)] = d + fcb;
    }
    __syncthreads();
}

__global__ void __launch_bounds__(256, 1) kA3(
    const float* __restrict__ x,
    const float* __restrict__ cb0, const float* __restrict__ lg0,
    const float* __restrict__ lb0,
    const float* __restrict__ cb1, const float* __restrict__ lg1,
    const float* __restrict__ lb1,
    const float* __restrict__ cb2, const float* __restrict__ lg2,
    const float* __restrict__ lb2,
    const float* __restrict__ fcw, const float* __restrict__ fcbp) {
    extern __shared__ char sm[];
    float* scr = (float*)(sm + SCR_OFF);
    if (threadIdx.x < 128) scr[16 + threadIdx.x] = fcw[threadIdx.x];
    float fcb = fcbp[0];
    int n0 = blockIdx.x * 4;

    run_scale<128>(x, n0 + 0, cb0, lg0, lb0, 0, g_Limg[0], g_Limg[1], 0, fcb, sm);
    run_scale<128>(x, n0 + 1, cb0, lg0, lb0, 0, g_Limg[0], g_Limg[1], 0, fcb, sm);
    run_scale<128>(x, n0 + 2, cb0, lg0, lb0, 0, g_Limg[0], g_Limg[1], 0, fcb, sm);
    run_scale<128>(x, n0 + 3, cb0, lg0, lb0, 0, g_Limg[0], g_Limg[1], 0, fcb, sm);

    run_scale<64>(x, n0 + 0, cb1, lg1, lb1, 1, g_Limg[2], g_Limg[3], 128, fcb, sm);
    run_scale<64>(x, n0 + 2, cb1, lg1, lb1, 1, g_Limg[2], g_Limg[3], 128, fcb, sm);

    run_scale<32>(x, n0 + 0, cb2, lg2, lb2, 3, g_Limg[4], g_Limg[5], 192, fcb, sm);
}

// ============================================================================
// phase 2 (unchanged — correct, tiny)
// ============================================================================
__device__ __forceinline__ void bred2(float& s, float& s2, float* scr) {
#pragma unroll
    for (int o = 16; o > 0; o >>= 1) {
        s  += __shfl_down_sync(0xffffffffu, s, o);
        s2 += __shfl_down_sync(0xffffffffu, s2, o);
    }
    int w = threadIdx.x >> 5, l = threadIdx.x & 31;
    if (l == 0) { scr[w] = s; scr[32 + w] = s2; }
    __syncthreads();
    if (threadIdx.x == 0) {
        float a = 0.f, b = 0.f;
        int nw = (blockDim.x + 31) >> 5;
        for (int i = 0; i < nw; i++) { a += scr[i]; b += scr[32 + i]; }
        scr[0] = a; scr[32] = b;
    }
    __syncthreads();
    s = scr[0]; s2 = scr[32];
}

__global__ void kB1() {
    float s = 0.f, s2 = 0.f;
    int base = blockIdx.x * 16 * 224;
    for (int idx = threadIdx.x; idx < 16 * 224; idx += 256) {
        float v = g_h[base + idx];
        s += v; s2 += v * v;
    }
    __shared__ float scr[64];
    bred2(s, s2, scr);
    if (threadIdx.x == 0) { g_bpart[blockIdx.x] = s; g_bpart[256 + blockIdx.x] = s2; }
}

__global__ void kB2() {
    float s = g_bpart[threadIdx.x];
    float s2 = g_bpart[256 + threadIdx.x];
    __shared__ float scr[64];
    bred2(s, s2, scr);
    if (threadIdx.x == 0) {
        const float inv = 1.0f / (4096.0f * 224.0f);
        float mu = s * inv;
        float var = s2 * inv - mu * mu;
        g_stats[0] = mu;
        g_stats[1] = rsqrtf(var + 1e-5f);
    }
}

__global__ void kC1(const float* __restrict__ M1,
                    const float* __restrict__ slg,
                    const float* __restrict__ slb) {
    int j = threadIdx.x;
    int b = blockIdx.x;
    float mu = g_stats[0], rinv = g_stats[1];
    float acc[64];
#pragma unroll
    for (int m = 0; m < 64; m++) acc[m] = 0.f;
    int n0 = b * 32;
    for (int n = n0; n < n0 + 32; n++) {
        int off = n * 224 + j;
        float hn = (g_h[off] - mu) * rinv * slg[off] + slb[off];
#pragma unroll
        for (int m = 0; m < 64; m++) acc[m] += M1[m * 4096 + n] * hn;
    }
#pragma unroll
    for (int m = 0; m < 64; m++) g_cpart[(b * 64 + m) * 224 + j] = acc[m];
}

__global__ void kC2(const float* __restrict__ smw) {
    int m = blockIdx.x, j = threadIdx.x;
    float g = 0.f;
    for (int b = 0; b < 128; b++) g += g_cpart[(b * 64 + m) * 224 + j];
    float v = hswf(g) * smw[224 + j];
    float dummy = 0.f;
    __shared__ float scr[64];
    bred2(v, dummy, scr);
    if (threadIdx.x == 0) g_gw[m] = v;
}

__global__ void kD(const float* __restrict__ M2,
                   const float* __restrict__ smw,
                   const float* __restrict__ smb,
                   float* __restrict__ out) {
    int warp = threadIdx.x >> 5, lane = threadIdx.x & 31;
    int n = blockIdx.x * 8 + warp;
    float acc = 0.f;
    for (int j = lane; j < 224; j += 32)
        acc += g_h[n * 224 + j] * (smw[j] + smw[224 + j]);
    for (int m = lane; m < 64; m += 32)
        acc += M2[n * 64 + m] * g_gw[m];
#pragma unroll
    for (int o = 16; o > 0; o >>= 1)
        acc += __shfl_down_sync(0xffffffffu, acc, o);
    if (lane == 0) out[n] = acc + smb[0];
}

// ============================================================================
extern "C" void kernel_launch(void* const* d_in, const int* in_sizes, int n_in,
                              void* d_out, int out_size) {
    const float* x   = (const float*)d_in[0];
    const float* cw0 = (const float*)d_in[1];
    const float* cb0 = (const float*)d_in[2];
    const float* lg0 = (const float*)d_in[3];
    const float* lb0 = (const float*)d_in[4];
    const float* L10 = (const float*)d_in[5];
    const float* L20 = (const float*)d_in[6];
    const float* cw1 = (const float*)d_in[7];
    const float* cb1 = (const float*)d_in[8];
    const float* lg1 = (const float*)d_in[9];
    const float* lb1 = (const float*)d_in[10];
    const float* L11 = (const float*)d_in[11];
    const float* L21 = (const float*)d_in[12];
    const float* cw2 = (const float*)d_in[13];
    const float* cb2 = (const float*)d_in[14];
    const float* lg2 = (const float*)d_in[15];
    const float* lb2 = (const float*)d_in[16];
    const float* L12 = (const float*)d_in[17];
    const float* L22 = (const float*)d_in[18];
    const float* fcw = (const float*)d_in[19];
    const float* fcb = (const float*)d_in[20];
    const float* slg = (const float*)d_in[21];
    const float* slb = (const float*)d_in[22];
    const float* M1  = (const float*)d_in[23];
    const float* M2  = (const float*)d_in[24];
    const float* smw = (const float*)d_in[25];
    const float* smb = (const float*)d_in[26];
    float* out = (float*)d_out;

    cudaFuncSetAttribute(kA3, cudaFuncAttributeMaxDynamicSharedMemorySize, SMEM_SZ);

    kW<<<13, 256>>>(cw0, cw1, cw2, L10, L20, L11, L21, L12, L22);
    kA3<<<1024, 256, SMEM_SZ>>>(x, cb0, lg0, lb0, cb1, lg1, lb1,
                                cb2, lg2, lb2, fcw, fcb);
    kB1<<<256, 256>>>();
    kB2<<<1, 256>>>();
    kC1<<<128, 224>>>(M1, slg, slb);
    kC2<<<64, 224>>>(smw);
    kD<<<512, 256>>>(M2, smw, smb, out);
}

// round 4
// speedup vs baseline: 2.7495x; 1.4741x over previous
#include <cuda_runtime.h>
#include <cuda_bf16.h>
#include <cstdint>

// ============================================================================
// StockMixer GB300 — mma.sync bf16 hi/lo, R4: cp.async overlap, chain-broken
// MMA schedule, shfl-paired transposes, register-resident xt/fc.
// ============================================================================

#define PW 144                         // words per image row (16-word pad)
#define IMG_WORDS (128 * PW)
#define IMG_BYTES (IMG_WORDS * 4)      // 73728
#define SCR_BASE  (3 * IMG_WORDS)      // word offset of scratch in smem
#define SMEM_SZ   (3 * IMG_BYTES + 1600)

// -------------------- device globals --------------------
__device__ __align__(16) uint32_t g_Wimg[7][IMG_WORDS];
__device__ __align__(16) uint32_t g_Limg[6][IMG_WORDS];
__device__ float g_h[4096 * 224];
__device__ float g_bpart[512];
__device__ float g_stats[2];
__device__ float g_cpart[32 * 64 * 224];
__device__ float g_gw[64];

// -------------------- helpers --------------------
__device__ __forceinline__ uint32_t smem_u32(const void* p) {
    uint32_t a;
    asm("{ .reg .u64 t; cvta.to.shared.u64 t, %1; cvt.u32.u64 %0, t; }"
        : "=r"(a) : "l"(p));
    return a;
}

#define CPA(d, s) \
    asm volatile("cp.async.ca.shared.global [%0], [%1], 16;" :: "r"(d), "l"(s) : "memory")
#define CPC()  asm volatile("cp.async.commit_group;" ::: "memory")
#define CPW(n) asm volatile("cp.async.wait_group %0;" :: "n"(n) : "memory")

__device__ __forceinline__ float hswf(float v) {
    return v * fminf(fmaxf(v + 3.0f, 0.0f), 6.0f) * (1.0f / 6.0f);
}

// word offset (within row) of the hi-word of k-pair (k even): chunk*16 + slot*2
__device__ __forceinline__ int wslot(int k) {
    int q = (k >> 1) & 7;
    int slot = ((q & 3) << 1) | (q >> 2);
    return ((k >> 4) << 4) + (slot << 1);
}
// full word address with row-XOR bank swizzle
__device__ __forceinline__ int waddr(int row, int k) {
    return row * PW + (wslot(k) ^ ((row & 7) << 2));
}

__device__ __forceinline__ void split2(float v0, float v1,
                                       uint32_t& hi, uint32_t& lo) {
    __nv_bfloat162 h, l;
    h.x = __float2bfloat16(v0);
    h.y = __float2bfloat16(v1);
    l.x = __float2bfloat16(v0 - __bfloat162float(h.x));
    l.y = __float2bfloat16(v1 - __bfloat162float(h.y));
    hi = *(uint32_t*)&h;
    lo = *(uint32_t*)&l;
}

__device__ __forceinline__ void putpair(uint32_t* img, int row, int k2,
                                        float v0, float v1) {
    uint32_t hi, lo;
    split2(v0, v1, hi, lo);
    int w = waddr(row, k2);
    img[w] = hi;
    img[w + 1] = lo;
}

__device__ __forceinline__ void mma16816(float* d, uint32_t a0, uint32_t a1,
                                         uint32_t a2, uint32_t a3,
                                         uint32_t b0, uint32_t b1) {
    asm volatile(
        "mma.sync.aligned.m16n8k16.row.col.f32.bf16.bf16.f32 "
        "{%0,%1,%2,%3}, {%4,%5,%6,%7}, {%8,%9}, {%0,%1,%2,%3};"
        : "+f"(d[0]), "+f"(d[1]), "+f"(d[2]), "+f"(d[3])
        : "r"(a0), "r"(a1), "r"(a2), "r"(a3), "r"(b0), "r"(b1));
}

// dual-m-tile 3-term GEMM, term-major schedule (chain gap >= 16)
__device__ __forceinline__ void gemm_dual(
    const uint32_t* __restrict__ A, const uint32_t* __restrict__ B,
    float (&accA)[8][4], float (&accB)[8][4],
    int mta, int mtb, int ks0, int kaEnd, int kbEnd, int g, int c, int c0) {
    const int sw = (g & 7) << 2;
    for (int ks = ks0; ks < kbEnd; ks++) {
        int off = (ks * 16 + c * 4) ^ sw;
        uint4 vb[8];
#pragma unroll
        for (int nt = 0; nt < 8; nt++)
            vb[nt] = *(const uint4*)(B + (c0 + nt * 8 + g) * PW + off);
        const uint32_t* apb = A + (mtb * 16 + g) * PW + off;
        uint4 tb0 = *(const uint4*)apb;
        uint4 tb1 = *(const uint4*)(apb + 8 * PW);
        bool doA = (ks < kaEnd);
        uint4 ta0, ta1;
        if (doA) {
            const uint32_t* apa = A + (mta * 16 + g) * PW + off;
            ta0 = *(const uint4*)apa;
            ta1 = *(const uint4*)(apa + 8 * PW);
        }
        // term hh
#pragma unroll
        for (int nt = 0; nt < 8; nt++)
            mma16816(accB[nt], tb0.x, tb1.x, tb0.z, tb1.z, vb[nt].x, vb[nt].z);
        if (doA) {
#pragma unroll
            for (int nt = 0; nt < 8; nt++)
                mma16816(accA[nt], ta0.x, ta1.x, ta0.z, ta1.z, vb[nt].x, vb[nt].z);
        }
        // term hl (A hi x B lo)
#pragma unroll
        for (int nt = 0; nt < 8; nt++)
            mma16816(accB[nt], tb0.x, tb1.x, tb0.z, tb1.z, vb[nt].y, vb[nt].w);
        if (doA) {
#pragma unroll
            for (int nt = 0; nt < 8; nt++)
                mma16816(accA[nt], ta0.x, ta1.x, ta0.z, ta1.z, vb[nt].y, vb[nt].w);
        }
        // term lh (A lo x B hi)
#pragma unroll
        for (int nt = 0; nt < 8; nt++)
            mma16816(accB[nt], tb0.y, tb1.y, tb0.w, tb1.w, vb[nt].x, vb[nt].z);
        if (doA) {
#pragma unroll
            for (int nt = 0; nt < 8; nt++)
                mma16816(accA[nt], ta0.y, ta1.y, ta0.w, ta1.w, vb[nt].x, vb[nt].z);
        }
    }
}

// shfl-paired transposed store: element (row=f, k=t), hi word by even-g lane,
// lo word by odd-g lane.
__device__ __forceinline__ void storeT(uint32_t* img, int f, int t, float v,
                                       int par) {
    float vp = __shfl_xor_sync(0xffffffffu, v, 4);
    float a = par ? vp : v;
    float b = par ? v : vp;
    __nv_bfloat16 ha = __float2bfloat16(a), hb = __float2bfloat16(b);
    uint32_t word;
    if (par) {
        __nv_bfloat162 lw;
        lw.x = __float2bfloat16(a - __bfloat162float(ha));
        lw.y = __float2bfloat16(b - __bfloat162float(hb));
        word = *(uint32_t*)&lw;
    } else {
        __nv_bfloat162 hw;
        hw.x = ha; hw.y = hb;
        word = *(uint32_t*)&hw;
    }
    img[waddr(f, t & ~1) + par] = word;
}

// async full-image copy (4608 lines of 16B, 256 threads)
__device__ __forceinline__ void cpa_full(uint32_t dst, const uint32_t* src,
                                         int tid) {
#pragma unroll
    for (int j = 0; j < 18; j++) {
        int l = tid + 256 * j;
        CPA(dst + l * 16, (const char*)src + l * 16);
    }
}

// trimmed L-image copy: only the block-diagonal k-range per row
template <int TK>
__device__ __forceinline__ void cpa_L(uint32_t dst, const uint32_t* src,
                                      int tid) {
    if (TK == 128) { cpa_full(dst, src, tid); return; }
    constexpr int LPR = TK / 4;        // 16B lines per row
    constexpr int TOT = 128 * LPR;
#pragma unroll
    for (int i = tid; i < TOT; i += 256) {
        int row = i / LPR, li = i % LPR;
        int off = row * PW + (row / TK) * TK + li * 4;   // words
        CPA(dst + off * 4, (const char*)(src + off));
    }
}

// ============================================================================
// kW: precompute operand images (layout incl. XOR swizzle)
// ============================================================================
__global__ void kW(const float* __restrict__ cw0, const float* __restrict__ cw1,
                   const float* __restrict__ cw2,
                   const float* __restrict__ L10, const float* __restrict__ L20,
                   const float* __restrict__ L11, const float* __restrict__ L21,
                   const float* __restrict__ L12, const float* __restrict__ L22) {
    int b = blockIdx.x;
    if (b < 7) {
        int s, kk;
        if (b == 0)      { s = 0; kk = 0; }
        else if (b < 3)  { s = 1; kk = b - 1; }
        else             { s = 2; kk = b - 3; }
        const float* cw = (s == 0) ? cw0 : (s == 1) ? cw1 : cw2;
        int k = 1 << s;
        uint32_t* dst = g_Wimg[b];
        for (int idx = threadIdx.x; idx < 128 * 64; idx += blockDim.x) {
            int o = idx >> 6, i = (idx & 63) << 1;
            putpair(dst, o, i, cw[(o * 128 + i) * k + kk],
                    cw[(o * 128 + i + 1) * k + kk]);
        }
    } else {
        int j = b - 7;
        int s = j >> 1, m = j & 1;
        const float* L = (s == 0) ? (m ? L20 : L10)
                       : (s == 1) ? (m ? L21 : L11)
                                  : (m ? L22 : L12);
        int tk = 128 >> s;
        uint32_t* dst = g_Limg[j];
        for (int idx = threadIdx.x; idx < 128 * 64; idx += blockDim.x) {
            int t = idx >> 6, sc = (idx & 63) << 1;
            float v[2];
#pragma unroll
            for (int e = 0; e < 2; e++) {
                int scc = sc + e;
                float vv = 0.0f;
                if ((t / tk) == (scc / tk)) {
                    int tp = t % tk, sp = scc % tk;
                    if (sp <= tp) vv = L[tp * tk + sp];
                }
                v[e] = vv;
            }
            putpair(dst, t, sc, v[0], v[1]);
        }
    }
}

// ============================================================================
// run_scale: one stacked-stock run of one scale
// ============================================================================
template <int TK>
__device__ __noinline__ void run_scale(
    const float* __restrict__ x, int n0run, int q0,
    const float* __restrict__ lg, const float* __restrict__ lb,
    const uint32_t* __restrict__ L1g, const uint32_t* __restrict__ L2g,
    int hoff, const float* __restrict__ cb, float fcb, bool first) {

    constexpr int K = 128 / TK;
    extern __shared__ uint32_t smw[];
    uint32_t* P = smw;
    uint32_t* Q = smw + IMG_WORDS;
    uint32_t* R = smw + 2 * IMG_WORDS;
    float* scr = (float*)(smw + SCR_BASE);
    float* s_fcw = scr + 16;
    float* s_cb  = scr + 144;
    float* scrF  = scr + 272;

    const int tid = threadIdx.x;
    const int w = tid >> 5, lane = tid & 31;
    const int w3 = w & 3;
    const int g = lane >> 2, c = lane & 3;
    const int par = g & 1;
    const int c0 = (w >> 2) * 64;
    const uint32_t Pu = smem_u32(P), Qu = smem_u32(Q), Ru = smem_u32(R);

    int mta, mtb;
    if (TK == 128)     { mta = w3;                          mtb = 7 - w3; }
    else if (TK == 64) { mta = ((w3 >> 1) << 2) + (w3 & 1); mtb = ((w3 >> 1) << 2) + 3 - (w3 & 1); }
    else               { mta = w3 << 1;                     mtb = (w3 << 1) + 1; }
    const int myg = (TK == 128) ? 0 : (TK == 64 ? (w3 >> 1) : w3);
    const int ks0 = (myg * TK) >> 4;

    if (first) {
        cpa_L<TK>(Qu, L1g, tid);         // L1 persists in Q for the whole scale
        CPC();
        if (tid < 128) s_cb[tid] = cb[tid];
    }

    float accA[8][4], accB[8][4], fcT[4];
#pragma unroll
    for (int i = 0; i < 4; i++) fcT[i] = 0.0f;
#pragma unroll
    for (int nt = 0; nt < 8; nt++)
#pragma unroll
        for (int e = 0; e < 4; e++) { accA[nt][e] = 0.0f; accB[nt][e] = 0.0f; }

    // ---------------- conv over K chunks ----------------
    for (int kk = 0; kk < K; kk++) {
        cpa_full(Ru, g_Wimg[q0 + kk], tid);
        CPC();
#pragma unroll 2
        for (int it = 0; it < 16; it++) {
            int r = it * 8 + (tid >> 5);
            int f4 = tid & 31;
            const float4 v = ((const float4*)(x +
                ((size_t)(n0run + r / TK) * 128 + (r & (TK - 1)) * K + kk) * 128))[f4];
            int k2 = f4 << 2;
            uint32_t h0, l0, h1, l1;
            split2(v.x, v.y, h0, l0);
            split2(v.z, v.w, h1, l1);
            *(uint2*)(P + waddr(r, k2))     = make_uint2(h0, l0);
            *(uint2*)(P + waddr(r, k2 + 2)) = make_uint2(h1, l1);
        }
        CPW(0);
        __syncthreads();
        gemm_dual(P, R, accA, accB, mta, mtb, 0, 8, 8, g, c, c0);
        __syncthreads();
    }

    // ---------------- LN stats ----------------
    float s = 0.0f, s2 = 0.0f;
#pragma unroll
    for (int ti = 0; ti < 2; ti++)
#pragma unroll
        for (int nt = 0; nt < 8; nt++)
#pragma unroll
            for (int e = 0; e < 4; e++) {
                int f = c0 + nt * 8 + (c << 1) + (e & 1);
                float v = (ti ? accB[nt][e] : accA[nt][e]) + s_cb[f];
                s += v; s2 += v * v;
            }
#pragma unroll
    for (int o = 16; o; o >>= 1) {
        s  += __shfl_down_sync(0xffffffffu, s, o);
        s2 += __shfl_down_sync(0xffffffffu, s2, o);
    }
    if (lane == 0) { scr[w] = s; scr[8 + w] = s2; }
    __syncthreads();

    cpa_L<TK>(Ru, L2g, tid);             // prefetch L2 into R (W dead)
    CPC();

    float gs = 0.0f, gs2 = 0.0f;
#pragma unroll
    for (int p = 0; p < 4; p++) {
        int pg = (TK == 128) ? 0 : (TK == 64 ? (p >> 1) : p);
        if (pg == myg) { gs += scr[p] + scr[4 + p]; gs2 += scr[8 + p] + scr[12 + p]; }
    }
    const float inv = 1.0f / (float)(TK * 128);
    float mu = gs * inv;
    float var = gs2 * inv - mu * mu;
    float rinv = rsqrtf(var + 1e-5f);

    // ---------------- hT -> P ; fc conv-part ----------------
#pragma unroll
    for (int ti = 0; ti < 2; ti++) {
        int mt = ti ? mtb : mta;
#pragma unroll
        for (int nt = 0; nt < 8; nt++)
#pragma unroll
            for (int eh = 0; eh < 2; eh++) {
                int t = mt * 16 + g + 8 * eh;
                int tl = t & (TK - 1);
                int fb = c0 + nt * 8 + (c << 1);
                float2 lgv = *(const float2*)(lg + tl * 128 + fb);
                float2 lbv = *(const float2*)(lb + tl * 128 + fb);
#pragma unroll
                for (int eo = 0; eo < 2; eo++) {
                    float v = (ti ? accB[nt][eh * 2 + eo] : accA[nt][eh * 2 + eo])
                              + s_cb[fb + eo];
                    fcT[ti * 2 + eh] += v * s_fcw[fb + eo];
                    float hh = (v - mu) * rinv * (eo ? lgv.y : lgv.x)
                               + (eo ? lbv.y : lbv.x);
                    storeT(P, fb + eo, t, hh, par);
                }
            }
    }
    CPW(1);                               // everything but L2 done
    __syncthreads();

    // ---------------- GEMM1: u = L1m @ h ----------------
#pragma unroll
    for (int nt = 0; nt < 8; nt++)
#pragma unroll
        for (int e = 0; e < 4; e++) { accA[nt][e] = 0.0f; accB[nt][e] = 0.0f; }
    gemm_dual(Q, P, accA, accB, mta, mtb, ks0, mta + 1, mtb + 1, g, c, c0);
    __syncthreads();

    // ---------------- uT = hsw(u) -> P ----------------
#pragma unroll
    for (int ti = 0; ti < 2; ti++) {
        int mt = ti ? mtb : mta;
#pragma unroll
        for (int nt = 0; nt < 8; nt++)
#pragma unroll
            for (int e = 0; e < 4; e++) {
                int t = mt * 16 + g + ((e >> 1) << 3);
                int f = c0 + nt * 8 + (c << 1) + (e & 1);
                storeT(P, f, t, hswf(ti ? accB[nt][e] : accA[nt][e]), par);
            }
    }
    CPW(0);                               // L2 ready
    __syncthreads();

    // ---------------- GEMM2: v = L2m @ u ; fc v-part ----------------
#pragma unroll
    for (int nt = 0; nt < 8; nt++)
#pragma unroll
        for (int e = 0; e < 4; e++) { accA[nt][e] = 0.0f; accB[nt][e] = 0.0f; }
    gemm_dual(R, P, accA, accB, mta, mtb, ks0, mta + 1, mtb + 1, g, c, c0);
#pragma unroll
    for (int ti = 0; ti < 2; ti++)
#pragma unroll
        for (int nt = 0; nt < 8; nt++)
#pragma unroll
            for (int e = 0; e < 4; e++) {
                int f = c0 + nt * 8 + (c << 1) + (e & 1);
                fcT[ti * 2 + (e >> 1)] +=
                    (ti ? accB[nt][e] : accA[nt][e]) * s_fcw[f];
            }

    // ---------------- fc reduce -> g_h ----------------
#pragma unroll
    for (int i = 0; i < 4; i++) {
        fcT[i] += __shfl_xor_sync(0xffffffffu, fcT[i], 1);
        fcT[i] += __shfl_xor_sync(0xffffffffu, fcT[i], 2);
    }
    if (w < 4 && c == 0) {
#pragma unroll
        for (int i = 0; i < 4; i++) {
            int t = ((i >> 1) ? mtb : mta) * 16 + g + 8 * (i & 1);
            scrF[t] = fcT[i];
        }
    }
    __syncthreads();
    if (w >= 4 && c == 0) {
#pragma unroll
        for (int i = 0; i < 4; i++) {
            int t = ((i >> 1) ? mtb : mta) * 16 + g + 8 * (i & 1);
            g_h[(n0run + t / TK) * 224 + hoff + (t & (TK - 1))] =
                scrF[t] + fcT[i] + fcb;
        }
    }
    __syncthreads();
}

__global__ void __launch_bounds__(256, 1) kA4(
    const float* __restrict__ x,
    const float* __restrict__ cb0, const float* __restrict__ lg0,
    const float* __restrict__ lb0,
    const float* __restrict__ cb1, const float* __restrict__ lg1,
    const float* __restrict__ lb1,
    const float* __restrict__ cb2, const float* __restrict__ lg2,
    const float* __restrict__ lb2,
    const float* __restrict__ fcw, const float* __restrict__ fcbp) {
    extern __shared__ uint32_t smw[];
    float* scr = (float*)(smw + SCR_BASE);
    if (threadIdx.x < 128) scr[16 + threadIdx.x] = fcw[threadIdx.x];
    float fcb = fcbp[0];
    int n0 = blockIdx.x * 4;

    run_scale<128>(x, n0 + 0, 0, lg0, lb0, g_Limg[0], g_Limg[1], 0, cb0, fcb, true);
    run_scale<128>(x, n0 + 1, 0, lg0, lb0, g_Limg[0], g_Limg[1], 0, cb0, fcb, false);
    run_scale<128>(x, n0 + 2, 0, lg0, lb0, g_Limg[0], g_Limg[1], 0, cb0, fcb, false);
    run_scale<128>(x, n0 + 3, 0, lg0, lb0, g_Limg[0], g_Limg[1], 0, cb0, fcb, false);

    run_scale<64>(x, n0 + 0, 1, lg1, lb1, g_Limg[2], g_Limg[3], 128, cb1, fcb, true);
    run_scale<64>(x, n0 + 2, 1, lg1, lb1, g_Limg[2], g_Limg[3], 128, cb1, fcb, false);

    run_scale<32>(x, n0 + 0, 3, lg2, lb2, g_Limg[4], g_Limg[5], 192, cb2, fcb, true);
}

// ============================================================================
// phase 2
// ============================================================================
__device__ __forceinline__ void bred2(float& s, float& s2, float* scr) {
#pragma unroll
    for (int o = 16; o > 0; o >>= 1) {
        s  += __shfl_down_sync(0xffffffffu, s, o);
        s2 += __shfl_down_sync(0xffffffffu, s2, o);
    }
    int w = threadIdx.x >> 5, l = threadIdx.x & 31;
    if (l == 0) { scr[w] = s; scr[32 + w] = s2; }
    __syncthreads();
    if (threadIdx.x == 0) {
        float a = 0.f, b = 0.f;
        int nw = (blockDim.x + 31) >> 5;
        for (int i = 0; i < nw; i++) { a += scr[i]; b += scr[32 + i]; }
        scr[0] = a; scr[32] = b;
    }
    __syncthreads();
    s = scr[0]; s2 = scr[32];
}

__global__ void kB1() {
    float s = 0.f, s2 = 0.f;
    int base = blockIdx.x * 16 * 224;
    for (int idx = threadIdx.x; idx < 16 * 224; idx += 256) {
        float v = g_h[base + idx];
        s += v; s2 += v * v;
    }
    __shared__ float scr[64];
    bred2(s, s2, scr);
    if (threadIdx.x == 0) { g_bpart[blockIdx.x] = s; g_bpart[256 + blockIdx.x] = s2; }
}

__global__ void kB2() {
    float s = g_bpart[threadIdx.x];
    float s2 = g_bpart[256 + threadIdx.x];
    __shared__ float scr[64];
    bred2(s, s2, scr);
    if (threadIdx.x == 0) {
        const float inv = 1.0f / (4096.0f * 224.0f);
        float mu = s * inv;
        float var = s2 * inv - mu * mu;
        g_stats[0] = mu;
        g_stats[1] = rsqrtf(var + 1e-5f);
    }
}

__global__ void kC1(const float* __restrict__ M1,
                    const float* __restrict__ slg,
                    const float* __restrict__ slb) {
    int j = threadIdx.x;
    int b = blockIdx.x;                  // 0..31
    float mu = g_stats[0], rinv = g_stats[1];
    float acc[64];
#pragma unroll
    for (int m = 0; m < 64; m++) acc[m] = 0.f;
    int n0 = b * 128;
    for (int n = n0; n < n0 + 128; n++) {
        int off = n * 224 + j;
        float hn = (g_h[off] - mu) * rinv * slg[off] + slb[off];
#pragma unroll
        for (int m = 0; m < 64; m++) acc[m] += M1[m * 4096 + n] * hn;
    }
#pragma unroll
    for (int m = 0; m < 64; m++) g_cpart[(b * 64 + m) * 224 + j] = acc[m];
}

__global__ void kC2(const float* __restrict__ smw_) {
    int m = blockIdx.x, j = threadIdx.x;
    float g = 0.f;
    for (int b = 0; b < 32; b++) g += g_cpart[(b * 64 + m) * 224 + j];
    float v = hswf(g) * smw_[224 + j];
    float dummy = 0.f;
    __shared__ float scr[64];
    bred2(v, dummy, scr);
    if (threadIdx.x == 0) g_gw[m] = v;
}

__global__ void kD(const float* __restrict__ M2,
                   const float* __restrict__ smw_,
                   const float* __restrict__ smb,
                   float* __restrict__ out) {
    int warp = threadIdx.x >> 5, lane = threadIdx.x & 31;
    int n = blockIdx.x * 8 + warp;
    float acc = 0.f;
    for (int j = lane; j < 224; j += 32)
        acc += g_h[n * 224 + j] * (smw_[j] + smw_[224 + j]);
    for (int m = lane; m < 64; m += 32)
        acc += M2[n * 64 + m] * g_gw[m];
#pragma unroll
    for (int o = 16; o > 0; o >>= 1)
        acc += __shfl_down_sync(0xffffffffu, acc, o);
    if (lane == 0) out[n] = acc + smb[0];
}

// ============================================================================
extern "C" void kernel_launch(void* const* d_in, const int* in_sizes, int n_in,
                              void* d_out, int out_size) {
    const float* x   = (const float*)d_in[0];
    const float* cw0 = (const float*)d_in[1];
    const float* cb0 = (const float*)d_in[2];
    const float* lg0 = (const float*)d_in[3];
    const float* lb0 = (const float*)d_in[4];
    const float* L10 = (const float*)d_in[5];
    const float* L20 = (const float*)d_in[6];
    const float* cw1 = (const float*)d_in[7];
    const float* cb1 = (const float*)d_in[8];
    const float* lg1 = (const float*)d_in[9];
    const float* lb1 = (const float*)d_in[10];
    const float* L11 = (const float*)d_in[11];
    const float* L21 = (const float*)d_in[12];
    const float* cw2 = (const float*)d_in[13];
    const float* cb2 = (const float*)d_in[14];
    const float* lg2 = (const float*)d_in[15];
    const float* lb2 = (const float*)d_in[16];
    const float* L12 = (const float*)d_in[17];
    const float* L22 = (const float*)d_in[18];
    const float* fcw = (const float*)d_in[19];
    const float* fcb = (const float*)d_in[20];
    const float* slg = (const float*)d_in[21];
    const float* slb = (const float*)d_in[22];
    const float* M1  = (const float*)d_in[23];
    const float* M2  = (const float*)d_in[24];
    const float* smw = (const float*)d_in[25];
    const float* smb = (const float*)d_in[26];
    float* out = (float*)d_out;

    cudaFuncSetAttribute(kA4, cudaFuncAttributeMaxDynamicSharedMemorySize, SMEM_SZ);

    kW<<<13, 256>>>(cw0, cw1, cw2, L10, L20, L11, L21, L12, L22);
    kA4<<<1024, 256, SMEM_SZ>>>(x, cb0, lg0, lb0, cb1, lg1, lb1,
                                cb2, lg2, lb2, fcw, fcb);
    kB1<<<256, 256>>>();
    kB2<<<1, 256>>>();
    kC1<<<32, 224>>>(M1, slg, slb);
    kC2<<<64, 224>>>(smw);
    kD<<<512, 256>>>(M2, smw, smb, out);
}

// round 5
// speedup vs baseline: 3.0523x; 1.1101x over previous
#include <cuda_runtime.h>
#include <cuda_bf16.h>
#include <cstdint>

// ============================================================================
// StockMixer GB300 — R5: 512-thread (16-warp) mma.sync bf16 hi/lo kernel,
// persistent-W buffer policy, overlapped trimmed L copies.
// ============================================================================

#define PW 144                         // words per image row
#define IMG_WORDS (128 * PW)
#define IMG_BYTES (IMG_WORDS * 4)      // 73728
#define SCR_BASE  (3 * IMG_WORDS)      // word offset of scratch
#define SMEM_SZ   (3 * IMG_BYTES + 3328)

#define NTH 512

// -------------------- device globals --------------------
__device__ __align__(16) uint32_t g_Wimg[7][IMG_WORDS];
__device__ __align__(16) uint32_t g_Limg[6][IMG_WORDS];
__device__ float g_h[4096 * 224];
__device__ float g_bpart[512];
__device__ float g_stats[2];
__device__ float g_cpart[32 * 64 * 224];
__device__ float g_gw[64];

// -------------------- helpers --------------------
__device__ __forceinline__ uint32_t smem_u32(const void* p) {
    uint32_t a;
    asm("{ .reg .u64 t; cvta.to.shared.u64 t, %1; cvt.u32.u64 %0, t; }"
        : "=r"(a) : "l"(p));
    return a;
}

#define CPA(d, s) \
    asm volatile("cp.async.ca.shared.global [%0], [%1], 16;" :: "r"(d), "l"(s) : "memory")
#define CPC()  asm volatile("cp.async.commit_group;" ::: "memory")
#define CPW(n) asm volatile("cp.async.wait_group %0;" :: "n"(n) : "memory")

__device__ __forceinline__ float hswf(float v) {
    return v * fminf(fmaxf(v + 3.0f, 0.0f), 6.0f) * (1.0f / 6.0f);
}

__device__ __forceinline__ int wslot(int k) {
    int q = (k >> 1) & 7;
    int slot = ((q & 3) << 1) | (q >> 2);
    return ((k >> 4) << 4) + (slot << 1);
}
__device__ __forceinline__ int waddr(int row, int k) {
    return row * PW + (wslot(k) ^ ((row & 7) << 2));
}

__device__ __forceinline__ void split2(float v0, float v1,
                                       uint32_t& hi, uint32_t& lo) {
    __nv_bfloat162 h, l;
    h.x = __float2bfloat16(v0);
    h.y = __float2bfloat16(v1);
    l.x = __float2bfloat16(v0 - __bfloat162float(h.x));
    l.y = __float2bfloat16(v1 - __bfloat162float(h.y));
    hi = *(uint32_t*)&h;
    lo = *(uint32_t*)&l;
}

__device__ __forceinline__ void putpair(uint32_t* img, int row, int k2,
                                        float v0, float v1) {
    uint32_t hi, lo;
    split2(v0, v1, hi, lo);
    int w = waddr(row, k2);
    img[w] = hi;
    img[w + 1] = lo;
}

__device__ __forceinline__ void mma16816(float* d, uint32_t a0, uint32_t a1,
                                         uint32_t a2, uint32_t a3,
                                         uint32_t b0, uint32_t b1) {
    asm volatile(
        "mma.sync.aligned.m16n8k16.row.col.f32.bf16.bf16.f32 "
        "{%0,%1,%2,%3}, {%4,%5,%6,%7}, {%8,%9}, {%0,%1,%2,%3};"
        : "+f"(d[0]), "+f"(d[1]), "+f"(d[2]), "+f"(d[3])
        : "r"(a0), "r"(a1), "r"(a2), "r"(a3), "r"(b0), "r"(b1));
}

// dual-m-tile 3-term GEMM (4 n-blocks = 32 cols per warp)
__device__ __forceinline__ void gemm_dual(
    const uint32_t* __restrict__ A, const uint32_t* __restrict__ B,
    float (&accA)[4][4], float (&accB)[4][4],
    int mta, int mtb, int ks0, int kaEnd, int kbEnd, int g, int c, int c0) {
    const int sw = (g & 7) << 2;
    for (int ks = ks0; ks < kbEnd; ks++) {
        int off = (ks * 16 + c * 4) ^ sw;
        uint4 vb[4];
#pragma unroll
        for (int nt = 0; nt < 4; nt++)
            vb[nt] = *(const uint4*)(B + (c0 + nt * 8 + g) * PW + off);
        const uint32_t* apb = A + (mtb * 16 + g) * PW + off;
        uint4 tb0 = *(const uint4*)apb;
        uint4 tb1 = *(const uint4*)(apb + 8 * PW);
        bool doA = (ks < kaEnd);
        uint4 ta0, ta1;
        if (doA) {
            const uint32_t* apa = A + (mta * 16 + g) * PW + off;
            ta0 = *(const uint4*)apa;
            ta1 = *(const uint4*)(apa + 8 * PW);
        }
#pragma unroll
        for (int nt = 0; nt < 4; nt++)
            mma16816(accB[nt], tb0.x, tb1.x, tb0.z, tb1.z, vb[nt].x, vb[nt].z);
        if (doA) {
#pragma unroll
            for (int nt = 0; nt < 4; nt++)
                mma16816(accA[nt], ta0.x, ta1.x, ta0.z, ta1.z, vb[nt].x, vb[nt].z);
        }
#pragma unroll
        for (int nt = 0; nt < 4; nt++)
            mma16816(accB[nt], tb0.x, tb1.x, tb0.z, tb1.z, vb[nt].y, vb[nt].w);
        if (doA) {
#pragma unroll
            for (int nt = 0; nt < 4; nt++)
                mma16816(accA[nt], ta0.x, ta1.x, ta0.z, ta1.z, vb[nt].y, vb[nt].w);
        }
#pragma unroll
        for (int nt = 0; nt < 4; nt++)
            mma16816(accB[nt], tb0.y, tb1.y, tb0.w, tb1.w, vb[nt].x, vb[nt].z);
        if (doA) {
#pragma unroll
            for (int nt = 0; nt < 4; nt++)
                mma16816(accA[nt], ta0.y, ta1.y, ta0.w, ta1.w, vb[nt].x, vb[nt].z);
        }
    }
}

// shfl-paired transposed store
__device__ __forceinline__ void storeT(uint32_t* img, int f, int t, float v,
                                       int par) {
    float vp = __shfl_xor_sync(0xffffffffu, v, 4);
    float a = par ? vp : v;
    float b = par ? v : vp;
    __nv_bfloat16 ha = __float2bfloat16(a), hb = __float2bfloat16(b);
    uint32_t word;
    if (par) {
        __nv_bfloat162 lw;
        lw.x = __float2bfloat16(a - __bfloat162float(ha));
        lw.y = __float2bfloat16(b - __bfloat162float(hb));
        word = *(uint32_t*)&lw;
    } else {
        __nv_bfloat162 hw;
        hw.x = ha; hw.y = hb;
        word = *(uint32_t*)&hw;
    }
    img[waddr(f, t & ~1) + par] = word;
}

// full-image async copy: 4608 lines / 512 threads = 9 each
__device__ __forceinline__ void cpa_full(uint32_t dst, const uint32_t* src,
                                         int tid) {
#pragma unroll
    for (int j = 0; j < 9; j++) {
        int l = tid + NTH * j;
        CPA(dst + l * 16, (const char*)src + l * 16);
    }
}

// L-image copy trimmed to needed region
template <int TK>
__device__ __forceinline__ void cpa_L(uint32_t dst, const uint32_t* src,
                                      int tid) {
    if (TK == 128) {
        // triangular chunk trim: logical chunk lq>>2 needed iff <= row>>4
#pragma unroll
        for (int i = tid; i < 128 * 32; i += NTH) {
            int row = i >> 5, lq = i & 31;
            if ((lq >> 2) <= (row >> 4)) {
                int off = row * PW + ((lq ^ (row & 7)) << 2);
                CPA(dst + off * 4, (const char*)(src + off));
            }
        }
    } else {
        constexpr int LPR = TK / 4;
        constexpr int TOT = 128 * LPR;
#pragma unroll
        for (int i = tid; i < TOT; i += NTH) {
            int row = i / LPR, li = i % LPR;
            int off = row * PW + (row / TK) * TK + li * 4;
            CPA(dst + off * 4, (const char*)(src + off));
        }
    }
}

// ============================================================================
// kW: precompute operand images
// ============================================================================
__global__ void kW(const float* __restrict__ cw0, const float* __restrict__ cw1,
                   const float* __restrict__ cw2,
                   const float* __restrict__ L10, const float* __restrict__ L20,
                   const float* __restrict__ L11, const float* __restrict__ L21,
                   const float* __restrict__ L12, const float* __restrict__ L22) {
    int b = blockIdx.x;
    if (b < 7) {
        int s, kk;
        if (b == 0)      { s = 0; kk = 0; }
        else if (b < 3)  { s = 1; kk = b - 1; }
        else             { s = 2; kk = b - 3; }
        const float* cw = (s == 0) ? cw0 : (s == 1) ? cw1 : cw2;
        int k = 1 << s;
        uint32_t* dst = g_Wimg[b];
        for (int idx = threadIdx.x; idx < 128 * 64; idx += blockDim.x) {
            int o = idx >> 6, i = (idx & 63) << 1;
            putpair(dst, o, i, cw[(o * 128 + i) * k + kk],
                    cw[(o * 128 + i + 1) * k + kk]);
        }
    } else {
        int j = b - 7;
        int s = j >> 1, m = j & 1;
        const float* L = (s == 0) ? (m ? L20 : L10)
                       : (s == 1) ? (m ? L21 : L11)
                                  : (m ? L22 : L12);
        int tk = 128 >> s;
        uint32_t* dst = g_Limg[j];
        for (int idx = threadIdx.x; idx < 128 * 64; idx += blockDim.x) {
            int t = idx >> 6, sc = (idx & 63) << 1;
            float v[2];
#pragma unroll
            for (int e = 0; e < 2; e++) {
                int scc = sc + e;
                float vv = 0.0f;
                if ((t / tk) == (scc / tk)) {
                    int tp = t % tk, sp = scc % tk;
                    if (sp <= tp) vv = L[tp * tk + sp];
                }
                v[e] = vv;
            }
            putpair(dst, t, sc, v[0], v[1]);
        }
    }
}

// ============================================================================
// run_scale
// ============================================================================
template <int TK>
__device__ __noinline__ void run_scale(
    const float* __restrict__ x, int n0run, int q0,
    const float* __restrict__ lg, const float* __restrict__ lb,
    const uint32_t* __restrict__ L1g, const uint32_t* __restrict__ L2g,
    int hoff, const float* __restrict__ cb, float fcb, bool first) {

    constexpr int K = 128 / TK;
    extern __shared__ uint32_t smw[];
    uint32_t* P = smw;
    uint32_t* Q = smw + IMG_WORDS;
    uint32_t* R = smw + 2 * IMG_WORDS;
    float* scr   = (float*)(smw + SCR_BASE);     // 32: partial sums
    float* s_fcw = scr + 32;                     // 128
    float* s_cb  = scr + 160;                    // 128
    float* scrF  = scr + 288;                    // 512

    const int tid = threadIdx.x;
    const int w = tid >> 5, lane = tid & 31;
    const int w3 = w & 3;
    const int g = lane >> 2, c = lane & 3;
    const int par = g & 1;
    const int c0 = (w >> 2) * 32;
    const uint32_t Qu = smem_u32(Q), Ru = smem_u32(R);

    int mta, mtb;
    if (TK == 128)     { mta = w3;                          mtb = 7 - w3; }
    else if (TK == 64) { mta = ((w3 >> 1) << 2) + (w3 & 1); mtb = ((w3 >> 1) << 2) + 3 - (w3 & 1); }
    else               { mta = w3 << 1;                     mtb = (w3 << 1) + 1; }
    const int myg = (TK == 128) ? 0 : (TK == 64 ? (w3 >> 1) : w3);
    const int ks0 = (myg * TK) >> 4;

    // L1 copy: every run for K==1 (Q clobbered by L2), once per scale otherwise
    if (first || K == 1) {
        cpa_L<TK>(Qu, L1g, tid);
        CPC();
    }
    if (first && tid < 128) s_cb[tid] = cb[tid];

    float accA[4][4], accB[4][4], fcT[4];
#pragma unroll
    for (int i = 0; i < 4; i++) fcT[i] = 0.0f;
#pragma unroll
    for (int nt = 0; nt < 4; nt++)
#pragma unroll
        for (int e = 0; e < 4; e++) { accA[nt][e] = 0.0f; accB[nt][e] = 0.0f; }

    // ---------------- conv over K chunks ----------------
    for (int kk = 0; kk < K; kk++) {
        if (K > 1 || (first && kk == 0)) {       // W persists in R for K==1
            cpa_full(Ru, g_Wimg[q0 + kk], tid);
            CPC();
        }
#pragma unroll 2
        for (int it = 0; it < 8; it++) {
            int r = it * 16 + (tid >> 5);
            int f4 = tid & 31;
            const float4 v = ((const float4*)(x +
                ((size_t)(n0run + r / TK) * 128 + (r & (TK - 1)) * K + kk) * 128))[f4];
            int k2 = f4 << 2;
            uint32_t h0, l0, h1, l1;
            split2(v.x, v.y, h0, l0);
            split2(v.z, v.w, h1, l1);
            *(uint2*)(P + waddr(r, k2))     = make_uint2(h0, l0);
            *(uint2*)(P + waddr(r, k2 + 2)) = make_uint2(h1, l1);
        }
        CPW(0);
        __syncthreads();
        gemm_dual(P, R, accA, accB, mta, mtb, 0, 8, 8, g, c, c0);
        __syncthreads();
    }
    if (K > 1) {                                 // R dead: prefetch L2 early
        cpa_L<TK>(Ru, L2g, tid);
        CPC();
    }

    // ---------------- LN stats ----------------
    float s = 0.0f, s2 = 0.0f;
#pragma unroll
    for (int ti = 0; ti < 2; ti++)
#pragma unroll
        for (int nt = 0; nt < 4; nt++)
#pragma unroll
            for (int e = 0; e < 4; e++) {
                int f = c0 + nt * 8 + (c << 1) + (e & 1);
                float v = (ti ? accB[nt][e] : accA[nt][e]) + s_cb[f];
                s += v; s2 += v * v;
            }
#pragma unroll
    for (int o = 16; o; o >>= 1) {
        s  += __shfl_down_sync(0xffffffffu, s, o);
        s2 += __shfl_down_sync(0xffffffffu, s2, o);
    }
    if (lane == 0) { scr[w] = s; scr[16 + w] = s2; }
    __syncthreads();

    float gs = 0.0f, gs2 = 0.0f;
#pragma unroll
    for (int p = 0; p < 16; p++) {
        int p3 = p & 3;
        int pg = (TK == 128) ? 0 : (TK == 64 ? (p3 >> 1) : p3);
        if (pg == myg) { gs += scr[p]; gs2 += scr[16 + p]; }
    }
    const float inv = 1.0f / (float)(TK * 128);
    float mu = gs * inv;
    float var = gs2 * inv - mu * mu;
    float rinv = rsqrtf(var + 1e-5f);

    // ---------------- hT -> P ; fc conv-part ----------------
#pragma unroll
    for (int ti = 0; ti < 2; ti++) {
        int mt = ti ? mtb : mta;
#pragma unroll
        for (int nt = 0; nt < 4; nt++)
#pragma unroll
            for (int eh = 0; eh < 2; eh++) {
                int t = mt * 16 + g + 8 * eh;
                int tl = t & (TK - 1);
                int fb = c0 + nt * 8 + (c << 1);
                float2 lgv = *(const float2*)(lg + tl * 128 + fb);
                float2 lbv = *(const float2*)(lb + tl * 128 + fb);
#pragma unroll
                for (int eo = 0; eo < 2; eo++) {
                    float v = (ti ? accB[nt][eh * 2 + eo] : accA[nt][eh * 2 + eo])
                              + s_cb[fb + eo];
                    fcT[ti * 2 + eh] += v * s_fcw[fb + eo];
                    float hh = (v - mu) * rinv * (eo ? lgv.y : lgv.x)
                               + (eo ? lbv.y : lbv.x);
                    storeT(P, fb + eo, t, hh, par);
                }
            }
    }
    __syncthreads();

    // ---------------- GEMM1: u = L1m @ h ----------------
#pragma unroll
    for (int nt = 0; nt < 4; nt++)
#pragma unroll
        for (int e = 0; e < 4; e++) { accA[nt][e] = 0.0f; accB[nt][e] = 0.0f; }
    gemm_dual(Q, P, accA, accB, mta, mtb, ks0, mta + 1, mtb + 1, g, c, c0);
    __syncthreads();

    if (K == 1) {                                // Q free now: L2 -> Q
        cpa_L<TK>(Qu, L2g, tid);
        CPC();
    }

    // ---------------- uT = hsw(u) -> P ----------------
#pragma unroll
    for (int ti = 0; ti < 2; ti++) {
        int mt = ti ? mtb : mta;
#pragma unroll
        for (int nt = 0; nt < 4; nt++)
#pragma unroll
            for (int e = 0; e < 4; e++) {
                int t = mt * 16 + g + ((e >> 1) << 3);
                int f = c0 + nt * 8 + (c << 1) + (e & 1);
                storeT(P, f, t, hswf(ti ? accB[nt][e] : accA[nt][e]), par);
            }
    }
    CPW(0);
    __syncthreads();

    // ---------------- GEMM2: v = L2m @ u ; fc v-part ----------------
#pragma unroll
    for (int nt = 0; nt < 4; nt++)
#pragma unroll
        for (int e = 0; e < 4; e++) { accA[nt][e] = 0.0f; accB[nt][e] = 0.0f; }
    const uint32_t* L2s = (K == 1) ? Q : R;
    gemm_dual(L2s, P, accA, accB, mta, mtb, ks0, mta + 1, mtb + 1, g, c, c0);
#pragma unroll
    for (int ti = 0; ti < 2; ti++)
#pragma unroll
        for (int nt = 0; nt < 4; nt++)
#pragma unroll
            for (int e = 0; e < 4; e++) {
                int f = c0 + nt * 8 + (c << 1) + (e & 1);
                fcT[ti * 2 + (e >> 1)] +=
                    (ti ? accB[nt][e] : accA[nt][e]) * s_fcw[f];
            }

    // ---------------- fc reduce -> g_h ----------------
#pragma unroll
    for (int i = 0; i < 4; i++) {
        fcT[i] += __shfl_xor_sync(0xffffffffu, fcT[i], 1);
        fcT[i] += __shfl_xor_sync(0xffffffffu, fcT[i], 2);
    }
    if (c == 0) {
#pragma unroll
        for (int i = 0; i < 4; i++) {
            int t = ((i >> 1) ? mtb : mta) * 16 + g + 8 * (i & 1);
            scrF[(w >> 2) * 128 + t] = fcT[i];
        }
    }
    __syncthreads();
    if (tid < 128) {
        int t = tid;
        float d = scrF[t] + scrF[128 + t] + scrF[256 + t] + scrF[384 + t];
        g_h[(n0run + t / TK) * 224 + hoff + (t & (TK - 1))] = d + fcb;
    }
    __syncthreads();
}

__global__ void __launch_bounds__(NTH, 1) kA5(
    const float* __restrict__ x,
    const float* __restrict__ cb0, const float* __restrict__ lg0,
    const float* __restrict__ lb0,
    const float* __restrict__ cb1, const float* __restrict__ lg1,
    const float* __restrict__ lb1,
    const float* __restrict__ cb2, const float* __restrict__ lg2,
    const float* __restrict__ lb2,
    const float* __restrict__ fcw, const float* __restrict__ fcbp) {
    extern __shared__ uint32_t smw[];
    float* scr = (float*)(smw + SCR_BASE);
    if (threadIdx.x < 128) scr[32 + threadIdx.x] = fcw[threadIdx.x];
    float fcb = fcbp[0];
    int n0 = blockIdx.x * 4;

    run_scale<128>(x, n0 + 0, 0, lg0, lb0, g_Limg[0], g_Limg[1], 0, cb0, fcb, true);
    run_scale<128>(x, n0 + 1, 0, lg0, lb0, g_Limg[0], g_Limg[1], 0, cb0, fcb, false);
    run_scale<128>(x, n0 + 2, 0, lg0, lb0, g_Limg[0], g_Limg[1], 0, cb0, fcb, false);
    run_scale<128>(x, n0 + 3, 0, lg0, lb0, g_Limg[0], g_Limg[1], 0, cb0, fcb, false);

    run_scale<64>(x, n0 + 0, 1, lg1, lb1, g_Limg[2], g_Limg[3], 128, cb1, fcb, true);
    run_scale<64>(x, n0 + 2, 1, lg1, lb1, g_Limg[2], g_Limg[3], 128, cb1, fcb, false);

    run_scale<32>(x, n0 + 0, 3, lg2, lb2, g_Limg[4], g_Limg[5], 192, cb2, fcb, true);
}

// ============================================================================
// phase 2
// ============================================================================
__device__ __forceinline__ void bred2(float& s, float& s2, float* scr) {
#pragma unroll
    for (int o = 16; o > 0; o >>= 1) {
        s  += __shfl_down_sync(0xffffffffu, s, o);
        s2 += __shfl_down_sync(0xffffffffu, s2, o);
    }
    int w = threadIdx.x >> 5, l = threadIdx.x & 31;
    if (l == 0) { scr[w] = s; scr[32 + w] = s2; }
    __syncthreads();
    if (threadIdx.x == 0) {
        float a = 0.f, b = 0.f;
        int nw = (blockDim.x + 31) >> 5;
        for (int i = 0; i < nw; i++) { a += scr[i]; b += scr[32 + i]; }
        scr[0] = a; scr[32] = b;
    }
    __syncthreads();
    s = scr[0]; s2 = scr[32];
}

__global__ void kB1() {
    float s = 0.f, s2 = 0.f;
    int base = blockIdx.x * 16 * 224;
    for (int idx = threadIdx.x; idx < 16 * 224; idx += 256) {
        float v = g_h[base + idx];
        s += v; s2 += v * v;
    }
    __shared__ float scr[64];
    bred2(s, s2, scr);
    if (threadIdx.x == 0) { g_bpart[blockIdx.x] = s; g_bpart[256 + blockIdx.x] = s2; }
}

__global__ void kB2() {
    float s = g_bpart[threadIdx.x];
    float s2 = g_bpart[256 + threadIdx.x];
    __shared__ float scr[64];
    bred2(s, s2, scr);
    if (threadIdx.x == 0) {
        const float inv = 1.0f / (4096.0f * 224.0f);
        float mu = s * inv;
        float var = s2 * inv - mu * mu;
        g_stats[0] = mu;
        g_stats[1] = rsqrtf(var + 1e-5f);
    }
}

__global__ void kC1(const float* __restrict__ M1,
                    const float* __restrict__ slg,
                    const float* __restrict__ slb) {
    int j = threadIdx.x;
    int b = blockIdx.x;
    float mu = g_stats[0], rinv = g_stats[1];
    float acc[64];
#pragma unroll
    for (int m = 0; m < 64; m++) acc[m] = 0.f;
    int n0 = b * 128;
    for (int n = n0; n < n0 + 128; n++) {
        int off = n * 224 + j;
        float hn = (g_h[off] - mu) * rinv * slg[off] + slb[off];
#pragma unroll
        for (int m = 0; m < 64; m++) acc[m] += M1[m * 4096 + n] * hn;
    }
#pragma unroll
    for (int m = 0; m < 64; m++) g_cpart[(b * 64 + m) * 224 + j] = acc[m];
}

__global__ void kC2(const float* __restrict__ smw_) {
    int m = blockIdx.x, j = threadIdx.x;
    float g = 0.f;
    for (int b = 0; b < 32; b++) g += g_cpart[(b * 64 + m) * 224 + j];
    float v = hswf(g) * smw_[224 + j];
    float dummy = 0.f;
    __shared__ float scr[64];
    bred2(v, dummy, scr);
    if (threadIdx.x == 0) g_gw[m] = v;
}

__global__ void kD(const float* __restrict__ M2,
                   const float* __restrict__ smw_,
                   const float* __restrict__ smb,
                   float* __restrict__ out) {
    int warp = threadIdx.x >> 5, lane = threadIdx.x & 31;
    int n = blockIdx.x * 8 + warp;
    float acc = 0.f;
    for (int j = lane; j < 224; j += 32)
        acc += g_h[n * 224 + j] * (smw_[j] + smw_[224 + j]);
    for (int m = lane; m < 64; m += 32)
        acc += M2[n * 64 + m] * g_gw[m];
#pragma unroll
    for (int o = 16; o > 0; o >>= 1)
        acc += __shfl_down_sync(0xffffffffu, acc, o);
    if (lane == 0) out[n] = acc + smb[0];
}

// ============================================================================
extern "C" void kernel_launch(void* const* d_in, const int* in_sizes, int n_in,
                              void* d_out, int out_size) {
    const float* x   = (const float*)d_in[0];
    const float* cw0 = (const float*)d_in[1];
    const float* cb0 = (const float*)d_in[2];
    const float* lg0 = (const float*)d_in[3];
    const float* lb0 = (const float*)d_in[4];
    const float* L10 = (const float*)d_in[5];
    const float* L20 = (const float*)d_in[6];
    const float* cw1 = (const float*)d_in[7];
    const float* cb1 = (const float*)d_in[8];
    const float* lg1 = (const float*)d_in[9];
    const float* lb1 = (const float*)d_in[10];
    const float* L11 = (const float*)d_in[11];
    const float* L21 = (const float*)d_in[12];
    const float* cw2 = (const float*)d_in[13];
    const float* cb2 = (const float*)d_in[14];
    const float* lg2 = (const float*)d_in[15];
    const float* lb2 = (const float*)d_in[16];
    const float* L12 = (const float*)d_in[17];
    const float* L22 = (const float*)d_in[18];
    const float* fcw = (const float*)d_in[19];
    const float* fcb = (const float*)d_in[20];
    const float* slg = (const float*)d_in[21];
    const float* slb = (const float*)d_in[22];
    const float* M1  = (const float*)d_in[23];
    const float* M2  = (const float*)d_in[24];
    const float* smw = (const float*)d_in[25];
    const float* smb = (const float*)d_in[26];
    float* out = (float*)d_out;

    cudaFuncSetAttribute(kA5, cudaFuncAttributeMaxDynamicSharedMemorySize, SMEM_SZ);

    kW<<<13, 256>>>(cw0, cw1, cw2, L10, L20, L11, L21, L12, L22);
    kA5<<<1024, NTH, SMEM_SZ>>>(x, cb0, lg0, lb0, cb1, lg1, lb1,
                                cb2, lg2, lb2, fcw, fcb);
    kB1<<<256, 256>>>();
    kB2<<<1, 256>>>();
    kC1<<<32, 224>>>(M1, slg, slb);
    kC2<<<64, 224>>>(smw);
    kD<<<512, 256>>>(M2, smw, smb, out);
}

// round 6
// speedup vs baseline: 3.7904x; 1.2418x over previous
#include <cuda_runtime.h>
#include <cuda_fp16.h>
#include <cstdint>

// ============================================================================
// StockMixer GB300 — R6: fp16 asymmetric hi/lo (2-term) mma.sync kernel.
// A operands (x, L1, L2) single fp16; B operands (W, hT, uT) fp16 hi/lo.
// ============================================================================

#define PW  144                        // B-type image row pitch (words)
#define PWA 72                         // A-type image row pitch (words)
#define BIMG_WORDS (128 * PW)          // 18432 (73728 B)
#define AIMG_WORDS (128 * PWA)         // 9216  (36864 B)

#define X_OFF  0
#define L1_OFF 9216
#define L2_OFF 18432
#define WH_OFF 27648
#define SCR_BASE 46080
#define SMEM_SZ (46912 * 4)            // 187648 B

#define NTH 512

// -------------------- device globals --------------------
__device__ __align__(16) uint32_t g_Wimg[7][BIMG_WORDS];   // B-type fp16 hi/lo
__device__ __align__(16) uint32_t g_LimgA[6][AIMG_WORDS];  // A-type fp16
__device__ float g_h[4096 * 224];
__device__ float g_bpart[512];
__device__ float g_stats[2];
__device__ float g_cpart[32 * 64 * 224];
__device__ float g_gw[64];

// -------------------- helpers --------------------
__device__ __forceinline__ uint32_t smem_u32(const void* p) {
    uint32_t a;
    asm("{ .reg .u64 t; cvta.to.shared.u64 t, %1; cvt.u32.u64 %0, t; }"
        : "=r"(a) : "l"(p));
    return a;
}

#define CPA(d, s) \
    asm volatile("cp.async.ca.shared.global [%0], [%1], 16;" :: "r"(d), "l"(s) : "memory")
#define CPC()  asm volatile("cp.async.commit_group;" ::: "memory")
#define CPW(n) asm volatile("cp.async.wait_group %0;" :: "n"(n) : "memory")

__device__ __forceinline__ float hswf(float v) {
    return v * fminf(fmaxf(v + 3.0f, 0.0f), 6.0f) * (1.0f / 6.0f);
}

// ---- B-type layout (hi/lo pairs, XOR swizzle) ----
__device__ __forceinline__ int wslot(int k) {
    int q = (k >> 1) & 7;
    int slot = ((q & 3) << 1) | (q >> 2);
    return ((k >> 4) << 4) + (slot << 1);
}
__device__ __forceinline__ int waddr(int row, int k) {
    return row * PW + (wslot(k) ^ ((row & 7) << 2));
}

// ---- A-type layout (single fp16, no swizzle needed) ----
__device__ __forceinline__ int wslotA(int k) {
    int q = (k >> 1) & 7;
    int pos = ((q & 3) << 1) | (q >> 2);
    return ((k >> 4) << 3) + pos;
}

__device__ __forceinline__ void split2h(float v0, float v1,
                                        uint32_t& hi, uint32_t& lo) {
    __half2 h, l;
    h.x = __float2half(v0);
    h.y = __float2half(v1);
    l.x = __float2half(v0 - __half2float(h.x));
    l.y = __float2half(v1 - __half2float(h.y));
    hi = *(uint32_t*)&h;
    lo = *(uint32_t*)&l;
}

__device__ __forceinline__ void mma16816(float* d, uint32_t a0, uint32_t a1,
                                         uint32_t a2, uint32_t a3,
                                         uint32_t b0, uint32_t b1) {
    asm volatile(
        "mma.sync.aligned.m16n8k16.row.col.f32.f16.f16.f32 "
        "{%0,%1,%2,%3}, {%4,%5,%6,%7}, {%8,%9}, {%0,%1,%2,%3};"
        : "+f"(d[0]), "+f"(d[1]), "+f"(d[2]), "+f"(d[3])
        : "r"(a0), "r"(a1), "r"(a2), "r"(a3), "r"(b0), "r"(b1));
}

// dual-m-tile 2-term GEMM: A single fp16 (A-type), B hi/lo (B-type)
__device__ __forceinline__ void gemm_dual(
    const uint32_t* __restrict__ A, const uint32_t* __restrict__ B,
    float (&accA)[4][4], float (&accB)[4][4],
    int mta, int mtb, int ks0, int kaEnd, int kbEnd, int g, int c, int c0) {
    const int swB = (g & 7) << 2;
    for (int ks = ks0; ks < kbEnd; ks++) {
        int offB = (ks * 16 + c * 4) ^ swB;
        int offA = ks * 8 + c * 2;
        uint4 vb[4];
#pragma unroll
        for (int nt = 0; nt < 4; nt++)
            vb[nt] = *(const uint4*)(B + (c0 + nt * 8 + g) * PW + offB);
        uint2 tb0 = *(const uint2*)(A + (mtb * 16 + g) * PWA + offA);
        uint2 tb1 = *(const uint2*)(A + (mtb * 16 + g + 8) * PWA + offA);
        bool doA = (ks < kaEnd);
        uint2 ta0, ta1;
        if (doA) {
            ta0 = *(const uint2*)(A + (mta * 16 + g) * PWA + offA);
            ta1 = *(const uint2*)(A + (mta * 16 + g + 8) * PWA + offA);
        }
        // hi term
#pragma unroll
        for (int nt = 0; nt < 4; nt++)
            mma16816(accB[nt], tb0.x, tb1.x, tb0.y, tb1.y, vb[nt].x, vb[nt].z);
        if (doA) {
#pragma unroll
            for (int nt = 0; nt < 4; nt++)
                mma16816(accA[nt], ta0.x, ta1.x, ta0.y, ta1.y, vb[nt].x, vb[nt].z);
        }
        // lo term
#pragma unroll
        for (int nt = 0; nt < 4; nt++)
            mma16816(accB[nt], tb0.x, tb1.x, tb0.y, tb1.y, vb[nt].y, vb[nt].w);
        if (doA) {
#pragma unroll
            for (int nt = 0; nt < 4; nt++)
                mma16816(accA[nt], ta0.x, ta1.x, ta0.y, ta1.y, vb[nt].y, vb[nt].w);
        }
    }
}

// shfl-paired transposed store into a B-type image (fp16 hi/lo)
__device__ __forceinline__ void storeT(uint32_t* img, int f, int t, float v,
                                       int par) {
    float vp = __shfl_xor_sync(0xffffffffu, v, 4);
    float a = par ? vp : v;
    float b = par ? v : vp;
    __half ha = __float2half(a), hb = __float2half(b);
    uint32_t word;
    if (par) {
        __half2 lw;
        lw.x = __float2half(a - __half2float(ha));
        lw.y = __float2half(b - __half2float(hb));
        word = *(uint32_t*)&lw;
    } else {
        __half2 hw;
        hw.x = ha; hw.y = hb;
        word = *(uint32_t*)&hw;
    }
    img[waddr(f, t & ~1) + par] = word;
}

// full B-type image copy: 4608 lines / 512 threads
__device__ __forceinline__ void cpa_full(uint32_t dst, const uint32_t* src,
                                         int tid) {
#pragma unroll
    for (int j = 0; j < 9; j++) {
        int l = tid + NTH * j;
        CPA(dst + l * 16, (const char*)src + l * 16);
    }
}

// trimmed A-type L-image copy (16 lines per row; line = 4 words = 8 k's)
template <int TK>
__device__ __forceinline__ void cpa_LA(uint32_t dst, const uint32_t* src,
                                       int tid) {
#pragma unroll
    for (int i = tid; i < 128 * 16; i += NTH) {
        int row = i >> 4, li = i & 15;
        bool need;
        if (TK == 128) need = (li >> 1) <= (row >> 4);
        else {
            int b0 = (row / TK) * (TK / 8);
            need = (li >= b0) && (li < b0 + TK / 8);
        }
        if (need) {
            int off = row * PWA + li * 4;
            CPA(dst + off * 4, (const char*)(src + off));
        }
    }
}

// ============================================================================
// kW: precompute operand images
// ============================================================================
__global__ void kW(const float* __restrict__ cw0, const float* __restrict__ cw1,
                   const float* __restrict__ cw2,
                   const float* __restrict__ L10, const float* __restrict__ L20,
                   const float* __restrict__ L11, const float* __restrict__ L21,
                   const float* __restrict__ L12, const float* __restrict__ L22) {
    int b = blockIdx.x;
    if (b < 7) {                       // W: B-type fp16 hi/lo
        int s, kk;
        if (b == 0)      { s = 0; kk = 0; }
        else if (b < 3)  { s = 1; kk = b - 1; }
        else             { s = 2; kk = b - 3; }
        const float* cw = (s == 0) ? cw0 : (s == 1) ? cw1 : cw2;
        int k = 1 << s;
        uint32_t* dst = g_Wimg[b];
        for (int idx = threadIdx.x; idx < 128 * 64; idx += blockDim.x) {
            int o = idx >> 6, i = (idx & 63) << 1;
            uint32_t hi, lo;
            split2h(cw[(o * 128 + i) * k + kk], cw[(o * 128 + i + 1) * k + kk],
                    hi, lo);
            int w = waddr(o, i);
            dst[w] = hi;
            dst[w + 1] = lo;
        }
    } else {                           // L: A-type single fp16
        int j = b - 7;
        int s = j >> 1, m = j & 1;
        const float* L = (s == 0) ? (m ? L20 : L10)
                       : (s == 1) ? (m ? L21 : L11)
                                  : (m ? L22 : L12);
        int tk = 128 >> s;
        uint32_t* dst = g_LimgA[j];
        for (int idx = threadIdx.x; idx < 128 * 64; idx += blockDim.x) {
            int t = idx >> 6, sc = (idx & 63) << 1;
            float v[2];
#pragma unroll
            for (int e = 0; e < 2; e++) {
                int scc = sc + e;
                float vv = 0.0f;
                if ((t / tk) == (scc / tk)) {
                    int tp = t % tk, sp = scc % tk;
                    if (sp <= tp) vv = L[tp * tk + sp];
                }
                v[e] = vv;
            }
            __half2 h2;
            h2.x = __float2half(v[0]);
            h2.y = __float2half(v[1]);
            dst[t * PWA + wslotA(sc)] = *(uint32_t*)&h2;
        }
    }
}

// ============================================================================
// run_scale
// ============================================================================
template <int TK>
__device__ __noinline__ void run_scale(
    const float* __restrict__ x, int n0run, int q0,
    const float* __restrict__ lg, const float* __restrict__ lb,
    const uint32_t* __restrict__ L1g, const uint32_t* __restrict__ L2g,
    int hoff, const float* __restrict__ cb, float fcb, bool first) {

    constexpr int K = 128 / TK;
    extern __shared__ uint32_t smw[];
    uint32_t* X  = smw + X_OFF;
    uint32_t* L1 = smw + L1_OFF;
    uint32_t* L2 = smw + L2_OFF;
    uint32_t* WH = smw + WH_OFF;
    float* scr   = (float*)(smw + SCR_BASE);
    float* s_fcw = scr + 32;
    float* s_cb  = scr + 160;
    float* scrF  = scr + 288;

    const int tid = threadIdx.x;
    const int w = tid >> 5, lane = tid & 31;
    const int w3 = w & 3;
    const int g = lane >> 2, c = lane & 3;
    const int par = g & 1;
    const int c0 = (w >> 2) * 32;
    const uint32_t L1u = smem_u32(L1), L2u = smem_u32(L2), WHu = smem_u32(WH);

    int mta, mtb;
    if (TK == 128)     { mta = w3;                          mtb = 7 - w3; }
    else if (TK == 64) { mta = ((w3 >> 1) << 2) + (w3 & 1); mtb = ((w3 >> 1) << 2) + 3 - (w3 & 1); }
    else               { mta = w3 << 1;                     mtb = (w3 << 1) + 1; }
    const int myg = (TK == 128) ? 0 : (TK == 64 ? (w3 >> 1) : w3);
    const int ks0 = (myg * TK) >> 4;

    if (first) {
        cpa_LA<TK>(L1u, L1g, tid);
        cpa_LA<TK>(L2u, L2g, tid);
        CPC();
        if (tid < 128) s_cb[tid] = cb[tid];
    }

    float accA[4][4], accB[4][4], fcT[4];
#pragma unroll
    for (int i = 0; i < 4; i++) fcT[i] = 0.0f;
#pragma unroll
    for (int nt = 0; nt < 4; nt++)
#pragma unroll
        for (int e = 0; e < 4; e++) { accA[nt][e] = 0.0f; accB[nt][e] = 0.0f; }

    // ---------------- conv over K chunks ----------------
    for (int kk = 0; kk < K; kk++) {
        cpa_full(WHu, g_Wimg[q0 + kk], tid);
        CPC();
#pragma unroll 2
        for (int it = 0; it < 8; it++) {
            int r = it * 16 + (tid >> 5);
            int f4 = tid & 31;
            const float4 v = ((const float4*)(x +
                ((size_t)(n0run + r / TK) * 128 + (r & (TK - 1)) * K + kk) * 128))[f4];
            __half2 h0, h1;
            h0.x = __float2half(v.x); h0.y = __float2half(v.y);
            h1.x = __float2half(v.z); h1.y = __float2half(v.w);
            int k2 = f4 << 2;
            X[r * PWA + wslotA(k2)]     = *(uint32_t*)&h0;
            X[r * PWA + wslotA(k2 + 2)] = *(uint32_t*)&h1;
        }
        CPW(0);
        __syncthreads();
        gemm_dual(X, WH, accA, accB, mta, mtb, 0, 8, 8, g, c, c0);
        __syncthreads();
    }

    // ---------------- LN stats ----------------
    float s = 0.0f, s2 = 0.0f;
#pragma unroll
    for (int ti = 0; ti < 2; ti++)
#pragma unroll
        for (int nt = 0; nt < 4; nt++)
#pragma unroll
            for (int e = 0; e < 4; e++) {
                int f = c0 + nt * 8 + (c << 1) + (e & 1);
                float v = (ti ? accB[nt][e] : accA[nt][e]) + s_cb[f];
                s += v; s2 += v * v;
            }
#pragma unroll
    for (int o = 16; o; o >>= 1) {
        s  += __shfl_down_sync(0xffffffffu, s, o);
        s2 += __shfl_down_sync(0xffffffffu, s2, o);
    }
    if (lane == 0) { scr[w] = s; scr[16 + w] = s2; }
    __syncthreads();

    float gs = 0.0f, gs2 = 0.0f;
#pragma unroll
    for (int p = 0; p < 16; p++) {
        int p3 = p & 3;
        int pg = (TK == 128) ? 0 : (TK == 64 ? (p3 >> 1) : p3);
        if (pg == myg) { gs += scr[p]; gs2 += scr[16 + p]; }
    }
    const float inv = 1.0f / (float)(TK * 128);
    float mu = gs * inv;
    float var = gs2 * inv - mu * mu;
    float rinv = rsqrtf(var + 1e-5f);

    // ---------------- hT -> WH ; fc conv-part ----------------
#pragma unroll
    for (int ti = 0; ti < 2; ti++) {
        int mt = ti ? mtb : mta;
#pragma unroll
        for (int nt = 0; nt < 4; nt++)
#pragma unroll
            for (int eh = 0; eh < 2; eh++) {
                int t = mt * 16 + g + 8 * eh;
                int tl = t & (TK - 1);
                int fb = c0 + nt * 8 + (c << 1);
                float2 lgv = *(const float2*)(lg + tl * 128 + fb);
                float2 lbv = *(const float2*)(lb + tl * 128 + fb);
#pragma unroll
                for (int eo = 0; eo < 2; eo++) {
                    float v = (ti ? accB[nt][eh * 2 + eo] : accA[nt][eh * 2 + eo])
                              + s_cb[fb + eo];
                    fcT[ti * 2 + eh] += v * s_fcw[fb + eo];
                    float hh = (v - mu) * rinv * (eo ? lgv.y : lgv.x)
                               + (eo ? lbv.y : lbv.x);
                    storeT(WH, fb + eo, t, hh, par);
                }
            }
    }
    __syncthreads();

    // ---------------- GEMM1: u = L1m @ h ----------------
#pragma unroll
    for (int nt = 0; nt < 4; nt++)
#pragma unroll
        for (int e = 0; e < 4; e++) { accA[nt][e] = 0.0f; accB[nt][e] = 0.0f; }
    gemm_dual(L1, WH, accA, accB, mta, mtb, ks0, mta + 1, mtb + 1, g, c, c0);
    __syncthreads();

    // ---------------- uT = hsw(u) -> WH ----------------
#pragma unroll
    for (int ti = 0; ti < 2; ti++) {
        int mt = ti ? mtb : mta;
#pragma unroll
        for (int nt = 0; nt < 4; nt++)
#pragma unroll
            for (int e = 0; e < 4; e++) {
                int t = mt * 16 + g + ((e >> 1) << 3);
                int f = c0 + nt * 8 + (c << 1) + (e & 1);
                storeT(WH, f, t, hswf(ti ? accB[nt][e] : accA[nt][e]), par);
            }
    }
    __syncthreads();

    // ---------------- GEMM2: v = L2m @ u ; fc v-part ----------------
#pragma unroll
    for (int nt = 0; nt < 4; nt++)
#pragma unroll
        for (int e = 0; e < 4; e++) { accA[nt][e] = 0.0f; accB[nt][e] = 0.0f; }
    gemm_dual(L2, WH, accA, accB, mta, mtb, ks0, mta + 1, mtb + 1, g, c, c0);
#pragma unroll
    for (int ti = 0; ti < 2; ti++)
#pragma unroll
        for (int nt = 0; nt < 4; nt++)
#pragma unroll
            for (int e = 0; e < 4; e++) {
                int f = c0 + nt * 8 + (c << 1) + (e & 1);
                fcT[ti * 2 + (e >> 1)] +=
                    (ti ? accB[nt][e] : accA[nt][e]) * s_fcw[f];
            }

    // ---------------- fc reduce -> g_h ----------------
#pragma unroll
    for (int i = 0; i < 4; i++) {
        fcT[i] += __shfl_xor_sync(0xffffffffu, fcT[i], 1);
        fcT[i] += __shfl_xor_sync(0xffffffffu, fcT[i], 2);
    }
    if (c == 0) {
#pragma unroll
        for (int i = 0; i < 4; i++) {
            int t = ((i >> 1) ? mtb : mta) * 16 + g + 8 * (i & 1);
            scrF[(w >> 2) * 128 + t] = fcT[i];
        }
    }
    __syncthreads();
    if (tid < 128) {
        int t = tid;
        float d = scrF[t] + scrF[128 + t] + scrF[256 + t] + scrF[384 + t];
        g_h[(n0run + t / TK) * 224 + hoff + (t & (TK - 1))] = d + fcb;
    }
    __syncthreads();
}

__global__ void __launch_bounds__(NTH, 1) kA6(
    const float* __restrict__ x,
    const float* __restrict__ cb0, const float* __restrict__ lg0,
    const float* __restrict__ lb0,
    const float* __restrict__ cb1, const float* __restrict__ lg1,
    const float* __restrict__ lb1,
    const float* __restrict__ cb2, const float* __restrict__ lg2,
    const float* __restrict__ lb2,
    const float* __restrict__ fcw, const float* __restrict__ fcbp) {
    extern __shared__ uint32_t smw[];
    float* scr = (float*)(smw + SCR_BASE);
    if (threadIdx.x < 128) scr[32 + threadIdx.x] = fcw[threadIdx.x];
    float fcb = fcbp[0];
    int n0 = blockIdx.x * 4;

    run_scale<128>(x, n0 + 0, 0, lg0, lb0, g_LimgA[0], g_LimgA[1], 0, cb0, fcb, true);
    run_scale<128>(x, n0 + 1, 0, lg0, lb0, g_LimgA[0], g_LimgA[1], 0, cb0, fcb, false);
    run_scale<128>(x, n0 + 2, 0, lg0, lb0, g_LimgA[0], g_LimgA[1], 0, cb0, fcb, false);
    run_scale<128>(x, n0 + 3, 0, lg0, lb0, g_LimgA[0], g_LimgA[1], 0, cb0, fcb, false);

    run_scale<64>(x, n0 + 0, 1, lg1, lb1, g_LimgA[2], g_LimgA[3], 128, cb1, fcb, true);
    run_scale<64>(x, n0 + 2, 1, lg1, lb1, g_LimgA[2], g_LimgA[3], 128, cb1, fcb, false);

    run_scale<32>(x, n0 + 0, 3, lg2, lb2, g_LimgA[4], g_LimgA[5], 192, cb2, fcb, true);
}

// ============================================================================
// phase 2
// ============================================================================
__device__ __forceinline__ void bred2(float& s, float& s2, float* scr) {
#pragma unroll
    for (int o = 16; o > 0; o >>= 1) {
        s  += __shfl_down_sync(0xffffffffu, s, o);
        s2 += __shfl_down_sync(0xffffffffu, s2, o);
    }
    int w = threadIdx.x >> 5, l = threadIdx.x & 31;
    if (l == 0) { scr[w] = s; scr[32 + w] = s2; }
    __syncthreads();
    if (threadIdx.x == 0) {
        float a = 0.f, b = 0.f;
        int nw = (blockDim.x + 31) >> 5;
        for (int i = 0; i < nw; i++) { a += scr[i]; b += scr[32 + i]; }
        scr[0] = a; scr[32] = b;
    }
    __syncthreads();
    s = scr[0]; s2 = scr[32];
}

__global__ void kB1() {
    float s = 0.f, s2 = 0.f;
    int base = blockIdx.x * 16 * 224;
    for (int idx = threadIdx.x; idx < 16 * 224; idx += 256) {
        float v = g_h[base + idx];
        s += v; s2 += v * v;
    }
    __shared__ float scr[64];
    bred2(s, s2, scr);
    if (threadIdx.x == 0) { g_bpart[blockIdx.x] = s; g_bpart[256 + blockIdx.x] = s2; }
}

__global__ void kB2() {
    float s = g_bpart[threadIdx.x];
    float s2 = g_bpart[256 + threadIdx.x];
    __shared__ float scr[64];
    bred2(s, s2, scr);
    if (threadIdx.x == 0) {
        const float inv = 1.0f / (4096.0f * 224.0f);
        float mu = s * inv;
        float var = s2 * inv - mu * mu;
        g_stats[0] = mu;
        g_stats[1] = rsqrtf(var + 1e-5f);
    }
}

__global__ void kC1(const float* __restrict__ M1,
                    const float* __restrict__ slg,
                    const float* __restrict__ slb) {
    int j = threadIdx.x;
    int b = blockIdx.x;
    float mu = g_stats[0], rinv = g_stats[1];
    float acc[64];
#pragma unroll
    for (int m = 0; m < 64; m++) acc[m] = 0.f;
    int n0 = b * 128;
    for (int n = n0; n < n0 + 128; n++) {
        int off = n * 224 + j;
        float hn = (g_h[off] - mu) * rinv * slg[off] + slb[off];
#pragma unroll
        for (int m = 0; m < 64; m++) acc[m] += M1[m * 4096 + n] * hn;
    }
#pragma unroll
    for (int m = 0; m < 64; m++) g_cpart[(b * 64 + m) * 224 + j] = acc[m];
}

__global__ void kC2(const float* __restrict__ smw_) {
    int m = blockIdx.x, j = threadIdx.x;
    float g = 0.f;
    for (int b = 0; b < 32; b++) g += g_cpart[(b * 64 + m) * 224 + j];
    float v = hswf(g) * smw_[224 + j];
    float dummy = 0.f;
    __shared__ float scr[64];
    bred2(v, dummy, scr);
    if (threadIdx.x == 0) g_gw[m] = v;
}

__global__ void kD(const float* __restrict__ M2,
                   const float* __restrict__ smw_,
                   const float* __restrict__ smb,
                   float* __restrict__ out) {
    int warp = threadIdx.x >> 5, lane = threadIdx.x & 31;
    int n = blockIdx.x * 8 + warp;
    float acc = 0.f;
    for (int j = lane; j < 224; j += 32)
        acc += g_h[n * 224 + j] * (smw_[j] + smw_[224 + j]);
    for (int m = lane; m < 64; m += 32)
        acc += M2[n * 64 + m] * g_gw[m];
#pragma unroll
    for (int o = 16; o > 0; o >>= 1)
        acc += __shfl_down_sync(0xffffffffu, acc, o);
    if (lane == 0) out[n] = acc + smb[0];
}

// ============================================================================
extern "C" void kernel_launch(void* const* d_in, const int* in_sizes, int n_in,
                              void* d_out, int out_size) {
    const float* x   = (const float*)d_in[0];
    const float* cw0 = (const float*)d_in[1];
    const float* cb0 = (const float*)d_in[2];
    const float* lg0 = (const float*)d_in[3];
    const float* lb0 = (const float*)d_in[4];
    const float* L10 = (const float*)d_in[5];
    const float* L20 = (const float*)d_in[6];
    const float* cw1 = (const float*)d_in[7];
    const float* cb1 = (const float*)d_in[8];
    const float* lg1 = (const float*)d_in[9];
    const float* lb1 = (const float*)d_in[10];
    const float* L11 = (const float*)d_in[11];
    const float* L21 = (const float*)d_in[12];
    const float* cw2 = (const float*)d_in[13];
    const float* cb2 = (const float*)d_in[14];
    const float* lg2 = (const float*)d_in[15];
    const float* lb2 = (const float*)d_in[16];
    const float* L12 = (const float*)d_in[17];
    const float* L22 = (const float*)d_in[18];
    const float* fcw = (const float*)d_in[19];
    const float* fcb = (const float*)d_in[20];
    const float* slg = (const float*)d_in[21];
    const float* slb = (const float*)d_in[22];
    const float* M1  = (const float*)d_in[23];
    const float* M2  = (const float*)d_in[24];
    const float* smw = (const float*)d_in[25];
    const float* smb = (const float*)d_in[26];
    float* out = (float*)d_out;

    cudaFuncSetAttribute(kA6, cudaFuncAttributeMaxDynamicSharedMemorySize, SMEM_SZ);

    kW<<<13, 256>>>(cw0, cw1, cw2, L10, L20, L11, L21, L12, L22);
    kA6<<<1024, NTH, SMEM_SZ>>>(x, cb0, lg0, lb0, cb1, lg1, lb1,
                                cb2, lg2, lb2, fcw, fcb);
    kB1<<<256, 256>>>();
    kB2<<<1, 256>>>();
    kC1<<<32, 224>>>(M1, slg, slb);
    kC2<<<64, 224>>>(smw);
    kD<<<512, 256>>>(M2, smw, smb, out);
}

// round 7
// speedup vs baseline: 5.3063x; 1.3999x over previous
#include <cuda_runtime.h>
#include <cuda_fp16.h>
#include <cstdint>

// ============================================================================
// StockMixer GB300 — R7: single-term fp16 mma.sync kernel (1 MMA per k16).
// All operands single fp16 in compact A-type images (pitch 72 words).
// ============================================================================

#define PWA 72
#define AIMG_WORDS (128 * PWA)         // 9216 words = 36864 B

#define X_OFF  0
#define L1_OFF 9216
#define L2_OFF 18432
#define WB_OFF 27648
#define HT_OFF 36864
#define SCR_BASE 46080
#define SMEM_SZ (46912 * 4)            // 187648 B

#define NTH 512

// -------------------- device globals --------------------
__device__ __align__(16) uint32_t g_Wimg[7][AIMG_WORDS];
__device__ __align__(16) uint32_t g_LimgA[6][AIMG_WORDS];
__device__ float g_h[4096 * 224];
__device__ float g_bpart[512];
__device__ float g_stats[2];
__device__ float g_cpart[32 * 64 * 224];
__device__ float g_gw[64];

// -------------------- helpers --------------------
__device__ __forceinline__ uint32_t smem_u32(const void* p) {
    uint32_t a;
    asm("{ .reg .u64 t; cvta.to.shared.u64 t, %1; cvt.u32.u64 %0, t; }"
        : "=r"(a) : "l"(p));
    return a;
}

#define CPA(d, s) \
    asm volatile("cp.async.ca.shared.global [%0], [%1], 16;" :: "r"(d), "l"(s) : "memory")
#define CPC()  asm volatile("cp.async.commit_group;" ::: "memory")
#define CPW(n) asm volatile("cp.async.wait_group %0;" :: "n"(n) : "memory")

__device__ __forceinline__ float hswf(float v) {
    return v * fminf(fmaxf(v + 3.0f, 0.0f), 6.0f) * (1.0f / 6.0f);
}

// A-type layout: word position of k-pair (k even) within a row
__device__ __forceinline__ int wslotA(int k) {
    int q = (k >> 1) & 7;
    int pos = ((q & 3) << 1) | (q >> 2);
    return ((k >> 4) << 3) + pos;
}

__device__ __forceinline__ void mma16816(float* d, uint32_t a0, uint32_t a1,
                                         uint32_t a2, uint32_t a3,
                                         uint32_t b0, uint32_t b1) {
    asm volatile(
        "mma.sync.aligned.m16n8k16.row.col.f32.f16.f16.f32 "
        "{%0,%1,%2,%3}, {%4,%5,%6,%7}, {%8,%9}, {%0,%1,%2,%3};"
        : "+f"(d[0]), "+f"(d[1]), "+f"(d[2]), "+f"(d[3])
        : "r"(a0), "r"(a1), "r"(a2), "r"(a3), "r"(b0), "r"(b1));
}

// dual-m-tile single-term GEMM (4 n-blocks = 32 cols per warp)
__device__ __forceinline__ void gemm_dual(
    const uint32_t* __restrict__ A, const uint32_t* __restrict__ B,
    float (&accA)[4][4], float (&accB)[4][4],
    int mta, int mtb, int ks0, int kaEnd, int kbEnd, int g, int c, int c0) {
    for (int ks = ks0; ks < kbEnd; ks++) {
        int off = ks * 8 + c * 2;
        uint2 vb[4];
#pragma unroll
        for (int nt = 0; nt < 4; nt++)
            vb[nt] = *(const uint2*)(B + (c0 + nt * 8 + g) * PWA + off);
        uint2 tb0 = *(const uint2*)(A + (mtb * 16 + g) * PWA + off);
        uint2 tb1 = *(const uint2*)(A + (mtb * 16 + g + 8) * PWA + off);
        bool doA = (ks < kaEnd);
        uint2 ta0, ta1;
        if (doA) {
            ta0 = *(const uint2*)(A + (mta * 16 + g) * PWA + off);
            ta1 = *(const uint2*)(A + (mta * 16 + g + 8) * PWA + off);
        }
#pragma unroll
        for (int nt = 0; nt < 4; nt++)
            mma16816(accB[nt], tb0.x, tb1.x, tb0.y, tb1.y, vb[nt].x, vb[nt].y);
        if (doA) {
#pragma unroll
            for (int nt = 0; nt < 4; nt++)
                mma16816(accA[nt], ta0.x, ta1.x, ta0.y, ta1.y, vb[nt].x, vb[nt].y);
        }
    }
}

// shfl-paired transposed store (single fp16): even-g lane stores pair word
__device__ __forceinline__ void storeTs(uint32_t* img, int f, int t, float v,
                                        int g) {
    float vp = __shfl_xor_sync(0xffffffffu, v, 4);
    if (!(g & 1)) {
        __half2 h2;
        h2.x = __float2half(v);
        h2.y = __float2half(vp);
        img[f * PWA + wslotA(t)] = *(uint32_t*)&h2;
    }
}

// full A-type image copy: 2304 lines of 16B
__device__ __forceinline__ void cpa_fullA(uint32_t dst, const uint32_t* src,
                                          int tid) {
#pragma unroll
    for (int j = 0; j < 4; j++) {
        int l = tid + NTH * j;
        CPA(dst + l * 16, (const char*)src + l * 16);
    }
    if (tid < 256) {
        int l = tid + NTH * 4;
        CPA(dst + l * 16, (const char*)src + l * 16);
    }
}

// trimmed A-type L-image copy (16 data lines per row)
template <int TK>
__device__ __forceinline__ void cpa_LA(uint32_t dst, const uint32_t* src,
                                       int tid) {
#pragma unroll
    for (int i = tid; i < 128 * 16; i += NTH) {
        int row = i >> 4, li = i & 15;
        bool need;
        if (TK == 128) need = (li >> 1) <= (row >> 4);
        else {
            int b0 = (row / TK) * (TK / 8);
            need = (li >= b0) && (li < b0 + TK / 8);
        }
        if (need) {
            int off = row * PWA + li * 4;
            CPA(dst + off * 4, (const char*)(src + off));
        }
    }
}

// ============================================================================
// kW: precompute operand images (all single fp16, A-type layout)
// ============================================================================
__global__ void kW(const float* __restrict__ cw0, const float* __restrict__ cw1,
                   const float* __restrict__ cw2,
                   const float* __restrict__ L10, const float* __restrict__ L20,
                   const float* __restrict__ L11, const float* __restrict__ L21,
                   const float* __restrict__ L12, const float* __restrict__ L22) {
    int b = blockIdx.x;
    if (b < 7) {
        int s, kk;
        if (b == 0)      { s = 0; kk = 0; }
        else if (b < 3)  { s = 1; kk = b - 1; }
        else             { s = 2; kk = b - 3; }
        const float* cw = (s == 0) ? cw0 : (s == 1) ? cw1 : cw2;
        int k = 1 << s;
        uint32_t* dst = g_Wimg[b];
        for (int idx = threadIdx.x; idx < 128 * 64; idx += blockDim.x) {
            int o = idx >> 6, i = (idx & 63) << 1;
            __half2 h2;
            h2.x = __float2half(cw[(o * 128 + i) * k + kk]);
            h2.y = __float2half(cw[(o * 128 + i + 1) * k + kk]);
            dst[o * PWA + wslotA(i)] = *(uint32_t*)&h2;
        }
    } else {
        int j = b - 7;
        int s = j >> 1, m = j & 1;
        const float* L = (s == 0) ? (m ? L20 : L10)
                       : (s == 1) ? (m ? L21 : L11)
                                  : (m ? L22 : L12);
        int tk = 128 >> s;
        uint32_t* dst = g_LimgA[j];
        for (int idx = threadIdx.x; idx < 128 * 64; idx += blockDim.x) {
            int t = idx >> 6, sc = (idx & 63) << 1;
            float v[2];
#pragma unroll
            for (int e = 0; e < 2; e++) {
                int scc = sc + e;
                float vv = 0.0f;
                if ((t / tk) == (scc / tk)) {
                    int tp = t % tk, sp = scc % tk;
                    if (sp <= tp) vv = L[tp * tk + sp];
                }
                v[e] = vv;
            }
            __half2 h2;
            h2.x = __float2half(v[0]);
            h2.y = __float2half(v[1]);
            dst[t * PWA + wslotA(sc)] = *(uint32_t*)&h2;
        }
    }
}

// ============================================================================
// run_scale
// ============================================================================
template <int TK>
__device__ __noinline__ void run_scale(
    const float* __restrict__ x, int n0run, int q0,
    const float* __restrict__ lg, const float* __restrict__ lb,
    const uint32_t* __restrict__ L1g, const uint32_t* __restrict__ L2g,
    int hoff, const float* __restrict__ cb, float fcb, bool first) {

    constexpr int K = 128 / TK;
    extern __shared__ uint32_t smw[];
    uint32_t* X  = smw + X_OFF;
    uint32_t* L1 = smw + L1_OFF;
    uint32_t* L2 = smw + L2_OFF;
    uint32_t* WB = smw + WB_OFF;
    uint32_t* HT = smw + HT_OFF;
    float* scr   = (float*)(smw + SCR_BASE);
    float* s_fcw = scr + 32;
    float* s_cb  = scr + 160;
    float* scrF  = scr + 288;

    const int tid = threadIdx.x;
    const int w = tid >> 5, lane = tid & 31;
    const int w3 = w & 3;
    const int g = lane >> 2, c = lane & 3;
    const int c0 = (w >> 2) * 32;
    const uint32_t L1u = smem_u32(L1), L2u = smem_u32(L2), WBu = smem_u32(WB);

    int mta, mtb;
    if (TK == 128)     { mta = w3;                          mtb = 7 - w3; }
    else if (TK == 64) { mta = ((w3 >> 1) << 2) + (w3 & 1); mtb = ((w3 >> 1) << 2) + 3 - (w3 & 1); }
    else               { mta = w3 << 1;                     mtb = (w3 << 1) + 1; }
    const int myg = (TK == 128) ? 0 : (TK == 64 ? (w3 >> 1) : w3);
    const int ks0 = (myg * TK) >> 4;

    if (first) {
        cpa_LA<TK>(L1u, L1g, tid);
        cpa_LA<TK>(L2u, L2g, tid);
        CPC();
        if (tid < 128) s_cb[tid] = cb[tid];
    }

    float accA[4][4], accB[4][4], fcT[4];
#pragma unroll
    for (int i = 0; i < 4; i++) fcT[i] = 0.0f;
#pragma unroll
    for (int nt = 0; nt < 4; nt++)
#pragma unroll
        for (int e = 0; e < 4; e++) { accA[nt][e] = 0.0f; accB[nt][e] = 0.0f; }

    // ---------------- conv over K chunks ----------------
    for (int kk = 0; kk < K; kk++) {
        if (K > 1 || (first && kk == 0)) {   // W persists in WB for K==1
            cpa_fullA(WBu, g_Wimg[q0 + kk], tid);
            CPC();
        }
#pragma unroll 2
        for (int it = 0; it < 8; it++) {
            int r = it * 16 + (tid >> 5);
            int f4 = tid & 31;
            const float4 v = ((const float4*)(x +
                ((size_t)(n0run + r / TK) * 128 + (r & (TK - 1)) * K + kk) * 128))[f4];
            __half2 h0, h1;
            h0.x = __float2half(v.x); h0.y = __float2half(v.y);
            h1.x = __float2half(v.z); h1.y = __float2half(v.w);
            int k2 = f4 << 2;
            X[r * PWA + wslotA(k2)]     = *(uint32_t*)&h0;
            X[r * PWA + wslotA(k2 + 2)] = *(uint32_t*)&h1;
        }
        CPW(0);
        __syncthreads();
        gemm_dual(X, WB, accA, accB, mta, mtb, 0, 8, 8, g, c, c0);
        __syncthreads();
    }

    // ---------------- LN stats ----------------
    float s = 0.0f, s2 = 0.0f;
#pragma unroll
    for (int ti = 0; ti < 2; ti++)
#pragma unroll
        for (int nt = 0; nt < 4; nt++)
#pragma unroll
            for (int e = 0; e < 4; e++) {
                int f = c0 + nt * 8 + (c << 1) + (e & 1);
                float v = (ti ? accB[nt][e] : accA[nt][e]) + s_cb[f];
                s += v; s2 += v * v;
            }
#pragma unroll
    for (int o = 16; o; o >>= 1) {
        s  += __shfl_down_sync(0xffffffffu, s, o);
        s2 += __shfl_down_sync(0xffffffffu, s2, o);
    }
    if (lane == 0) { scr[w] = s; scr[16 + w] = s2; }
    __syncthreads();

    float gs = 0.0f, gs2 = 0.0f;
#pragma unroll
    for (int p = 0; p < 16; p++) {
        int p3 = p & 3;
        int pg = (TK == 128) ? 0 : (TK == 64 ? (p3 >> 1) : p3);
        if (pg == myg) { gs += scr[p]; gs2 += scr[16 + p]; }
    }
    const float inv = 1.0f / (float)(TK * 128);
    float mu = gs * inv;
    float var = gs2 * inv - mu * mu;
    float rinv = rsqrtf(var + 1e-5f);

    // ---------------- hT -> HT ; fc conv-part ----------------
#pragma unroll
    for (int ti = 0; ti < 2; ti++) {
        int mt = ti ? mtb : mta;
#pragma unroll
        for (int nt = 0; nt < 4; nt++)
#pragma unroll
            for (int eh = 0; eh < 2; eh++) {
                int t = mt * 16 + g + 8 * eh;
                int tl = t & (TK - 1);
                int fb = c0 + nt * 8 + (c << 1);
                float2 lgv = *(const float2*)(lg + tl * 128 + fb);
                float2 lbv = *(const float2*)(lb + tl * 128 + fb);
#pragma unroll
                for (int eo = 0; eo < 2; eo++) {
                    float v = (ti ? accB[nt][eh * 2 + eo] : accA[nt][eh * 2 + eo])
                              + s_cb[fb + eo];
                    fcT[ti * 2 + eh] += v * s_fcw[fb + eo];
                    float hh = (v - mu) * rinv * (eo ? lgv.y : lgv.x)
                               + (eo ? lbv.y : lbv.x);
                    storeTs(HT, fb + eo, t, hh, g);
                }
            }
    }
    __syncthreads();

    // ---------------- GEMM1: u = L1m @ h ----------------
#pragma unroll
    for (int nt = 0; nt < 4; nt++)
#pragma unroll
        for (int e = 0; e < 4; e++) { accA[nt][e] = 0.0f; accB[nt][e] = 0.0f; }
    gemm_dual(L1, HT, accA, accB, mta, mtb, ks0, mta + 1, mtb + 1, g, c, c0);
    __syncthreads();

    // ---------------- uT = hsw(u) -> HT ----------------
#pragma unroll
    for (int ti = 0; ti < 2; ti++) {
        int mt = ti ? mtb : mta;
#pragma unroll
        for (int nt = 0; nt < 4; nt++)
#pragma unroll
            for (int e = 0; e < 4; e++) {
                int t = mt * 16 + g + ((e >> 1) << 3);
                int f = c0 + nt * 8 + (c << 1) + (e & 1);
                storeTs(HT, f, t, hswf(ti ? accB[nt][e] : accA[nt][e]), g);
            }
    }
    __syncthreads();

    // ---------------- GEMM2: v = L2m @ u ; fc v-part ----------------
#pragma unroll
    for (int nt = 0; nt < 4; nt++)
#pragma unroll
        for (int e = 0; e < 4; e++) { accA[nt][e] = 0.0f; accB[nt][e] = 0.0f; }
    gemm_dual(L2, HT, accA, accB, mta, mtb, ks0, mta + 1, mtb + 1, g, c, c0);
#pragma unroll
    for (int ti = 0; ti < 2; ti++)
#pragma unroll
        for (int nt = 0; nt < 4; nt++)
#pragma unroll
            for (int e = 0; e < 4; e++) {
                int f = c0 + nt * 8 + (c << 1) + (e & 1);
                fcT[ti * 2 + (e >> 1)] +=
                    (ti ? accB[nt][e] : accA[nt][e]) * s_fcw[f];
            }

    // ---------------- fc reduce -> g_h ----------------
#pragma unroll
    for (int i = 0; i < 4; i++) {
        fcT[i] += __shfl_xor_sync(0xffffffffu, fcT[i], 1);
        fcT[i] += __shfl_xor_sync(0xffffffffu, fcT[i], 2);
    }
    if (c == 0) {
#pragma unroll
        for (int i = 0; i < 4; i++) {
            int t = ((i >> 1) ? mtb : mta) * 16 + g + 8 * (i & 1);
            scrF[(w >> 2) * 128 + t] = fcT[i];
        }
    }
    __syncthreads();
    if (tid < 128) {
        int t = tid;
        float d = scrF[t] + scrF[128 + t] + scrF[256 + t] + scrF[384 + t];
        g_h[(n0run + t / TK) * 224 + hoff + (t & (TK - 1))] = d + fcb;
    }
    __syncthreads();
}

__global__ void __launch_bounds__(NTH, 1) kA7(
    const float* __restrict__ x,
    const float* __restrict__ cb0, const float* __restrict__ lg0,
    const float* __restrict__ lb0,
    const float* __restrict__ cb1, const float* __restrict__ lg1,
    const float* __restrict__ lb1,
    const float* __restrict__ cb2, const float* __restrict__ lg2,
    const float* __restrict__ lb2,
    const float* __restrict__ fcw, const float* __restrict__ fcbp) {
    extern __shared__ uint32_t smw[];
    float* scr = (float*)(smw + SCR_BASE);
    if (threadIdx.x < 128) scr[32 + threadIdx.x] = fcw[threadIdx.x];
    float fcb = fcbp[0];
    int n0 = blockIdx.x * 4;

    run_scale<128>(x, n0 + 0, 0, lg0, lb0, g_LimgA[0], g_LimgA[1], 0, cb0, fcb, true);
    run_scale<128>(x, n0 + 1, 0, lg0, lb0, g_LimgA[0], g_LimgA[1], 0, cb0, fcb, false);
    run_scale<128>(x, n0 + 2, 0, lg0, lb0, g_LimgA[0], g_LimgA[1], 0, cb0, fcb, false);
    run_scale<128>(x, n0 + 3, 0, lg0, lb0, g_LimgA[0], g_LimgA[1], 0, cb0, fcb, false);

    run_scale<64>(x, n0 + 0, 1, lg1, lb1, g_LimgA[2], g_LimgA[3], 128, cb1, fcb, true);
    run_scale<64>(x, n0 + 2, 1, lg1, lb1, g_LimgA[2], g_LimgA[3], 128, cb1, fcb, false);

    run_scale<32>(x, n0 + 0, 3, lg2, lb2, g_LimgA[4], g_LimgA[5], 192, cb2, fcb, true);
}

// ============================================================================
// phase 2
// ============================================================================
__device__ __forceinline__ void bred2(float& s, float& s2, float* scr) {
#pragma unroll
    for (int o = 16; o > 0; o >>= 1) {
        s  += __shfl_down_sync(0xffffffffu, s, o);
        s2 += __shfl_down_sync(0xffffffffu, s2, o);
    }
    int w = threadIdx.x >> 5, l = threadIdx.x & 31;
    if (l == 0) { scr[w] = s; scr[32 + w] = s2; }
    __syncthreads();
    if (threadIdx.x == 0) {
        float a = 0.f, b = 0.f;
        int nw = (blockDim.x + 31) >> 5;
        for (int i = 0; i < nw; i++) { a += scr[i]; b += scr[32 + i]; }
        scr[0] = a; scr[32] = b;
    }
    __syncthreads();
    s = scr[0]; s2 = scr[32];
}

__global__ void kB1() {
    float s = 0.f, s2 = 0.f;
    int base = blockIdx.x * 16 * 224;
    for (int idx = threadIdx.x; idx < 16 * 224; idx += 256) {
        float v = g_h[base + idx];
        s += v; s2 += v * v;
    }
    __shared__ float scr[64];
    bred2(s, s2, scr);
    if (threadIdx.x == 0) { g_bpart[blockIdx.x] = s; g_bpart[256 + blockIdx.x] = s2; }
}

__global__ void kB2() {
    float s = g_bpart[threadIdx.x];
    float s2 = g_bpart[256 + threadIdx.x];
    __shared__ float scr[64];
    bred2(s, s2, scr);
    if (threadIdx.x == 0) {
        const float inv = 1.0f / (4096.0f * 224.0f);
        float mu = s * inv;
        float var = s2 * inv - mu * mu;
        g_stats[0] = mu;
        g_stats[1] = rsqrtf(var + 1e-5f);
    }
}

__global__ void kC1(const float* __restrict__ M1,
                    const float* __restrict__ slg,
                    const float* __restrict__ slb) {
    int j = threadIdx.x;
    int b = blockIdx.x;
    float mu = g_stats[0], rinv = g_stats[1];
    float acc[64];
#pragma unroll
    for (int m = 0; m < 64; m++) acc[m] = 0.f;
    int n0 = b * 128;
    for (int n = n0; n < n0 + 128; n++) {
        int off = n * 224 + j;
        float hn = (g_h[off] - mu) * rinv * slg[off] + slb[off];
#pragma unroll
        for (int m = 0; m < 64; m++) acc[m] += M1[m * 4096 + n] * hn;
    }
#pragma unroll
    for (int m = 0; m < 64; m++) g_cpart[(b * 64 + m) * 224 + j] = acc[m];
}

__global__ void kC2(const float* __restrict__ smw_) {
    int m = blockIdx.x, j = threadIdx.x;
    float g = 0.f;
    for (int b = 0; b < 32; b++) g += g_cpart[(b * 64 + m) * 224 + j];
    float v = hswf(g) * smw_[224 + j];
    float dummy = 0.f;
    __shared__ float scr[64];
    bred2(v, dummy, scr);
    if (threadIdx.x == 0) g_gw[m] = v;
}

__global__ void kD(const float* __restrict__ M2,
                   const float* __restrict__ smw_,
                   const float* __restrict__ smb,
                   float* __restrict__ out) {
    int warp = threadIdx.x >> 5, lane = threadIdx.x & 31;
    int n = blockIdx.x * 8 + warp;
    float acc = 0.f;
    for (int j = lane; j < 224; j += 32)
        acc += g_h[n * 224 + j] * (smw_[j] + smw_[224 + j]);
    for (int m = lane; m < 64; m += 32)
        acc += M2[n * 64 + m] * g_gw[m];
#pragma unroll
    for (int o = 16; o > 0; o >>= 1)
        acc += __shfl_down_sync(0xffffffffu, acc, o);
    if (lane == 0) out[n] = acc + smb[0];
}

// ============================================================================
extern "C" void kernel_launch(void* const* d_in, const int* in_sizes, int n_in,
                              void* d_out, int out_size) {
    const float* x   = (const float*)d_in[0];
    const float* cw0 = (const float*)d_in[1];
    const float* cb0 = (const float*)d_in[2];
    const float* lg0 = (const float*)d_in[3];
    const float* lb0 = (const float*)d_in[4];
    const float* L10 = (const float*)d_in[5];
    const float* L20 = (const float*)d_in[6];
    const float* cw1 = (const float*)d_in[7];
    const float* cb1 = (const float*)d_in[8];
    const float* lg1 = (const float*)d_in[9];
    const float* lb1 = (const float*)d_in[10];
    const float* L11 = (const float*)d_in[11];
    const float* L21 = (const float*)d_in[12];
    const float* cw2 = (const float*)d_in[13];
    const float* cb2 = (const float*)d_in[14];
    const float* lg2 = (const float*)d_in[15];
    const float* lb2 = (const float*)d_in[16];
    const float* L12 = (const float*)d_in[17];
    const float* L22 = (const float*)d_in[18];
    const float* fcw = (const float*)d_in[19];
    const float* fcb = (const float*)d_in[20];
    const float* slg = (const float*)d_in[21];
    const float* slb = (const float*)d_in[22];
    const float* M1  = (const float*)d_in[23];
    const float* M2  = (const float*)d_in[24];
    const float* smw = (const float*)d_in[25];
    const float* smb = (const float*)d_in[26];
    float* out = (float*)d_out;

    cudaFuncSetAttribute(kA7, cudaFuncAttributeMaxDynamicSharedMemorySize, SMEM_SZ);

    kW<<<13, 256>>>(cw0, cw1, cw2, L10, L20, L11, L21, L12, L22);
    kA7<<<1024, NTH, SMEM_SZ>>>(x, cb0, lg0, lb0, cb1, lg1, lb1,
                                cb2, lg2, lb2, fcw, fcb);
    kB1<<<256, 256>>>();
    kB2<<<1, 256>>>();
    kC1<<<32, 224>>>(M1, slg, slb);
    kC2<<<64, 224>>>(smw);
    kD<<<512, 256>>>(M2, smw, smb, out);
}

// round 8
// speedup vs baseline: 5.5475x; 1.0454x over previous
#include <cuda_runtime.h>
#include <cuda_fp16.h>
#include <cstdint>

// ============================================================================
// StockMixer GB300 — R8: single-term fp16 mma.sync with fragment-major gmem
// operands (W, L1, L2 read directly via coalesced LDG into mma fragments;
// no cp.async staging). Smem holds only X and HT images (77 KB).
// ============================================================================

#define PWA 72
#define AIMG_WORDS (128 * PWA)         // 9216 words = 36864 B

#define X_OFF  0
#define HT_OFF 9216
#define SCR_BASE 18432
#define SMEM_SZ ((18432 + 832) * 4)    // 77056 B

#define NTH 512

// -------------------- device globals --------------------
// W fragments: [chunk][((wg*8+ks)*4+nt)*32 + lane] (uint2 = b0,b1)
__device__ __align__(16) uint2 g_Wf[7][4096];
// L fragments: [img][(mt*8+ks)*32 + lane] (uint4 = a0,a1,a2,a3)
__device__ __align__(16) uint4 g_Lf[6][2048];
__device__ float g_h[4096 * 224];
__device__ float g_bpart[512];
__device__ float g_stats[2];
__device__ float g_cpart[32 * 64 * 224];
__device__ float g_gw[64];

// -------------------- helpers --------------------
__device__ __forceinline__ float hswf(float v) {
    return v * fminf(fmaxf(v + 3.0f, 0.0f), 6.0f) * (1.0f / 6.0f);
}

// A-type smem layout: word position of k-pair (k even) within a row
__device__ __forceinline__ int wslotA(int k) {
    int q = (k >> 1) & 7;
    int pos = ((q & 3) << 1) | (q >> 2);
    return ((k >> 4) << 3) + pos;
}

__device__ __forceinline__ void mma16816(float* d, uint32_t a0, uint32_t a1,
                                         uint32_t a2, uint32_t a3,
                                         uint32_t b0, uint32_t b1) {
    asm volatile(
        "mma.sync.aligned.m16n8k16.row.col.f32.f16.f16.f32 "
        "{%0,%1,%2,%3}, {%4,%5,%6,%7}, {%8,%9}, {%0,%1,%2,%3};"
        : "+f"(d[0]), "+f"(d[1]), "+f"(d[2]), "+f"(d[3])
        : "r"(a0), "r"(a1), "r"(a2), "r"(a3), "r"(b0), "r"(b1));
}

// conv GEMM: A = X (smem, dual m-tiles), B = W fragments (gmem, direct LDG)
__device__ __forceinline__ void gemm_XW(
    const uint32_t* __restrict__ X, const uint2* __restrict__ Wf,
    float (&accA)[4][4], float (&accB)[4][4],
    int mta, int mtb, int wg, int g, int c, int lane) {
#pragma unroll 2
    for (int ks = 0; ks < 8; ks++) {
        int off = ks * 8 + c * 2;
        const uint2* wfp = Wf + (wg * 8 + ks) * 128 + lane;
        uint2 vb[4];
#pragma unroll
        for (int nt = 0; nt < 4; nt++) vb[nt] = wfp[nt * 32];
        uint2 ta0 = *(const uint2*)(X + (mta * 16 + g) * PWA + off);
        uint2 ta1 = *(const uint2*)(X + (mta * 16 + g + 8) * PWA + off);
        uint2 tb0 = *(const uint2*)(X + (mtb * 16 + g) * PWA + off);
        uint2 tb1 = *(const uint2*)(X + (mtb * 16 + g + 8) * PWA + off);
#pragma unroll
        for (int nt = 0; nt < 4; nt++)
            mma16816(accA[nt], ta0.x, ta1.x, ta0.y, ta1.y, vb[nt].x, vb[nt].y);
#pragma unroll
        for (int nt = 0; nt < 4; nt++)
            mma16816(accB[nt], tb0.x, tb1.x, tb0.y, tb1.y, vb[nt].x, vb[nt].y);
    }
}

// time-mix GEMM: A = L fragments (gmem direct LDG, dual tiles), B = HT (smem)
__device__ __forceinline__ void gemm_LHT(
    const uint4* __restrict__ Lf, const uint32_t* __restrict__ HT,
    float (&accA)[4][4], float (&accB)[4][4],
    int mta, int mtb, int ks0, int g, int c, int c0, int lane) {
    for (int ks = ks0; ks <= mtb; ks++) {
        int off = ks * 8 + c * 2;
        uint2 vb[4];
#pragma unroll
        for (int nt = 0; nt < 4; nt++)
            vb[nt] = *(const uint2*)(HT + (c0 + nt * 8 + g) * PWA + off);
        uint4 bv = Lf[(mtb * 8 + ks) * 32 + lane];
#pragma unroll
        for (int nt = 0; nt < 4; nt++)
            mma16816(accB[nt], bv.x, bv.y, bv.z, bv.w, vb[nt].x, vb[nt].y);
        if (ks <= mta) {
            uint4 av = Lf[(mta * 8 + ks) * 32 + lane];
#pragma unroll
            for (int nt = 0; nt < 4; nt++)
                mma16816(accA[nt], av.x, av.y, av.z, av.w, vb[nt].x, vb[nt].y);
        }
    }
}

// shfl-paired transposed store (single fp16): even-g lane stores pair word
__device__ __forceinline__ void storeTs(uint32_t* img, int f, int t, float v,
                                        int g) {
    float vp = __shfl_xor_sync(0xffffffffu, v, 4);
    if (!(g & 1)) {
        __half2 h2;
        h2.x = __float2half(v);
        h2.y = __float2half(vp);
        img[f * PWA + wslotA(t)] = *(uint32_t*)&h2;
    }
}

// ============================================================================
// kW: build fragment-major operand images
// ============================================================================
__global__ void kW(const float* __restrict__ cw0, const float* __restrict__ cw1,
                   const float* __restrict__ cw2,
                   const float* __restrict__ L10, const float* __restrict__ L20,
                   const float* __restrict__ L11, const float* __restrict__ L21,
                   const float* __restrict__ L12, const float* __restrict__ L22) {
    int b = blockIdx.x;
    if (b < 7) {                           // W fragments
        int s, kk;
        if (b == 0)      { s = 0; kk = 0; }
        else if (b < 3)  { s = 1; kk = b - 1; }
        else             { s = 2; kk = b - 3; }
        const float* cw = (s == 0) ? cw0 : (s == 1) ? cw1 : cw2;
        int k = 1 << s;
        uint2* dst = g_Wf[b];
        for (int idx = threadIdx.x; idx < 4096; idx += blockDim.x) {
            int lane = idx & 31;
            int nt = (idx >> 5) & 3;
            int ks = (idx >> 7) & 7;
            int wg = idx >> 10;
            int g = lane >> 2, c = lane & 3;
            int row = wg * 32 + nt * 8 + g;      // out feature o
            int k0 = ks * 16 + 2 * c;            // in feature i
            __half2 b0, b1;
            b0.x = __float2half(cw[(row * 128 + k0) * k + kk]);
            b0.y = __float2half(cw[(row * 128 + k0 + 1) * k + kk]);
            b1.x = __float2half(cw[(row * 128 + k0 + 8) * k + kk]);
            b1.y = __float2half(cw[(row * 128 + k0 + 9) * k + kk]);
            uint2 o;
            o.x = *(uint32_t*)&b0;
            o.y = *(uint32_t*)&b1;
            dst[idx] = o;
        }
    } else {                               // L fragments (masked block-diag)
        int j = b - 7;
        int s = j >> 1, m = j & 1;
        const float* L = (s == 0) ? (m ? L20 : L10)
                       : (s == 1) ? (m ? L21 : L11)
                                  : (m ? L22 : L12);
        int tk = 128 >> s;
        uint4* dst = g_Lf[j];
        for (int idx = threadIdx.x; idx < 2048; idx += blockDim.x) {
            int lane = idx & 31;
            int ks = (idx >> 5) & 7;
            int mt = idx >> 8;
            int g = lane >> 2, c = lane & 3;
            int r0 = mt * 16 + g, r1 = r0 + 8;
            int k0 = ks * 16 + 2 * c;
            float v[8];
#pragma unroll
            for (int e = 0; e < 8; e++) {
                int t = (e & 1) ? r1 : r0;
                int sc = k0 + ((e >> 2) << 3) + ((e >> 1) & 1);
                float vv = 0.0f;
                if ((t / tk) == (sc / tk)) {
                    int tp = t % tk, sp = sc % tk;
                    if (sp <= tp) vv = L[tp * tk + sp];
                }
                v[e] = vv;
            }
            __half2 a0, a1, a2, a3;
            a0.x = __float2half(v[0]); a0.y = __float2half(v[2]);
            a1.x = __float2half(v[1]); a1.y = __float2half(v[3]);
            a2.x = __float2half(v[4]); a2.y = __float2half(v[6]);
            a3.x = __float2half(v[5]); a3.y = __float2half(v[7]);
            uint4 o;
            o.x = *(uint32_t*)&a0;
            o.y = *(uint32_t*)&a1;
            o.z = *(uint32_t*)&a2;
            o.w = *(uint32_t*)&a3;
            dst[idx] = o;
        }
    }
}

// ============================================================================
// run_scale
// ============================================================================
template <int TK>
__device__ __noinline__ void run_scale(
    const float* __restrict__ x, int n0run, int q0,
    const float* __restrict__ lg, const float* __restrict__ lb,
    const uint4* __restrict__ L1f, const uint4* __restrict__ L2f,
    int hoff, const float* __restrict__ cb, float fcb, bool first) {

    constexpr int K = 128 / TK;
    extern __shared__ uint32_t smw[];
    uint32_t* X  = smw + X_OFF;
    uint32_t* HT = smw + HT_OFF;
    float* scr   = (float*)(smw + SCR_BASE);
    float* s_fcw = scr + 32;
    float* s_cb  = scr + 160;
    float* scrF  = scr + 288;

    const int tid = threadIdx.x;
    const int w = tid >> 5, lane = tid & 31;
    const int w3 = w & 3;
    const int wg = w >> 2;
    const int g = lane >> 2, c = lane & 3;
    const int c0 = wg * 32;

    int mta, mtb;
    if (TK == 128)     { mta = w3;                          mtb = 7 - w3; }
    else if (TK == 64) { mta = ((w3 >> 1) << 2) + (w3 & 1); mtb = ((w3 >> 1) << 2) + 3 - (w3 & 1); }
    else               { mta = w3 << 1;                     mtb = (w3 << 1) + 1; }
    const int myg = (TK == 128) ? 0 : (TK == 64 ? (w3 >> 1) : w3);
    const int ks0 = (myg * TK) >> 4;

    if (first && tid < 128) s_cb[tid] = cb[tid];

    float accA[4][4], accB[4][4], fcT[4];
#pragma unroll
    for (int i = 0; i < 4; i++) fcT[i] = 0.0f;
#pragma unroll
    for (int nt = 0; nt < 4; nt++)
#pragma unroll
        for (int e = 0; e < 4; e++) { accA[nt][e] = 0.0f; accB[nt][e] = 0.0f; }

    // ---------------- conv over K chunks ----------------
    for (int kk = 0; kk < K; kk++) {
#pragma unroll
        for (int it = 0; it < 8; it++) {
            int r = it * 16 + (tid >> 5);
            int f4 = tid & 31;
            const float4 v = ((const float4*)(x +
                ((size_t)(n0run + r / TK) * 128 + (r & (TK - 1)) * K + kk) * 128))[f4];
            __half2 h0, h1;
            h0.x = __float2half(v.x); h0.y = __float2half(v.y);
            h1.x = __float2half(v.z); h1.y = __float2half(v.w);
            int k2 = f4 << 2;
            X[r * PWA + wslotA(k2)]     = *(uint32_t*)&h0;
            X[r * PWA + wslotA(k2 + 2)] = *(uint32_t*)&h1;
        }
        __syncthreads();
        gemm_XW(X, g_Wf[q0 + kk], accA, accB, mta, mtb, wg, g, c, lane);
        __syncthreads();
    }

    // ---------------- LN stats ----------------
    float s = 0.0f, s2 = 0.0f;
#pragma unroll
    for (int ti = 0; ti < 2; ti++)
#pragma unroll
        for (int nt = 0; nt < 4; nt++)
#pragma unroll
            for (int e = 0; e < 4; e++) {
                int f = c0 + nt * 8 + (c << 1) + (e & 1);
                float v = (ti ? accB[nt][e] : accA[nt][e]) + s_cb[f];
                s += v; s2 += v * v;
            }
#pragma unroll
    for (int o = 16; o; o >>= 1) {
        s  += __shfl_down_sync(0xffffffffu, s, o);
        s2 += __shfl_down_sync(0xffffffffu, s2, o);
    }
    if (lane == 0) { scr[w] = s; scr[16 + w] = s2; }
    __syncthreads();

    float gs = 0.0f, gs2 = 0.0f;
#pragma unroll
    for (int p = 0; p < 16; p++) {
        int p3 = p & 3;
        int pg = (TK == 128) ? 0 : (TK == 64 ? (p3 >> 1) : p3);
        if (pg == myg) { gs += scr[p]; gs2 += scr[16 + p]; }
    }
    const float inv = 1.0f / (float)(TK * 128);
    float mu = gs * inv;
    float var = gs2 * inv - mu * mu;
    float rinv = rsqrtf(var + 1e-5f);

    // ---------------- hT -> HT ; fc conv-part ----------------
#pragma unroll
    for (int ti = 0; ti < 2; ti++) {
        int mt = ti ? mtb : mta;
#pragma unroll
        for (int nt = 0; nt < 4; nt++)
#pragma unroll
            for (int eh = 0; eh < 2; eh++) {
                int t = mt * 16 + g + 8 * eh;
                int tl = t & (TK - 1);
                int fb = c0 + nt * 8 + (c << 1);
                float2 lgv = *(const float2*)(lg + tl * 128 + fb);
                float2 lbv = *(const float2*)(lb + tl * 128 + fb);
#pragma unroll
                for (int eo = 0; eo < 2; eo++) {
                    float v = (ti ? accB[nt][eh * 2 + eo] : accA[nt][eh * 2 + eo])
                              + s_cb[fb + eo];
                    fcT[ti * 2 + eh] += v * s_fcw[fb + eo];
                    float hh = (v - mu) * rinv * (eo ? lgv.y : lgv.x)
                               + (eo ? lbv.y : lbv.x);
                    storeTs(HT, fb + eo, t, hh, g);
                }
            }
    }
    __syncthreads();

    // ---------------- GEMM1: u = L1m @ h ----------------
#pragma unroll
    for (int nt = 0; nt < 4; nt++)
#pragma unroll
        for (int e = 0; e < 4; e++) { accA[nt][e] = 0.0f; accB[nt][e] = 0.0f; }
    gemm_LHT(L1f, HT, accA, accB, mta, mtb, ks0, g, c, c0, lane);
    __syncthreads();

    // ---------------- uT = hsw(u) -> HT ----------------
#pragma unroll
    for (int ti = 0; ti < 2; ti++) {
        int mt = ti ? mtb : mta;
#pragma unroll
        for (int nt = 0; nt < 4; nt++)
#pragma unroll
            for (int e = 0; e < 4; e++) {
                int t = mt * 16 + g + ((e >> 1) << 3);
                int f = c0 + nt * 8 + (c << 1) + (e & 1);
                storeTs(HT, f, t, hswf(ti ? accB[nt][e] : accA[nt][e]), g);
            }
    }
    __syncthreads();

    // ---------------- GEMM2: v = L2m @ u ; fc v-part ----------------
#pragma unroll
    for (int nt = 0; nt < 4; nt++)
#pragma unroll
        for (int e = 0; e < 4; e++) { accA[nt][e] = 0.0f; accB[nt][e] = 0.0f; }
    gemm_LHT(L2f, HT, accA, accB, mta, mtb, ks0, g, c, c0, lane);
#pragma unroll
    for (int ti = 0; ti < 2; ti++)
#pragma unroll
        for (int nt = 0; nt < 4; nt++)
#pragma unroll
            for (int e = 0; e < 4; e++) {
                int f = c0 + nt * 8 + (c << 1) + (e & 1);
                fcT[ti * 2 + (e >> 1)] +=
                    (ti ? accB[nt][e] : accA[nt][e]) * s_fcw[f];
            }

    // ---------------- fc reduce -> g_h ----------------
#pragma unroll
    for (int i = 0; i < 4; i++) {
        fcT[i] += __shfl_xor_sync(0xffffffffu, fcT[i], 1);
        fcT[i] += __shfl_xor_sync(0xffffffffu, fcT[i], 2);
    }
    if (c == 0) {
#pragma unroll
        for (int i = 0; i < 4; i++) {
            int t = ((i >> 1) ? mtb : mta) * 16 + g + 8 * (i & 1);
            scrF[wg * 128 + t] = fcT[i];
        }
    }
    __syncthreads();
    if (tid < 128) {
        int t = tid;
        float d = scrF[t] + scrF[128 + t] + scrF[256 + t] + scrF[384 + t];
        g_h[(n0run + t / TK) * 224 + hoff + (t & (TK - 1))] = d + fcb;
    }
    __syncthreads();
}

__global__ void __launch_bounds__(NTH, 1) kA8(
    const float* __restrict__ x,
    const float* __restrict__ cb0, const float* __restrict__ lg0,
    const float* __restrict__ lb0,
    const float* __restrict__ cb1, const float* __restrict__ lg1,
    const float* __restrict__ lb1,
    const float* __restrict__ cb2, const float* __restrict__ lg2,
    const float* __restrict__ lb2,
    const float* __restrict__ fcw, const float* __restrict__ fcbp) {
    extern __shared__ uint32_t smw[];
    float* scr = (float*)(smw + SCR_BASE);
    if (threadIdx.x < 128) scr[32 + threadIdx.x] = fcw[threadIdx.x];
    float fcb = fcbp[0];
    int n0 = blockIdx.x * 4;

    run_scale<128>(x, n0 + 0, 0, lg0, lb0, g_Lf[0], g_Lf[1], 0, cb0, fcb, true);
    run_scale<128>(x, n0 + 1, 0, lg0, lb0, g_Lf[0], g_Lf[1], 0, cb0, fcb, false);
    run_scale<128>(x, n0 + 2, 0, lg0, lb0, g_Lf[0], g_Lf[1], 0, cb0, fcb, false);
    run_scale<128>(x, n0 + 3, 0, lg0, lb0, g_Lf[0], g_Lf[1], 0, cb0, fcb, false);

    run_scale<64>(x, n0 + 0, 1, lg1, lb1, g_Lf[2], g_Lf[3], 128, cb1, fcb, true);
    run_scale<64>(x, n0 + 2, 1, lg1, lb1, g_Lf[2], g_Lf[3], 128, cb1, fcb, false);

    run_scale<32>(x, n0 + 0, 3, lg2, lb2, g_Lf[4], g_Lf[5], 192, cb2, fcb, true);
}

// ============================================================================
// phase 2
// ============================================================================
__device__ __forceinline__ void bred2(float& s, float& s2, float* scr) {
#pragma unroll
    for (int o = 16; o > 0; o >>= 1) {
        s  += __shfl_down_sync(0xffffffffu, s, o);
        s2 += __shfl_down_sync(0xffffffffu, s2, o);
    }
    int w = threadIdx.x >> 5, l = threadIdx.x & 31;
    if (l == 0) { scr[w] = s; scr[32 + w] = s2; }
    __syncthreads();
    if (threadIdx.x == 0) {
        float a = 0.f, b = 0.f;
        int nw = (blockDim.x + 31) >> 5;
        for (int i = 0; i < nw; i++) { a += scr[i]; b += scr[32 + i]; }
        scr[0] = a; scr[32] = b;
    }
    __syncthreads();
    s = scr[0]; s2 = scr[32];
}

__global__ void kB1() {
    float s = 0.f, s2 = 0.f;
    int base = blockIdx.x * 16 * 224;
    for (int idx = threadIdx.x; idx < 16 * 224; idx += 256) {
        float v = g_h[base + idx];
        s += v; s2 += v * v;
    }
    __shared__ float scr[64];
    bred2(s, s2, scr);
    if (threadIdx.x == 0) { g_bpart[blockIdx.x] = s; g_bpart[256 + blockIdx.x] = s2; }
}

__global__ void kB2() {
    float s = g_bpart[threadIdx.x];
    float s2 = g_bpart[256 + threadIdx.x];
    __shared__ float scr[64];
    bred2(s, s2, scr);
    if (threadIdx.x == 0) {
        const float inv = 1.0f / (4096.0f * 224.0f);
        float mu = s * inv;
        float var = s2 * inv - mu * mu;
        g_stats[0] = mu;
        g_stats[1] = rsqrtf(var + 1e-5f);
    }
}

__global__ void kC1(const float* __restrict__ M1,
                    const float* __restrict__ slg,
                    const float* __restrict__ slb) {
    int j = threadIdx.x;
    int b = blockIdx.x;
    float mu = g_stats[0], rinv = g_stats[1];
    float acc[64];
#pragma unroll
    for (int m = 0; m < 64; m++) acc[m] = 0.f;
    int n0 = b * 128;
    for (int n = n0; n < n0 + 128; n++) {
        int off = n * 224 + j;
        float hn = (g_h[off] - mu) * rinv * slg[off] + slb[off];
#pragma unroll
        for (int m = 0; m < 64; m++) acc[m] += M1[m * 4096 + n] * hn;
    }
#pragma unroll
    for (int m = 0; m < 64; m++) g_cpart[(b * 64 + m) * 224 + j] = acc[m];
}

__global__ void kC2(const float* __restrict__ smw_) {
    int m = blockIdx.x, j = threadIdx.x;
    float g = 0.f;
    for (int b = 0; b < 32; b++) g += g_cpart[(b * 64 + m) * 224 + j];
    float v = hswf(g) * smw_[224 + j];
    float dummy = 0.f;
    __shared__ float scr[64];
    bred2(v, dummy, scr);
    if (threadIdx.x == 0) g_gw[m] = v;
}

__global__ void kD(const float* __restrict__ M2,
                   const float* __restrict__ smw_,
                   const float* __restrict__ smb,
                   float* __restrict__ out) {
    int warp = threadIdx.x >> 5, lane = threadIdx.x & 31;
    int n = blockIdx.x * 8 + warp;
    float acc = 0.f;
    for (int j = lane; j < 224; j += 32)
        acc += g_h[n * 224 + j] * (smw_[j] + smw_[224 + j]);
    for (int m = lane; m < 64; m += 32)
        acc += M2[n * 64 + m] * g_gw[m];
#pragma unroll
    for (int o = 16; o > 0; o >>= 1)
        acc += __shfl_down_sync(0xffffffffu, acc, o);
    if (lane == 0) out[n] = acc + smb[0];
}

// ============================================================================
extern "C" void kernel_launch(void* const* d_in, const int* in_sizes, int n_in,
                              void* d_out, int out_size) {
    const float* x   = (const float*)d_in[0];
    const float* cw0 = (const float*)d_in[1];
    const float* cb0 = (const float*)d_in[2];
    const float* lg0 = (const float*)d_in[3];
    const float* lb0 = (const float*)d_in[4];
    const float* L10 = (const float*)d_in[5];
    const float* L20 = (const float*)d_in[6];
    const float* cw1 = (const float*)d_in[7];
    const float* cb1 = (const float*)d_in[8];
    const float* lg1 = (const float*)d_in[9];
    const float* lb1 = (const float*)d_in[10];
    const float* L11 = (const float*)d_in[11];
    const float* L21 = (const float*)d_in[12];
    const float* cw2 = (const float*)d_in[13];
    const float* cb2 = (const float*)d_in[14];
    const float* lg2 = (const float*)d_in[15];
    const float* lb2 = (const float*)d_in[16];
    const float* L12 = (const float*)d_in[17];
    const float* L22 = (const float*)d_in[18];
    const float* fcw = (const float*)d_in[19];
    const float* fcb = (const float*)d_in[20];
    const float* slg = (const float*)d_in[21];
    const float* slb = (const float*)d_in[22];
    const float* M1  = (const float*)d_in[23];
    const float* M2  = (const float*)d_in[24];
    const float* smw = (const float*)d_in[25];
    const float* smb = (const float*)d_in[26];
    float* out = (float*)d_out;

    cudaFuncSetAttribute(kA8, cudaFuncAttributeMaxDynamicSharedMemorySize, SMEM_SZ);

    kW<<<13, 256>>>(cw0, cw1, cw2, L10, L20, L11, L21, L12, L22);
    kA8<<<1024, NTH, SMEM_SZ>>>(x, cb0, lg0, lb0, cb1, lg1, lb1,
                                cb2, lg2, lb2, fcw, fcb);
    kB1<<<256, 256>>>();
    kB2<<<1, 256>>>();
    kC1<<<32, 224>>>(M1, slg, slb);
    kC2<<<64, 224>>>(smw);
    kD<<<512, 256>>>(M2, smw, smb, out);
}

// round 9
// speedup vs baseline: 5.8848x; 1.0608x over previous
#include <cuda_runtime.h>
#include <cuda_fp16.h>
#include <cstdint>

// ============================================================================
// StockMixer GB300 — R9: 256-thread / 2-stock blocks, 2 blocks per SM
// (phase-overlap across co-resident blocks). Single-term fp16 mma.sync,
// fragment-major gmem operands, smem only for X and HT (77 KB).
// ============================================================================

#define PWA 72
#define X_OFF  0
#define HT_OFF 9216
#define SCR_BASE 18432
#define SMEM_SZ ((18432 + 832) * 4)    // 77056 B

#define NTH 256

// -------------------- device globals --------------------
__device__ __align__(16) uint2 g_Wf[7][4096];   // W fragments (b0,b1)
__device__ __align__(16) uint4 g_Lf[6][2048];   // L fragments (a0..a3)
__device__ float g_h[4096 * 224];
__device__ float g_bpart[512];
__device__ float g_stats[2];
__device__ float g_cpart[32 * 64 * 224];
__device__ float g_gw[64];

// -------------------- helpers --------------------
__device__ __forceinline__ float hswf(float v) {
    return v * fminf(fmaxf(v + 3.0f, 0.0f), 6.0f) * (1.0f / 6.0f);
}

__device__ __forceinline__ int wslotA(int k) {
    int q = (k >> 1) & 7;
    int pos = ((q & 3) << 1) | (q >> 2);
    return ((k >> 4) << 3) + pos;
}

__device__ __forceinline__ void mma16816(float* d, uint32_t a0, uint32_t a1,
                                         uint32_t a2, uint32_t a3,
                                         uint32_t b0, uint32_t b1) {
    asm volatile(
        "mma.sync.aligned.m16n8k16.row.col.f32.f16.f16.f32 "
        "{%0,%1,%2,%3}, {%4,%5,%6,%7}, {%8,%9}, {%0,%1,%2,%3};"
        : "+f"(d[0]), "+f"(d[1]), "+f"(d[2]), "+f"(d[3])
        : "r"(a0), "r"(a1), "r"(a2), "r"(a3), "r"(b0), "r"(b1));
}

// W fragment index for 64-col group layout (nt 0..7 maps onto two old
// 32-col groups)
__device__ __forceinline__ int wfidx(int wg, int nt, int ks, int lane) {
    int wgOld = wg * 2 + (nt >> 2);
    int ntOld = nt & 3;
    return (((wgOld * 8 + ks) * 4) + ntOld) * 32 + lane;
}

// shfl-paired transposed store (single fp16)
__device__ __forceinline__ void storeTs(uint32_t* img, int f, int t, float v,
                                        int g) {
    float vp = __shfl_xor_sync(0xffffffffu, v, 4);
    if (!(g & 1)) {
        __half2 h2;
        h2.x = __float2half(v);
        h2.y = __float2half(vp);
        img[f * PWA + wslotA(t)] = *(uint32_t*)&h2;
    }
}

// ============================================================================
// kW: build fragment-major operand images (unchanged layouts from R8)
// ============================================================================
__global__ void kW(const float* __restrict__ cw0, const float* __restrict__ cw1,
                   const float* __restrict__ cw2,
                   const float* __restrict__ L10, const float* __restrict__ L20,
                   const float* __restrict__ L11, const float* __restrict__ L21,
                   const float* __restrict__ L12, const float* __restrict__ L22) {
    int b = blockIdx.x;
    if (b < 7) {
        int s, kk;
        if (b == 0)      { s = 0; kk = 0; }
        else if (b < 3)  { s = 1; kk = b - 1; }
        else             { s = 2; kk = b - 3; }
        const float* cw = (s == 0) ? cw0 : (s == 1) ? cw1 : cw2;
        int k = 1 << s;
        uint2* dst = g_Wf[b];
        for (int idx = threadIdx.x; idx < 4096; idx += blockDim.x) {
            int lane = idx & 31;
            int nt = (idx >> 5) & 3;
            int ks = (idx >> 7) & 7;
            int wg = idx >> 10;
            int g = lane >> 2, c = lane & 3;
            int row = wg * 32 + nt * 8 + g;
            int k0 = ks * 16 + 2 * c;
            __half2 b0, b1;
            b0.x = __float2half(cw[(row * 128 + k0) * k + kk]);
            b0.y = __float2half(cw[(row * 128 + k0 + 1) * k + kk]);
            b1.x = __float2half(cw[(row * 128 + k0 + 8) * k + kk]);
            b1.y = __float2half(cw[(row * 128 + k0 + 9) * k + kk]);
            uint2 o;
            o.x = *(uint32_t*)&b0;
            o.y = *(uint32_t*)&b1;
            dst[idx] = o;
        }
    } else {
        int j = b - 7;
        int s = j >> 1, m = j & 1;
        const float* L = (s == 0) ? (m ? L20 : L10)
                       : (s == 1) ? (m ? L21 : L11)
                                  : (m ? L22 : L12);
        int tk = 128 >> s;
        uint4* dst = g_Lf[j];
        for (int idx = threadIdx.x; idx < 2048; idx += blockDim.x) {
            int lane = idx & 31;
            int ks = (idx >> 5) & 7;
            int mt = idx >> 8;
            int g = lane >> 2, c = lane & 3;
            int r0 = mt * 16 + g, r1 = r0 + 8;
            int k0 = ks * 16 + 2 * c;
            float v[8];
#pragma unroll
            for (int e = 0; e < 8; e++) {
                int t = (e & 1) ? r1 : r0;
                int sc = k0 + ((e >> 2) << 3) + ((e >> 1) & 1);
                float vv = 0.0f;
                if ((t / tk) == (sc / tk)) {
                    int tp = t % tk, sp = sc % tk;
                    if (sp <= tp) vv = L[tp * tk + sp];
                }
                v[e] = vv;
            }
            __half2 a0, a1, a2, a3;
            a0.x = __float2half(v[0]); a0.y = __float2half(v[2]);
            a1.x = __float2half(v[1]); a1.y = __float2half(v[3]);
            a2.x = __float2half(v[4]); a2.y = __float2half(v[6]);
            a3.x = __float2half(v[5]); a3.y = __float2half(v[7]);
            uint4 o;
            o.x = *(uint32_t*)&a0;
            o.y = *(uint32_t*)&a1;
            o.z = *(uint32_t*)&a2;
            o.w = *(uint32_t*)&a3;
            dst[idx] = o;
        }
    }
}

// ============================================================================
// run_scale: TK = per-stock time length, MT = total m-tiles (8 or 4)
// ============================================================================
template <int TK, int MT>
__device__ __noinline__ void run_scale(
    const float* __restrict__ x, int n0run, int q0,
    const float* __restrict__ lg, const float* __restrict__ lb,
    const uint4* __restrict__ L1f, const uint4* __restrict__ L2f,
    int hoff, const float* __restrict__ cb, float fcb, bool first) {

    constexpr int K = 128 / TK;
    constexpr int NTILE = (MT == 8) ? 2 : 1;
    extern __shared__ uint32_t smw[];
    uint32_t* X  = smw + X_OFF;
    uint32_t* HT = smw + HT_OFF;
    float* scr   = (float*)(smw + SCR_BASE);
    float* s_fcw = scr + 32;
    float* s_cb  = scr + 160;
    float* scrF  = scr + 288;

    const int tid = threadIdx.x;
    const int w = tid >> 5, lane = tid & 31;
    const int w3 = w & 3;
    const int wg = w >> 2;                 // 0..1 (64-col group)
    const int g = lane >> 2, c = lane & 3;
    const int c0 = wg * 64;

    int mta, mtb = 0;
    int myg;
    if (MT == 4) {                         // TK==32, 2 stocks, M=64
        mta = w3;
        myg = w3 >> 1;
    } else if (TK == 128) {
        mta = w3; mtb = 7 - w3;
        myg = 0;
    } else {                               // TK==64, 2 stocks
        mta = ((w3 >> 1) << 2) + (w3 & 1);
        mtb = ((w3 >> 1) << 2) + 3 - (w3 & 1);
        myg = w3 >> 1;
    }
    const int ks0 = (myg * TK) >> 4;

    if (first && tid < 128) s_cb[tid] = cb[tid];

    float accA[8][4], accB[NTILE == 2 ? 8 : 1][4], fcT[2 * NTILE];
#pragma unroll
    for (int i = 0; i < 2 * NTILE; i++) fcT[i] = 0.0f;
#pragma unroll
    for (int nt = 0; nt < 8; nt++)
#pragma unroll
        for (int e = 0; e < 4; e++) accA[nt][e] = 0.0f;
    if (NTILE == 2) {
#pragma unroll
        for (int nt = 0; nt < 8; nt++)
#pragma unroll
            for (int e = 0; e < 4; e++) accB[nt][e] = 0.0f;
    }

    // ---------------- conv over K chunks ----------------
    for (int kk = 0; kk < K; kk++) {
        // build X (MT*16 rows x 128 cols fp16)
#pragma unroll 2
        for (int it = 0; it < MT * 2; it++) {
            int r = it * 8 + w;
            int f4 = lane;
            const float4 v = ((const float4*)(x +
                ((size_t)(n0run + r / TK) * 128 + (r & (TK - 1)) * K + kk) * 128))[f4];
            __half2 h0, h1;
            h0.x = __float2half(v.x); h0.y = __float2half(v.y);
            h1.x = __float2half(v.z); h1.y = __float2half(v.w);
            int k2 = f4 << 2;
            X[r * PWA + wslotA(k2)]     = *(uint32_t*)&h0;
            X[r * PWA + wslotA(k2 + 2)] = *(uint32_t*)&h1;
        }
        __syncthreads();
        // conv GEMM
        const uint2* Wf = g_Wf[q0 + kk];
#pragma unroll 2
        for (int ks = 0; ks < 8; ks++) {
            int off = ks * 8 + c * 2;
            uint2 vb[8];
#pragma unroll
            for (int nt = 0; nt < 8; nt++) vb[nt] = Wf[wfidx(wg, nt, ks, lane)];
            uint2 ta0 = *(const uint2*)(X + (mta * 16 + g) * PWA + off);
            uint2 ta1 = *(const uint2*)(X + (mta * 16 + g + 8) * PWA + off);
#pragma unroll
            for (int nt = 0; nt < 8; nt++)
                mma16816(accA[nt], ta0.x, ta1.x, ta0.y, ta1.y, vb[nt].x, vb[nt].y);
            if (NTILE == 2) {
                uint2 tb0 = *(const uint2*)(X + (mtb * 16 + g) * PWA + off);
                uint2 tb1 = *(const uint2*)(X + (mtb * 16 + g + 8) * PWA + off);
#pragma unroll
                for (int nt = 0; nt < 8; nt++)
                    mma16816(accB[nt], tb0.x, tb1.x, tb0.y, tb1.y, vb[nt].x, vb[nt].y);
            }
        }
        __syncthreads();
    }

    // ---------------- LN stats ----------------
    float s = 0.0f, s2 = 0.0f;
#pragma unroll
    for (int ti = 0; ti < NTILE; ti++)
#pragma unroll
        for (int nt = 0; nt < 8; nt++)
#pragma unroll
            for (int e = 0; e < 4; e++) {
                int f = c0 + nt * 8 + (c << 1) + (e & 1);
                float v = (ti ? accB[nt][e] : accA[nt][e]) + s_cb[f];
                s += v; s2 += v * v;
            }
#pragma unroll
    for (int o = 16; o; o >>= 1) {
        s  += __shfl_down_sync(0xffffffffu, s, o);
        s2 += __shfl_down_sync(0xffffffffu, s2, o);
    }
    if (lane == 0) { scr[w] = s; scr[8 + w] = s2; }
    __syncthreads();

    float gs = 0.0f, gs2 = 0.0f;
#pragma unroll
    for (int p = 0; p < 8; p++) {
        int p3 = p & 3;
        int pg = (TK == 128) ? 0 : (p3 >> 1);
        if (pg == myg) { gs += scr[p]; gs2 += scr[8 + p]; }
    }
    const float inv = 1.0f / (float)(TK * 128);
    float mu = gs * inv;
    float var = gs2 * inv - mu * mu;
    float rinv = rsqrtf(var + 1e-5f);

    // ---------------- hT -> HT ; fc conv-part ----------------
#pragma unroll
    for (int ti = 0; ti < NTILE; ti++) {
        int mt = ti ? mtb : mta;
#pragma unroll
        for (int nt = 0; nt < 8; nt++)
#pragma unroll
            for (int eh = 0; eh < 2; eh++) {
                int t = mt * 16 + g + 8 * eh;
                int tl = t & (TK - 1);
                int fb = c0 + nt * 8 + (c << 1);
                float2 lgv = *(const float2*)(lg + tl * 128 + fb);
                float2 lbv = *(const float2*)(lb + tl * 128 + fb);
#pragma unroll
                for (int eo = 0; eo < 2; eo++) {
                    float v = (ti ? accB[nt][eh * 2 + eo] : accA[nt][eh * 2 + eo])
                              + s_cb[fb + eo];
                    fcT[ti * 2 + eh] += v * s_fcw[fb + eo];
                    float hh = (v - mu) * rinv * (eo ? lgv.y : lgv.x)
                               + (eo ? lbv.y : lbv.x);
                    storeTs(HT, fb + eo, t, hh, g);
                }
            }
    }
    __syncthreads();

    // ---------------- GEMM1: u = L1m @ h ----------------
#pragma unroll
    for (int nt = 0; nt < 8; nt++)
#pragma unroll
        for (int e = 0; e < 4; e++) accA[nt][e] = 0.0f;
    if (NTILE == 2) {
#pragma unroll
        for (int nt = 0; nt < 8; nt++)
#pragma unroll
            for (int e = 0; e < 4; e++) accB[nt][e] = 0.0f;
    }
    {
        int kEnd = (NTILE == 2) ? mtb : mta;
        for (int ks = ks0; ks <= kEnd; ks++) {
            int off = ks * 8 + c * 2;
            uint2 vb[8];
#pragma unroll
            for (int nt = 0; nt < 8; nt++)
                vb[nt] = *(const uint2*)(HT + (c0 + nt * 8 + g) * PWA + off);
            if (NTILE == 2) {
                uint4 bv = L1f[(mtb * 8 + ks) * 32 + lane];
#pragma unroll
                for (int nt = 0; nt < 8; nt++)
                    mma16816(accB[nt], bv.x, bv.y, bv.z, bv.w, vb[nt].x, vb[nt].y);
            }
            if (ks <= mta) {
                uint4 av = L1f[(mta * 8 + ks) * 32 + lane];
#pragma unroll
                for (int nt = 0; nt < 8; nt++)
                    mma16816(accA[nt], av.x, av.y, av.z, av.w, vb[nt].x, vb[nt].y);
            }
        }
    }
    __syncthreads();

    // ---------------- uT = hsw(u) -> HT ----------------
#pragma unroll
    for (int ti = 0; ti < NTILE; ti++) {
        int mt = ti ? mtb : mta;
#pragma unroll
        for (int nt = 0; nt < 8; nt++)
#pragma unroll
            for (int e = 0; e < 4; e++) {
                int t = mt * 16 + g + ((e >> 1) << 3);
                int f = c0 + nt * 8 + (c << 1) + (e & 1);
                storeTs(HT, f, t, hswf(ti ? accB[nt][e] : accA[nt][e]), g);
            }
    }
    __syncthreads();

    // ---------------- GEMM2: v = L2m @ u ; fc v-part ----------------
#pragma unroll
    for (int nt = 0; nt < 8; nt++)
#pragma unroll
        for (int e = 0; e < 4; e++) accA[nt][e] = 0.0f;
    if (NTILE == 2) {
#pragma unroll
        for (int nt = 0; nt < 8; nt++)
#pragma unroll
            for (int e = 0; e < 4; e++) accB[nt][e] = 0.0f;
    }
    {
        int kEnd = (NTILE == 2) ? mtb : mta;
        for (int ks = ks0; ks <= kEnd; ks++) {
            int off = ks * 8 + c * 2;
            uint2 vb[8];
#pragma unroll
            for (int nt = 0; nt < 8; nt++)
                vb[nt] = *(const uint2*)(HT + (c0 + nt * 8 + g) * PWA + off);
            if (NTILE == 2) {
                uint4 bv = L2f[(mtb * 8 + ks) * 32 + lane];
#pragma unroll
                for (int nt = 0; nt < 8; nt++)
                    mma16816(accB[nt], bv.x, bv.y, bv.z, bv.w, vb[nt].x, vb[nt].y);
            }
            if (ks <= mta) {
                uint4 av = L2f[(mta * 8 + ks) * 32 + lane];
#pragma unroll
                for (int nt = 0; nt < 8; nt++)
                    mma16816(accA[nt], av.x, av.y, av.z, av.w, vb[nt].x, vb[nt].y);
            }
        }
    }
#pragma unroll
    for (int ti = 0; ti < NTILE; ti++)
#pragma unroll
        for (int nt = 0; nt < 8; nt++)
#pragma unroll
            for (int e = 0; e < 4; e++) {
                int f = c0 + nt * 8 + (c << 1) + (e & 1);
                fcT[ti * 2 + (e >> 1)] +=
                    (ti ? accB[nt][e] : accA[nt][e]) * s_fcw[f];
            }

    // ---------------- fc reduce -> g_h ----------------
#pragma unroll
    for (int i = 0; i < 2 * NTILE; i++) {
        fcT[i] += __shfl_xor_sync(0xffffffffu, fcT[i], 1);
        fcT[i] += __shfl_xor_sync(0xffffffffu, fcT[i], 2);
    }
    if (c == 0) {
#pragma unroll
        for (int i = 0; i < 2 * NTILE; i++) {
            int t = ((i >> 1) ? mtb : mta) * 16 + g + 8 * (i & 1);
            scrF[wg * 128 + t] = fcT[i];
        }
    }
    __syncthreads();
    if (tid < MT * 16) {
        int t = tid;
        float d = scrF[t] + scrF[128 + t];
        g_h[(n0run + t / TK) * 224 + hoff + (t & (TK - 1))] = d + fcb;
    }
    __syncthreads();
}

__global__ void __launch_bounds__(NTH, 2) kA9(
    const float* __restrict__ x,
    const float* __restrict__ cb0, const float* __restrict__ lg0,
    const float* __restrict__ lb0,
    const float* __restrict__ cb1, const float* __restrict__ lg1,
    const float* __restrict__ lb1,
    const float* __restrict__ cb2, const float* __restrict__ lg2,
    const float* __restrict__ lb2,
    const float* __restrict__ fcw, const float* __restrict__ fcbp) {
    extern __shared__ uint32_t smw[];
    float* scr = (float*)(smw + SCR_BASE);
    if (threadIdx.x < 128) scr[32 + threadIdx.x] = fcw[threadIdx.x];
    float fcb = fcbp[0];
    int n0 = blockIdx.x * 2;

    run_scale<128, 8>(x, n0 + 0, 0, lg0, lb0, g_Lf[0], g_Lf[1], 0, cb0, fcb, true);
    run_scale<128, 8>(x, n0 + 1, 0, lg0, lb0, g_Lf[0], g_Lf[1], 0, cb0, fcb, false);

    run_scale<64, 8>(x, n0 + 0, 1, lg1, lb1, g_Lf[2], g_Lf[3], 128, cb1, fcb, true);

    run_scale<32, 4>(x, n0 + 0, 3, lg2, lb2, g_Lf[4], g_Lf[5], 192, cb2, fcb, true);
}

// ============================================================================
// phase 2 (unchanged)
// ============================================================================
__device__ __forceinline__ void bred2(float& s, float& s2, float* scr) {
#pragma unroll
    for (int o = 16; o > 0; o >>= 1) {
        s  += __shfl_down_sync(0xffffffffu, s, o);
        s2 += __shfl_down_sync(0xffffffffu, s2, o);
    }
    int w = threadIdx.x >> 5, l = threadIdx.x & 31;
    if (l == 0) { scr[w] = s; scr[32 + w] = s2; }
    __syncthreads();
    if (threadIdx.x == 0) {
        float a = 0.f, b = 0.f;
        int nw = (blockDim.x + 31) >> 5;
        for (int i = 0; i < nw; i++) { a += scr[i]; b += scr[32 + i]; }
        scr[0] = a; scr[32] = b;
    }
    __syncthreads();
    s = scr[0]; s2 = scr[32];
}

__global__ void kB1() {
    float s = 0.f, s2 = 0.f;
    int base = blockIdx.x * 16 * 224;
    for (int idx = threadIdx.x; idx < 16 * 224; idx += 256) {
        float v = g_h[base + idx];
        s += v; s2 += v * v;
    }
    __shared__ float scr[64];
    bred2(s, s2, scr);
    if (threadIdx.x == 0) { g_bpart[blockIdx.x] = s; g_bpart[256 + blockIdx.x] = s2; }
}

__global__ void kB2() {
    float s = g_bpart[threadIdx.x];
    float s2 = g_bpart[256 + threadIdx.x];
    __shared__ float scr[64];
    bred2(s, s2, scr);
    if (threadIdx.x == 0) {
        const float inv = 1.0f / (4096.0f * 224.0f);
        float mu = s * inv;
        float var = s2 * inv - mu * mu;
        g_stats[0] = mu;
        g_stats[1] = rsqrtf(var + 1e-5f);
    }
}

__global__ void kC1(const float* __restrict__ M1,
                    const float* __restrict__ slg,
                    const float* __restrict__ slb) {
    int j = threadIdx.x;
    int b = blockIdx.x;
    float mu = g_stats[0], rinv = g_stats[1];
    float acc[64];
#pragma unroll
    for (int m = 0; m < 64; m++) acc[m] = 0.f;
    int n0 = b * 128;
    for (int n = n0; n < n0 + 128; n++) {
        int off = n * 224 + j;
        float hn = (g_h[off] - mu) * rinv * slg[off] + slb[off];
#pragma unroll
        for (int m = 0; m < 64; m++) acc[m] += M1[m * 4096 + n] * hn;
    }
#pragma unroll
    for (int m = 0; m < 64; m++) g_cpart[(b * 64 + m) * 224 + j] = acc[m];
}

__global__ void kC2(const float* __restrict__ smw_) {
    int m = blockIdx.x, j = threadIdx.x;
    float g = 0.f;
    for (int b = 0; b < 32; b++) g += g_cpart[(b * 64 + m) * 224 + j];
    float v = hswf(g) * smw_[224 + j];
    float dummy = 0.f;
    __shared__ float scr[64];
    bred2(v, dummy, scr);
    if (threadIdx.x == 0) g_gw[m] = v;
}

__global__ void kD(const float* __restrict__ M2,
                   const float* __restrict__ smw_,
                   const float* __restrict__ smb,
                   float* __restrict__ out) {
    int warp = threadIdx.x >> 5, lane = threadIdx.x & 31;
    int n = blockIdx.x * 8 + warp;
    float acc = 0.f;
    for (int j = lane; j < 224; j += 32)
        acc += g_h[n * 224 + j] * (smw_[j] + smw_[224 + j]);
    for (int m = lane; m < 64; m += 32)
        acc += M2[n * 64 + m] * g_gw[m];
#pragma unroll
    for (int o = 16; o > 0; o >>= 1)
        acc += __shfl_down_sync(0xffffffffu, acc, o);
    if (lane == 0) out[n] = acc + smb[0];
}

// ============================================================================
extern "C" void kernel_launch(void* const* d_in, const int* in_sizes, int n_in,
                              void* d_out, int out_size) {
    const float* x   = (const float*)d_in[0];
    const float* cw0 = (const float*)d_in[1];
    const float* cb0 = (const float*)d_in[2];
    const float* lg0 = (const float*)d_in[3];
    const float* lb0 = (const float*)d_in[4];
    const float* L10 = (const float*)d_in[5];
    const float* L20 = (const float*)d_in[6];
    const float* cw1 = (const float*)d_in[7];
    const float* cb1 = (const float*)d_in[8];
    const float* lg1 = (const float*)d_in[9];
    const float* lb1 = (const float*)d_in[10];
    const float* L11 = (const float*)d_in[11];
    const float* L21 = (const float*)d_in[12];
    const float* cw2 = (const float*)d_in[13];
    const float* cb2 = (const float*)d_in[14];
    const float* lg2 = (const float*)d_in[15];
    const float* lb2 = (const float*)d_in[16];
    const float* L12 = (const float*)d_in[17];
    const float* L22 = (const float*)d_in[18];
    const float* fcw = (const float*)d_in[19];
    const float* fcb = (const float*)d_in[20];
    const float* slg = (const float*)d_in[21];
    const float* slb = (const float*)d_in[22];
    const float* M1  = (const float*)d_in[23];
    const float* M2  = (const float*)d_in[24];
    const float* smw = (const float*)d_in[25];
    const float* smb = (const float*)d_in[26];
    float* out = (float*)d_out;

    cudaFuncSetAttribute(kA9, cudaFuncAttributeMaxDynamicSharedMemorySize, SMEM_SZ);

    kW<<<13, 256>>>(cw0, cw1, cw2, L10, L20, L11, L21, L12, L22);
    kA9<<<2048, NTH, SMEM_SZ>>>(x, cb0, lg0, lb0, cb1, lg1, lb1,
                                cb2, lg2, lb2, fcw, fcb);
    kB1<<<256, 256>>>();
    kB2<<<1, 256>>>();
    kC1<<<32, 224>>>(M1, slg, slb);
    kC2<<<64, 224>>>(smw);
    kD<<<512, 256>>>(M2, smw, smb, out);
}

// round 10
// speedup vs baseline: 6.3023x; 1.0710x over previous
#include <cuda_runtime.h>
#include <cuda_fp16.h>
#include <cstdint>

// ============================================================================
// StockMixer GB300 — R10: single X image per block (built once, row-permuted
// access per scale/chunk, barrier-free conv), XOR bank swizzle, kB1 fused
// into kA tail. Single-term fp16 mma.sync, fragment-major gmem W/L operands.
// ============================================================================

#define PWA 72
#define X_OFF  0                        // 256 rows * 72 words = 18432
#define HT_OFF 18432                    // 128 rows * 72 words = 9216
#define SCR_BASE 27648
#define SMEM_SZ ((27648 + 832) * 4)     // 113920 B  (x2 blocks = 227840 <= 228K)

#define NTH 256

// -------------------- device globals --------------------
__device__ __align__(16) uint2 g_Wf[7][4096];   // W fragments (b0,b1)
__device__ __align__(16) uint4 g_Lf[6][2048];   // L fragments (a0..a3)
__device__ float g_h[4096 * 224];
__device__ float g_bpart[4096];                 // [0:2048) sum, [2048:4096) sumsq
__device__ float g_stats[2];
__device__ float g_cpart[32 * 64 * 224];
__device__ float g_gw[64];

// -------------------- helpers --------------------
__device__ __forceinline__ float hswf(float v) {
    return v * fminf(fmaxf(v + 3.0f, 0.0f), 6.0f) * (1.0f / 6.0f);
}

__device__ __forceinline__ int wslotA(int k) {
    int q = (k >> 1) & 7;
    int pos = ((q & 3) << 1) | (q >> 2);
    return ((k >> 4) << 3) + pos;
}
// row-keyed bank swizzle (bits 3..4 of word offset)
__device__ __forceinline__ int swz(int r) { return ((r >> 2) & 3) << 3; }

__device__ __forceinline__ void mma16816(float* d, uint32_t a0, uint32_t a1,
                                         uint32_t a2, uint32_t a3,
                                         uint32_t b0, uint32_t b1) {
    asm volatile(
        "mma.sync.aligned.m16n8k16.row.col.f32.f16.f16.f32 "
        "{%0,%1,%2,%3}, {%4,%5,%6,%7}, {%8,%9}, {%0,%1,%2,%3};"
        : "+f"(d[0]), "+f"(d[1]), "+f"(d[2]), "+f"(d[3])
        : "r"(a0), "r"(a1), "r"(a2), "r"(a3), "r"(b0), "r"(b1));
}

__device__ __forceinline__ int wfidx(int wg, int nt, int ks, int lane) {
    int wgOld = wg * 2 + (nt >> 2);
    int ntOld = nt & 3;
    return (((wgOld * 8 + ks) * 4) + ntOld) * 32 + lane;
}

// transposed fp16 store with swizzle (even-g lanes write the pair word)
__device__ __forceinline__ void storeTs(uint32_t* img, int f, int t, float v,
                                        int g) {
    float vp = __shfl_xor_sync(0xffffffffu, v, 4);
    if (!(g & 1)) {
        __half2 h2;
        h2.x = __float2half(v);
        h2.y = __float2half(vp);
        img[f * PWA + (wslotA(t) ^ swz(f))] = *(uint32_t*)&h2;
    }
}

// ============================================================================
// kW: build fragment-major operand images (same layouts as R9)
// ============================================================================
__global__ void kW(const float* __restrict__ cw0, const float* __restrict__ cw1,
                   const float* __restrict__ cw2,
                   const float* __restrict__ L10, const float* __restrict__ L20,
                   const float* __restrict__ L11, const float* __restrict__ L21,
                   const float* __restrict__ L12, const float* __restrict__ L22) {
    int b = blockIdx.x;
    if (b < 7) {
        int s, kk;
        if (b == 0)      { s = 0; kk = 0; }
        else if (b < 3)  { s = 1; kk = b - 1; }
        else             { s = 2; kk = b - 3; }
        const float* cw = (s == 0) ? cw0 : (s == 1) ? cw1 : cw2;
        int k = 1 << s;
        uint2* dst = g_Wf[b];
        for (int idx = threadIdx.x; idx < 4096; idx += blockDim.x) {
            int lane = idx & 31;
            int nt = (idx >> 5) & 3;
            int ks = (idx >> 7) & 7;
            int wg = idx >> 10;
            int g = lane >> 2, c = lane & 3;
            int row = wg * 32 + nt * 8 + g;
            int k0 = ks * 16 + 2 * c;
            __half2 b0, b1;
            b0.x = __float2half(cw[(row * 128 + k0) * k + kk]);
            b0.y = __float2half(cw[(row * 128 + k0 + 1) * k + kk]);
            b1.x = __float2half(cw[(row * 128 + k0 + 8) * k + kk]);
            b1.y = __float2half(cw[(row * 128 + k0 + 9) * k + kk]);
            uint2 o;
            o.x = *(uint32_t*)&b0;
            o.y = *(uint32_t*)&b1;
            dst[idx] = o;
        }
    } else {
        int j = b - 7;
        int s = j >> 1, m = j & 1;
        const float* L = (s == 0) ? (m ? L20 : L10)
                       : (s == 1) ? (m ? L21 : L11)
                                  : (m ? L22 : L12);
        int tk = 128 >> s;
        uint4* dst = g_Lf[j];
        for (int idx = threadIdx.x; idx < 2048; idx += blockDim.x) {
            int lane = idx & 31;
            int ks = (idx >> 5) & 7;
            int mt = idx >> 8;
            int g = lane >> 2, c = lane & 3;
            int r0 = mt * 16 + g, r1 = r0 + 8;
            int k0 = ks * 16 + 2 * c;
            float v[8];
#pragma unroll
            for (int e = 0; e < 8; e++) {
                int t = (e & 1) ? r1 : r0;
                int sc = k0 + ((e >> 2) << 3) + ((e >> 1) & 1);
                float vv = 0.0f;
                if ((t / tk) == (sc / tk)) {
                    int tp = t % tk, sp = sc % tk;
                    if (sp <= tp) vv = L[tp * tk + sp];
                }
                v[e] = vv;
            }
            __half2 a0, a1, a2, a3;
            a0.x = __float2half(v[0]); a0.y = __float2half(v[2]);
            a1.x = __float2half(v[1]); a1.y = __float2half(v[3]);
            a2.x = __float2half(v[4]); a2.y = __float2half(v[6]);
            a3.x = __float2half(v[5]); a3.y = __float2half(v[7]);
            uint4 o;
            o.x = *(uint32_t*)&a0;
            o.y = *(uint32_t*)&a1;
            o.z = *(uint32_t*)&a2;
            o.w = *(uint32_t*)&a3;
            dst[idx] = o;
        }
    }
}

// ============================================================================
// run_scale: conv reads the shared X image with per-scale row permutation.
// TK = per-stock time length, MT = total m-tiles (8 or 4), sbase = stock
// offset for TK==128 runs.
// ============================================================================
template <int TK, int MT>
__device__ __noinline__ void run_scale(
    int n0, int sbase, int q0,
    const float* __restrict__ lg, const float* __restrict__ lb,
    const uint4* __restrict__ L1f, const uint4* __restrict__ L2f,
    int hoff, const float* __restrict__ cb, float fcb, bool first) {

    constexpr int K = 128 / TK;
    constexpr int NTILE = (MT == 8) ? 2 : 1;
    extern __shared__ uint32_t smw[];
    uint32_t* X  = smw + X_OFF;
    uint32_t* HT = smw + HT_OFF;
    float* scr   = (float*)(smw + SCR_BASE);
    float* s_fcw = scr + 32;
    float* s_cb  = scr + 160;
    float* scrF  = scr + 288;

    const int tid = threadIdx.x;
    const int w = tid >> 5, lane = tid & 31;
    const int w3 = w & 3;
    const int wg = w >> 2;
    const int g = lane >> 2, c = lane & 3;
    const int c0 = wg * 64;

    int mta, mtb = 0;
    int myg;
    if (MT == 4) { mta = w3; myg = w3 >> 1; }
    else if (TK == 128) { mta = w3; mtb = 7 - w3; myg = 0; }
    else {
        mta = ((w3 >> 1) << 2) + (w3 & 1);
        mtb = ((w3 >> 1) << 2) + 3 - (w3 & 1);
        myg = w3 >> 1;
    }
    const int ks0 = (myg * TK) >> 4;

    if (first) {
        if (tid < 128) s_cb[tid] = cb[tid];
        __syncthreads();
    }

    // physical X row of logical row l for chunk kk
    auto rowmap = [&](int l, int kk) {
        return (TK == 128) ? (sbase * 128 + l)
                           : ((l / TK) * 128 + (l % TK) * K + kk);
    };

    float accA[8][4], accB[NTILE == 2 ? 8 : 1][4], fcT[2 * NTILE];
#pragma unroll
    for (int i = 0; i < 2 * NTILE; i++) fcT[i] = 0.0f;
#pragma unroll
    for (int nt = 0; nt < 8; nt++)
#pragma unroll
        for (int e = 0; e < 4; e++) accA[nt][e] = 0.0f;
    if (NTILE == 2) {
#pragma unroll
        for (int nt = 0; nt < 8; nt++)
#pragma unroll
            for (int e = 0; e < 4; e++) accB[nt][e] = 0.0f;
    }

    // ---------------- conv: barrier-free over K chunks ----------------
    for (int kk = 0; kk < K; kk++) {
        const uint2* Wf = g_Wf[q0 + kk];
#pragma unroll 2
        for (int ks = 0; ks < 8; ks++) {
            int off = ks * 8 + c * 2;
            uint2 vb[8];
#pragma unroll
            for (int nt = 0; nt < 8; nt++) vb[nt] = Wf[wfidx(wg, nt, ks, lane)];
            int ra0 = rowmap(mta * 16 + g, kk);
            int ra1 = rowmap(mta * 16 + g + 8, kk);
            uint2 ta0 = *(const uint2*)(X + ra0 * PWA + (off ^ swz(ra0)));
            uint2 ta1 = *(const uint2*)(X + ra1 * PWA + (off ^ swz(ra1)));
#pragma unroll
            for (int nt = 0; nt < 8; nt++)
                mma16816(accA[nt], ta0.x, ta1.x, ta0.y, ta1.y, vb[nt].x, vb[nt].y);
            if (NTILE == 2) {
                int rb0 = rowmap(mtb * 16 + g, kk);
                int rb1 = rowmap(mtb * 16 + g + 8, kk);
                uint2 tb0 = *(const uint2*)(X + rb0 * PWA + (off ^ swz(rb0)));
                uint2 tb1 = *(const uint2*)(X + rb1 * PWA + (off ^ swz(rb1)));
#pragma unroll
                for (int nt = 0; nt < 8; nt++)
                    mma16816(accB[nt], tb0.x, tb1.x, tb0.y, tb1.y, vb[nt].x, vb[nt].y);
            }
        }
    }

    // ---------------- LN stats ----------------
    float s = 0.0f, s2 = 0.0f;
#pragma unroll
    for (int ti = 0; ti < NTILE; ti++)
#pragma unroll
        for (int nt = 0; nt < 8; nt++)
#pragma unroll
            for (int e = 0; e < 4; e++) {
                int f = c0 + nt * 8 + (c << 1) + (e & 1);
                float v = (ti ? accB[nt][e] : accA[nt][e]) + s_cb[f];
                s += v; s2 += v * v;
            }
#pragma unroll
    for (int o = 16; o; o >>= 1) {
        s  += __shfl_down_sync(0xffffffffu, s, o);
        s2 += __shfl_down_sync(0xffffffffu, s2, o);
    }
    if (lane == 0) { scr[w] = s; scr[8 + w] = s2; }
    __syncthreads();

    float gs = 0.0f, gs2 = 0.0f;
#pragma unroll
    for (int p = 0; p < 8; p++) {
        int p3 = p & 3;
        int pg = (TK == 128) ? 0 : (p3 >> 1);
        if (pg == myg) { gs += scr[p]; gs2 += scr[8 + p]; }
    }
    const float inv = 1.0f / (float)(TK * 128);
    float mu = gs * inv;
    float var = gs2 * inv - mu * mu;
    float rinv = rsqrtf(var + 1e-5f);

    // ---------------- hT -> HT ; fc conv-part ----------------
#pragma unroll
    for (int ti = 0; ti < NTILE; ti++) {
        int mt = ti ? mtb : mta;
#pragma unroll
        for (int nt = 0; nt < 8; nt++)
#pragma unroll
            for (int eh = 0; eh < 2; eh++) {
                int t = mt * 16 + g + 8 * eh;
                int tl = t & (TK - 1);
                int fb = c0 + nt * 8 + (c << 1);
                float2 lgv = *(const float2*)(lg + tl * 128 + fb);
                float2 lbv = *(const float2*)(lb + tl * 128 + fb);
#pragma unroll
                for (int eo = 0; eo < 2; eo++) {
                    float v = (ti ? accB[nt][eh * 2 + eo] : accA[nt][eh * 2 + eo])
                              + s_cb[fb + eo];
                    fcT[ti * 2 + eh] += v * s_fcw[fb + eo];
                    float hh = (v - mu) * rinv * (eo ? lgv.y : lgv.x)
                               + (eo ? lbv.y : lbv.x);
                    storeTs(HT, fb + eo, t, hh, g);
                }
            }
    }
    __syncthreads();

    // ---------------- GEMM1: u = L1m @ h ----------------
#pragma unroll
    for (int nt = 0; nt < 8; nt++)
#pragma unroll
        for (int e = 0; e < 4; e++) accA[nt][e] = 0.0f;
    if (NTILE == 2) {
#pragma unroll
        for (int nt = 0; nt < 8; nt++)
#pragma unroll
            for (int e = 0; e < 4; e++) accB[nt][e] = 0.0f;
    }
    {
        int kEnd = (NTILE == 2) ? mtb : mta;
        for (int ks = ks0; ks <= kEnd; ks++) {
            int off = ks * 8 + c * 2;
            uint2 vb[8];
#pragma unroll
            for (int nt = 0; nt < 8; nt++) {
                int hr = c0 + nt * 8 + g;
                vb[nt] = *(const uint2*)(HT + hr * PWA + (off ^ swz(hr)));
            }
            if (NTILE == 2) {
                uint4 bv = L1f[(mtb * 8 + ks) * 32 + lane];
#pragma unroll
                for (int nt = 0; nt < 8; nt++)
                    mma16816(accB[nt], bv.x, bv.y, bv.z, bv.w, vb[nt].x, vb[nt].y);
            }
            if (ks <= mta) {
                uint4 av = L1f[(mta * 8 + ks) * 32 + lane];
#pragma unroll
                for (int nt = 0; nt < 8; nt++)
                    mma16816(accA[nt], av.x, av.y, av.z, av.w, vb[nt].x, vb[nt].y);
            }
        }
    }
    __syncthreads();

    // ---------------- uT = hsw(u) -> HT ----------------
#pragma unroll
    for (int ti = 0; ti < NTILE; ti++) {
        int mt = ti ? mtb : mta;
#pragma unroll
        for (int nt = 0; nt < 8; nt++)
#pragma unroll
            for (int e = 0; e < 4; e++) {
                int t = mt * 16 + g + ((e >> 1) << 3);
                int f = c0 + nt * 8 + (c << 1) + (e & 1);
                storeTs(HT, f, t, hswf(ti ? accB[nt][e] : accA[nt][e]), g);
            }
    }
    __syncthreads();

    // ---------------- GEMM2: v = L2m @ u ; fc v-part ----------------
#pragma unroll
    for (int nt = 0; nt < 8; nt++)
#pragma unroll
        for (int e = 0; e < 4; e++) accA[nt][e] = 0.0f;
    if (NTILE == 2) {
#pragma unroll
        for (int nt = 0; nt < 8; nt++)
#pragma unroll
            for (int e = 0; e < 4; e++) accB[nt][e] = 0.0f;
    }
    {
        int kEnd = (NTILE == 2) ? mtb : mta;
        for (int ks = ks0; ks <= kEnd; ks++) {
            int off = ks * 8 + c * 2;
            uint2 vb[8];
#pragma unroll
            for (int nt = 0; nt < 8; nt++) {
                int hr = c0 + nt * 8 + g;
                vb[nt] = *(const uint2*)(HT + hr * PWA + (off ^ swz(hr)));
            }
            if (NTILE == 2) {
                uint4 bv = L2f[(mtb * 8 + ks) * 32 + lane];
#pragma unroll
                for (int nt = 0; nt < 8; nt++)
                    mma16816(accB[nt], bv.x, bv.y, bv.z, bv.w, vb[nt].x, vb[nt].y);
            }
            if (ks <= mta) {
                uint4 av = L2f[(mta * 8 + ks) * 32 + lane];
#pragma unroll
                for (int nt = 0; nt < 8; nt++)
                    mma16816(accA[nt], av.x, av.y, av.z, av.w, vb[nt].x, vb[nt].y);
            }
        }
    }
#pragma unroll
    for (int ti = 0; ti < NTILE; ti++)
#pragma unroll
        for (int nt = 0; nt < 8; nt++)
#pragma unroll
            for (int e = 0; e < 4; e++) {
                int f = c0 + nt * 8 + (c << 1) + (e & 1);
                fcT[ti * 2 + (e >> 1)] +=
                    (ti ? accB[nt][e] : accA[nt][e]) * s_fcw[f];
            }

    // ---------------- fc reduce -> g_h ----------------
#pragma unroll
    for (int i = 0; i < 2 * NTILE; i++) {
        fcT[i] += __shfl_xor_sync(0xffffffffu, fcT[i], 1);
        fcT[i] += __shfl_xor_sync(0xffffffffu, fcT[i], 2);
    }
    if (c == 0) {
#pragma unroll
        for (int i = 0; i < 2 * NTILE; i++) {
            int t = ((i >> 1) ? mtb : mta) * 16 + g + 8 * (i & 1);
            scrF[wg * 128 + t] = fcT[i];
        }
    }
    __syncthreads();
    if (tid < MT * 16) {
        int t = tid;
        float d = scrF[t] + scrF[128 + t];
        g_h[(n0 + sbase + t / TK) * 224 + hoff + (t & (TK - 1))] = d + fcb;
    }
    __syncthreads();
}

__global__ void __launch_bounds__(NTH, 2) kA10(
    const float* __restrict__ x,
    const float* __restrict__ cb0, const float* __restrict__ lg0,
    const float* __restrict__ lb0,
    const float* __restrict__ cb1, const float* __restrict__ lg1,
    const float* __restrict__ lb1,
    const float* __restrict__ cb2, const float* __restrict__ lg2,
    const float* __restrict__ lb2,
    const float* __restrict__ fcw, const float* __restrict__ fcbp) {
    extern __shared__ uint32_t smw[];
    uint32_t* X = smw + X_OFF;
    float* scr = (float*)(smw + SCR_BASE);
    const int tid = threadIdx.x;
    if (tid < 128) scr[32 + tid] = fcw[tid];
    float fcb = fcbp[0];
    int n0 = blockIdx.x * 2;

    // ---- build X once: 256 rows (2 stocks, natural time order) ----
#pragma unroll 4
    for (int it = 0; it < 32; it++) {
        int idx = it * 256 + tid;
        int r = idx >> 5, f4 = idx & 31;
        const float4 v = ((const float4*)(x +
            ((size_t)(n0 + (r >> 7)) * 128 + (r & 127)) * 128))[f4];
        __half2 h0, h1;
        h0.x = __float2half(v.x); h0.y = __float2half(v.y);
        h1.x = __float2half(v.z); h1.y = __float2half(v.w);
        int k2 = f4 << 2;
        int sw = swz(r);
        X[r * PWA + (wslotA(k2) ^ sw)]     = *(uint32_t*)&h0;
        X[r * PWA + (wslotA(k2 + 2) ^ sw)] = *(uint32_t*)&h1;
    }
    __syncthreads();

    run_scale<128, 8>(n0, 0, 0, lg0, lb0, g_Lf[0], g_Lf[1], 0, cb0, fcb, true);
    run_scale<128, 8>(n0, 1, 0, lg0, lb0, g_Lf[0], g_Lf[1], 0, cb0, fcb, false);
    run_scale<64, 8>(n0, 0, 1, lg1, lb1, g_Lf[2], g_Lf[3], 128, cb1, fcb, true);
    run_scale<32, 4>(n0, 0, 3, lg2, lb2, g_Lf[4], g_Lf[5], 192, cb2, fcb, true);

    // ---- fused kB1: block-local LN partials over own 448 h values ----
    float s = 0.0f, s2 = 0.0f;
    for (int i = tid; i < 448; i += 256) {
        float v = g_h[n0 * 224 + i];
        s += v; s2 += v * v;
    }
#pragma unroll
    for (int o = 16; o; o >>= 1) {
        s  += __shfl_down_sync(0xffffffffu, s, o);
        s2 += __shfl_down_sync(0xffffffffu, s2, o);
    }
    float* scrR = scr + 288;
    int wI = tid >> 5, lI = tid & 31;
    if (lI == 0) { scrR[wI] = s; scrR[8 + wI] = s2; }
    __syncthreads();
    if (tid == 0) {
        float a = 0.0f, b = 0.0f;
#pragma unroll
        for (int i = 0; i < 8; i++) { a += scrR[i]; b += scrR[8 + i]; }
        g_bpart[blockIdx.x] = a;
        g_bpart[2048 + blockIdx.x] = b;
    }
}

// ============================================================================
// phase 2
// ============================================================================
__device__ __forceinline__ void bred2(float& s, float& s2, float* scr) {
#pragma unroll
    for (int o = 16; o > 0; o >>= 1) {
        s  += __shfl_down_sync(0xffffffffu, s, o);
        s2 += __shfl_down_sync(0xffffffffu, s2, o);
    }
    int w = threadIdx.x >> 5, l = threadIdx.x & 31;
    if (l == 0) { scr[w] = s; scr[32 + w] = s2; }
    __syncthreads();
    if (threadIdx.x == 0) {
        float a = 0.f, b = 0.f;
        int nw = (blockDim.x + 31) >> 5;
        for (int i = 0; i < nw; i++) { a += scr[i]; b += scr[32 + i]; }
        scr[0] = a; scr[32] = b;
    }
    __syncthreads();
    s = scr[0]; s2 = scr[32];
}

__global__ void kB2() {
    float s = 0.0f, s2 = 0.0f;
#pragma unroll
    for (int k = 0; k < 8; k++) {
        int i = threadIdx.x + 256 * k;
        s  += g_bpart[i];
        s2 += g_bpart[2048 + i];
    }
    __shared__ float scr[64];
    bred2(s, s2, scr);
    if (threadIdx.x == 0) {
        const float inv = 1.0f / (4096.0f * 224.0f);
        float mu = s * inv;
        float var = s2 * inv - mu * mu;
        g_stats[0] = mu;
        g_stats[1] = rsqrtf(var + 1e-5f);
    }
}

__global__ void kC1(const float* __restrict__ M1,
                    const float* __restrict__ slg,
                    const float* __restrict__ slb) {
    int j = threadIdx.x;
    int b = blockIdx.x;
    float mu = g_stats[0], rinv = g_stats[1];
    float acc[64];
#pragma unroll
    for (int m = 0; m < 64; m++) acc[m] = 0.f;
    int n0 = b * 128;
    for (int n = n0; n < n0 + 128; n++) {
        int off = n * 224 + j;
        float hn = (g_h[off] - mu) * rinv * slg[off] + slb[off];
#pragma unroll
        for (int m = 0; m < 64; m++) acc[m] += M1[m * 4096 + n] * hn;
    }
#pragma unroll
    for (int m = 0; m < 64; m++) g_cpart[(b * 64 + m) * 224 + j] = acc[m];
}

__global__ void kC2(const float* __restrict__ smw_) {
    int m = blockIdx.x, j = threadIdx.x;
    float g = 0.f;
    for (int b = 0; b < 32; b++) g += g_cpart[(b * 64 + m) * 224 + j];
    float v = hswf(g) * smw_[224 + j];
    float dummy = 0.f;
    __shared__ float scr[64];
    bred2(v, dummy, scr);
    if (threadIdx.x == 0) g_gw[m] = v;
}

__global__ void kD(const float* __restrict__ M2,
                   const float* __restrict__ smw_,
                   const float* __restrict__ smb,
                   float* __restrict__ out) {
    int warp = threadIdx.x >> 5, lane = threadIdx.x & 31;
    int n = blockIdx.x * 8 + warp;
    float acc = 0.f;
    for (int j = lane; j < 224; j += 32)
        acc += g_h[n * 224 + j] * (smw_[j] + smw_[224 + j]);
    for (int m = lane; m < 64; m += 32)
        acc += M2[n * 64 + m] * g_gw[m];
#pragma unroll
    for (int o = 16; o > 0; o >>= 1)
        acc += __shfl_down_sync(0xffffffffu, acc, o);
    if (lane == 0) out[n] = acc + smb[0];
}

// ============================================================================
extern "C" void kernel_launch(void* const* d_in, const int* in_sizes, int n_in,
                              void* d_out, int out_size) {
    const float* x   = (const float*)d_in[0];
    const float* cw0 = (const float*)d_in[1];
    const float* cb0 = (const float*)d_in[2];
    const float* lg0 = (const float*)d_in[3];
    const float* lb0 = (const float*)d_in[4];
    const float* L10 = (const float*)d_in[5];
    const float* L20 = (const float*)d_in[6];
    const float* cw1 = (const float*)d_in[7];
    const float* cb1 = (const float*)d_in[8];
    const float* lg1 = (const float*)d_in[9];
    const float* lb1 = (const float*)d_in[10];
    const float* L11 = (const float*)d_in[11];
    const float* L21 = (const float*)d_in[12];
    const float* cw2 = (const float*)d_in[13];
    const float* cb2 = (const float*)d_in[14];
    const float* lg2 = (const float*)d_in[15];
    const float* lb2 = (const float*)d_in[16];
    const float* L12 = (const float*)d_in[17];
    const float* L22 = (const float*)d_in[18];
    const float* fcw = (const float*)d_in[19];
    const float* fcb = (const float*)d_in[20];
    const float* slg = (const float*)d_in[21];
    const float* slb = (const float*)d_in[22];
    const float* M1  = (const float*)d_in[23];
    const float* M2  = (const float*)d_in[24];
    const float* smw = (const float*)d_in[25];
    const float* smb = (const float*)d_in[26];
    float* out = (float*)d_out;

    cudaFuncSetAttribute(kA10, cudaFuncAttributeMaxDynamicSharedMemorySize,
                         SMEM_SZ);

    kW<<<13, 256>>>(cw0, cw1, cw2, L10, L20, L11, L21, L12, L22);
    kA10<<<2048, NTH, SMEM_SZ>>>(x, cb0, lg0, lb0, cb1, lg1, lb1,
                                 cb2, lg2, lb2, fcw, fcb);
    kB2<<<1, 256>>>();
    kC1<<<32, 224>>>(M1, slg, slb);
    kC2<<<64, 224>>>(smw);
    kD<<<512, 256>>>(M2, smw, smb, out);
}

// round 11
// speedup vs baseline: 8.0266x; 1.2736x over previous
#include <cuda_runtime.h>
#include <cuda_fp16.h>
#include <cstdint>

// ============================================================================
// StockMixer GB300 — R11: R10 kernel + parallelized kC1 (grid 32 -> 256,
// smem-staged M1 tile) and widened kC2 reduction.
// ============================================================================

#define PWA 72
#define X_OFF  0                        // 256 rows * 72 words = 18432
#define HT_OFF 18432                    // 128 rows * 72 words = 9216
#define SCR_BASE 27648
#define SMEM_SZ ((27648 + 832) * 4)     // 113920 B  (x2 blocks <= 228K)

#define NTH 256

// -------------------- device globals --------------------
__device__ __align__(16) uint2 g_Wf[7][4096];   // W fragments (b0,b1)
__device__ __align__(16) uint4 g_Lf[6][2048];   // L fragments (a0..a3)
__device__ float g_h[4096 * 224];
__device__ float g_bpart[4096];                 // [0:2048) sum, [2048:4096) sumsq
__device__ float g_stats[2];
__device__ float g_cpart[256 * 64 * 224];       // 14.7 MB partials
__device__ float g_gw[64];

// -------------------- helpers --------------------
__device__ __forceinline__ float hswf(float v) {
    return v * fminf(fmaxf(v + 3.0f, 0.0f), 6.0f) * (1.0f / 6.0f);
}

__device__ __forceinline__ int wslotA(int k) {
    int q = (k >> 1) & 7;
    int pos = ((q & 3) << 1) | (q >> 2);
    return ((k >> 4) << 3) + pos;
}
__device__ __forceinline__ int swz(int r) { return ((r >> 2) & 3) << 3; }

__device__ __forceinline__ void mma16816(float* d, uint32_t a0, uint32_t a1,
                                         uint32_t a2, uint32_t a3,
                                         uint32_t b0, uint32_t b1) {
    asm volatile(
        "mma.sync.aligned.m16n8k16.row.col.f32.f16.f16.f32 "
        "{%0,%1,%2,%3}, {%4,%5,%6,%7}, {%8,%9}, {%0,%1,%2,%3};"
        : "+f"(d[0]), "+f"(d[1]), "+f"(d[2]), "+f"(d[3])
        : "r"(a0), "r"(a1), "r"(a2), "r"(a3), "r"(b0), "r"(b1));
}

__device__ __forceinline__ int wfidx(int wg, int nt, int ks, int lane) {
    int wgOld = wg * 2 + (nt >> 2);
    int ntOld = nt & 3;
    return (((wgOld * 8 + ks) * 4) + ntOld) * 32 + lane;
}

__device__ __forceinline__ void storeTs(uint32_t* img, int f, int t, float v,
                                        int g) {
    float vp = __shfl_xor_sync(0xffffffffu, v, 4);
    if (!(g & 1)) {
        __half2 h2;
        h2.x = __float2half(v);
        h2.y = __float2half(vp);
        img[f * PWA + (wslotA(t) ^ swz(f))] = *(uint32_t*)&h2;
    }
}

// ============================================================================
// kW: build fragment-major operand images
// ============================================================================
__global__ void kW(const float* __restrict__ cw0, const float* __restrict__ cw1,
                   const float* __restrict__ cw2,
                   const float* __restrict__ L10, const float* __restrict__ L20,
                   const float* __restrict__ L11, const float* __restrict__ L21,
                   const float* __restrict__ L12, const float* __restrict__ L22) {
    int b = blockIdx.x;
    if (b < 7) {
        int s, kk;
        if (b == 0)      { s = 0; kk = 0; }
        else if (b < 3)  { s = 1; kk = b - 1; }
        else             { s = 2; kk = b - 3; }
        const float* cw = (s == 0) ? cw0 : (s == 1) ? cw1 : cw2;
        int k = 1 << s;
        uint2* dst = g_Wf[b];
        for (int idx = threadIdx.x; idx < 4096; idx += blockDim.x) {
            int lane = idx & 31;
            int nt = (idx >> 5) & 3;
            int ks = (idx >> 7) & 7;
            int wg = idx >> 10;
            int g = lane >> 2, c = lane & 3;
            int row = wg * 32 + nt * 8 + g;
            int k0 = ks * 16 + 2 * c;
            __half2 b0, b1;
            b0.x = __float2half(cw[(row * 128 + k0) * k + kk]);
            b0.y = __float2half(cw[(row * 128 + k0 + 1) * k + kk]);
            b1.x = __float2half(cw[(row * 128 + k0 + 8) * k + kk]);
            b1.y = __float2half(cw[(row * 128 + k0 + 9) * k + kk]);
            uint2 o;
            o.x = *(uint32_t*)&b0;
            o.y = *(uint32_t*)&b1;
            dst[idx] = o;
        }
    } else {
        int j = b - 7;
        int s = j >> 1, m = j & 1;
        const float* L = (s == 0) ? (m ? L20 : L10)
                       : (s == 1) ? (m ? L21 : L11)
                                  : (m ? L22 : L12);
        int tk = 128 >> s;
        uint4* dst = g_Lf[j];
        for (int idx = threadIdx.x; idx < 2048; idx += blockDim.x) {
            int lane = idx & 31;
            int ks = (idx >> 5) & 7;
            int mt = idx >> 8;
            int g = lane >> 2, c = lane & 3;
            int r0 = mt * 16 + g, r1 = r0 + 8;
            int k0 = ks * 16 + 2 * c;
            float v[8];
#pragma unroll
            for (int e = 0; e < 8; e++) {
                int t = (e & 1) ? r1 : r0;
                int sc = k0 + ((e >> 2) << 3) + ((e >> 1) & 1);
                float vv = 0.0f;
                if ((t / tk) == (sc / tk)) {
                    int tp = t % tk, sp = sc % tk;
                    if (sp <= tp) vv = L[tp * tk + sp];
                }
                v[e] = vv;
            }
            __half2 a0, a1, a2, a3;
            a0.x = __float2half(v[0]); a0.y = __float2half(v[2]);
            a1.x = __float2half(v[1]); a1.y = __float2half(v[3]);
            a2.x = __float2half(v[4]); a2.y = __float2half(v[6]);
            a3.x = __float2half(v[5]); a3.y = __float2half(v[7]);
            uint4 o;
            o.x = *(uint32_t*)&a0;
            o.y = *(uint32_t*)&a1;
            o.z = *(uint32_t*)&a2;
            o.w = *(uint32_t*)&a3;
            dst[idx] = o;
        }
    }
}

// ============================================================================
// run_scale (unchanged from R10)
// ============================================================================
template <int TK, int MT>
__device__ __noinline__ void run_scale(
    int n0, int sbase, int q0,
    const float* __restrict__ lg, const float* __restrict__ lb,
    const uint4* __restrict__ L1f, const uint4* __restrict__ L2f,
    int hoff, const float* __restrict__ cb, float fcb, bool first) {

    constexpr int K = 128 / TK;
    constexpr int NTILE = (MT == 8) ? 2 : 1;
    extern __shared__ uint32_t smw[];
    uint32_t* X  = smw + X_OFF;
    uint32_t* HT = smw + HT_OFF;
    float* scr   = (float*)(smw + SCR_BASE);
    float* s_fcw = scr + 32;
    float* s_cb  = scr + 160;
    float* scrF  = scr + 288;

    const int tid = threadIdx.x;
    const int w = tid >> 5, lane = tid & 31;
    const int w3 = w & 3;
    const int wg = w >> 2;
    const int g = lane >> 2, c = lane & 3;
    const int c0 = wg * 64;

    int mta, mtb = 0;
    int myg;
    if (MT == 4) { mta = w3; myg = w3 >> 1; }
    else if (TK == 128) { mta = w3; mtb = 7 - w3; myg = 0; }
    else {
        mta = ((w3 >> 1) << 2) + (w3 & 1);
        mtb = ((w3 >> 1) << 2) + 3 - (w3 & 1);
        myg = w3 >> 1;
    }
    const int ks0 = (myg * TK) >> 4;

    if (first) {
        if (tid < 128) s_cb[tid] = cb[tid];
        __syncthreads();
    }

    auto rowmap = [&](int l, int kk) {
        return (TK == 128) ? (sbase * 128 + l)
                           : ((l / TK) * 128 + (l % TK) * K + kk);
    };

    float accA[8][4], accB[NTILE == 2 ? 8 : 1][4], fcT[2 * NTILE];
#pragma unroll
    for (int i = 0; i < 2 * NTILE; i++) fcT[i] = 0.0f;
#pragma unroll
    for (int nt = 0; nt < 8; nt++)
#pragma unroll
        for (int e = 0; e < 4; e++) accA[nt][e] = 0.0f;
    if (NTILE == 2) {
#pragma unroll
        for (int nt = 0; nt < 8; nt++)
#pragma unroll
            for (int e = 0; e < 4; e++) accB[nt][e] = 0.0f;
    }

    // ---------------- conv: barrier-free over K chunks ----------------
    for (int kk = 0; kk < K; kk++) {
        const uint2* Wf = g_Wf[q0 + kk];
#pragma unroll 2
        for (int ks = 0; ks < 8; ks++) {
            int off = ks * 8 + c * 2;
            uint2 vb[8];
#pragma unroll
            for (int nt = 0; nt < 8; nt++) vb[nt] = Wf[wfidx(wg, nt, ks, lane)];
            int ra0 = rowmap(mta * 16 + g, kk);
            int ra1 = rowmap(mta * 16 + g + 8, kk);
            uint2 ta0 = *(const uint2*)(X + ra0 * PWA + (off ^ swz(ra0)));
            uint2 ta1 = *(const uint2*)(X + ra1 * PWA + (off ^ swz(ra1)));
#pragma unroll
            for (int nt = 0; nt < 8; nt++)
                mma16816(accA[nt], ta0.x, ta1.x, ta0.y, ta1.y, vb[nt].x, vb[nt].y);
            if (NTILE == 2) {
                int rb0 = rowmap(mtb * 16 + g, kk);
                int rb1 = rowmap(mtb * 16 + g + 8, kk);
                uint2 tb0 = *(const uint2*)(X + rb0 * PWA + (off ^ swz(rb0)));
                uint2 tb1 = *(const uint2*)(X + rb1 * PWA + (off ^ swz(rb1)));
#pragma unroll
                for (int nt = 0; nt < 8; nt++)
                    mma16816(accB[nt], tb0.x, tb1.x, tb0.y, tb1.y, vb[nt].x, vb[nt].y);
            }
        }
    }

    // ---------------- LN stats ----------------
    float s = 0.0f, s2 = 0.0f;
#pragma unroll
    for (int ti = 0; ti < NTILE; ti++)
#pragma unroll
        for (int nt = 0; nt < 8; nt++)
#pragma unroll
            for (int e = 0; e < 4; e++) {
                int f = c0 + nt * 8 + (c << 1) + (e & 1);
                float v = (ti ? accB[nt][e] : accA[nt][e]) + s_cb[f];
                s += v; s2 += v * v;
            }
#pragma unroll
    for (int o = 16; o; o >>= 1) {
        s  += __shfl_down_sync(0xffffffffu, s, o);
        s2 += __shfl_down_sync(0xffffffffu, s2, o);
    }
    if (lane == 0) { scr[w] = s; scr[8 + w] = s2; }
    __syncthreads();

    float gs = 0.0f, gs2 = 0.0f;
#pragma unroll
    for (int p = 0; p < 8; p++) {
        int p3 = p & 3;
        int pg = (TK == 128) ? 0 : (p3 >> 1);
        if (pg == myg) { gs += scr[p]; gs2 += scr[8 + p]; }
    }
    const float inv = 1.0f / (float)(TK * 128);
    float mu = gs * inv;
    float var = gs2 * inv - mu * mu;
    float rinv = rsqrtf(var + 1e-5f);

    // ---------------- hT -> HT ; fc conv-part ----------------
#pragma unroll
    for (int ti = 0; ti < NTILE; ti++) {
        int mt = ti ? mtb : mta;
#pragma unroll
        for (int nt = 0; nt < 8; nt++)
#pragma unroll
            for (int eh = 0; eh < 2; eh++) {
                int t = mt * 16 + g + 8 * eh;
                int tl = t & (TK - 1);
                int fb = c0 + nt * 8 + (c << 1);
                float2 lgv = *(const float2*)(lg + tl * 128 + fb);
                float2 lbv = *(const float2*)(lb + tl * 128 + fb);
#pragma unroll
                for (int eo = 0; eo < 2; eo++) {
                    float v = (ti ? accB[nt][eh * 2 + eo] : accA[nt][eh * 2 + eo])
                              + s_cb[fb + eo];
                    fcT[ti * 2 + eh] += v * s_fcw[fb + eo];
                    float hh = (v - mu) * rinv * (eo ? lgv.y : lgv.x)
                               + (eo ? lbv.y : lbv.x);
                    storeTs(HT, fb + eo, t, hh, g);
                }
            }
    }
    __syncthreads();

    // ---------------- GEMM1: u = L1m @ h ----------------
#pragma unroll
    for (int nt = 0; nt < 8; nt++)
#pragma unroll
        for (int e = 0; e < 4; e++) accA[nt][e] = 0.0f;
    if (NTILE == 2) {
#pragma unroll
        for (int nt = 0; nt < 8; nt++)
#pragma unroll
            for (int e = 0; e < 4; e++) accB[nt][e] = 0.0f;
    }
    {
        int kEnd = (NTILE == 2) ? mtb : mta;
        for (int ks = ks0; ks <= kEnd; ks++) {
            int off = ks * 8 + c * 2;
            uint2 vb[8];
#pragma unroll
            for (int nt = 0; nt < 8; nt++) {
                int hr = c0 + nt * 8 + g;
                vb[nt] = *(const uint2*)(HT + hr * PWA + (off ^ swz(hr)));
            }
            if (NTILE == 2) {
                uint4 bv = L1f[(mtb * 8 + ks) * 32 + lane];
#pragma unroll
                for (int nt = 0; nt < 8; nt++)
                    mma16816(accB[nt], bv.x, bv.y, bv.z, bv.w, vb[nt].x, vb[nt].y);
            }
            if (ks <= mta) {
                uint4 av = L1f[(mta * 8 + ks) * 32 + lane];
#pragma unroll
                for (int nt = 0; nt < 8; nt++)
                    mma16816(accA[nt], av.x, av.y, av.z, av.w, vb[nt].x, vb[nt].y);
            }
        }
    }
    __syncthreads();

    // ---------------- uT = hsw(u) -> HT ----------------
#pragma unroll
    for (int ti = 0; ti < NTILE; ti++) {
        int mt = ti ? mtb : mta;
#pragma unroll
        for (int nt = 0; nt < 8; nt++)
#pragma unroll
            for (int e = 0; e < 4; e++) {
                int t = mt * 16 + g + ((e >> 1) << 3);
                int f = c0 + nt * 8 + (c << 1) + (e & 1);
                storeTs(HT, f, t, hswf(ti ? accB[nt][e] : accA[nt][e]), g);
            }
    }
    __syncthreads();

    // ---------------- GEMM2: v = L2m @ u ; fc v-part ----------------
#pragma unroll
    for (int nt = 0; nt < 8; nt++)
#pragma unroll
        for (int e = 0; e < 4; e++) accA[nt][e] = 0.0f;
    if (NTILE == 2) {
#pragma unroll
        for (int nt = 0; nt < 8; nt++)
#pragma unroll
            for (int e = 0; e < 4; e++) accB[nt][e] = 0.0f;
    }
    {
        int kEnd = (NTILE == 2) ? mtb : mta;
        for (int ks = ks0; ks <= kEnd; ks++) {
            int off = ks * 8 + c * 2;
            uint2 vb[8];
#pragma unroll
            for (int nt = 0; nt < 8; nt++) {
                int hr = c0 + nt * 8 + g;
                vb[nt] = *(const uint2*)(HT + hr * PWA + (off ^ swz(hr)));
            }
            if (NTILE == 2) {
                uint4 bv = L2f[(mtb * 8 + ks) * 32 + lane];
#pragma unroll
                for (int nt = 0; nt < 8; nt++)
                    mma16816(accB[nt], bv.x, bv.y, bv.z, bv.w, vb[nt].x, vb[nt].y);
            }
            if (ks <= mta) {
                uint4 av = L2f[(mta * 8 + ks) * 32 + lane];
#pragma unroll
                for (int nt = 0; nt < 8; nt++)
                    mma16816(accA[nt], av.x, av.y, av.z, av.w, vb[nt].x, vb[nt].y);
            }
        }
    }
#pragma unroll
    for (int ti = 0; ti < NTILE; ti++)
#pragma unroll
        for (int nt = 0; nt < 8; nt++)
#pragma unroll
            for (int e = 0; e < 4; e++) {
                int f = c0 + nt * 8 + (c << 1) + (e & 1);
                fcT[ti * 2 + (e >> 1)] +=
                    (ti ? accB[nt][e] : accA[nt][e]) * s_fcw[f];
            }

    // ---------------- fc reduce -> g_h ----------------
#pragma unroll
    for (int i = 0; i < 2 * NTILE; i++) {
        fcT[i] += __shfl_xor_sync(0xffffffffu, fcT[i], 1);
        fcT[i] += __shfl_xor_sync(0xffffffffu, fcT[i], 2);
    }
    if (c == 0) {
#pragma unroll
        for (int i = 0; i < 2 * NTILE; i++) {
            int t = ((i >> 1) ? mtb : mta) * 16 + g + 8 * (i & 1);
            scrF[wg * 128 + t] = fcT[i];
        }
    }
    __syncthreads();
    if (tid < MT * 16) {
        int t = tid;
        float d = scrF[t] + scrF[128 + t];
        g_h[(n0 + sbase + t / TK) * 224 + hoff + (t & (TK - 1))] = d + fcb;
    }
    __syncthreads();
}

__global__ void __launch_bounds__(NTH, 2) kA11(
    const float* __restrict__ x,
    const float* __restrict__ cb0, const float* __restrict__ lg0,
    const float* __restrict__ lb0,
    const float* __restrict__ cb1, const float* __restrict__ lg1,
    const float* __restrict__ lb1,
    const float* __restrict__ cb2, const float* __restrict__ lg2,
    const float* __restrict__ lb2,
    const float* __restrict__ fcw, const float* __restrict__ fcbp) {
    extern __shared__ uint32_t smw[];
    uint32_t* X = smw + X_OFF;
    float* scr = (float*)(smw + SCR_BASE);
    const int tid = threadIdx.x;
    if (tid < 128) scr[32 + tid] = fcw[tid];
    float fcb = fcbp[0];
    int n0 = blockIdx.x * 2;

    // ---- build X once ----
#pragma unroll 4
    for (int it = 0; it < 32; it++) {
        int idx = it * 256 + tid;
        int r = idx >> 5, f4 = idx & 31;
        const float4 v = ((const float4*)(x +
            ((size_t)(n0 + (r >> 7)) * 128 + (r & 127)) * 128))[f4];
        __half2 h0, h1;
        h0.x = __float2half(v.x); h0.y = __float2half(v.y);
        h1.x = __float2half(v.z); h1.y = __float2half(v.w);
        int k2 = f4 << 2;
        int sw = swz(r);
        X[r * PWA + (wslotA(k2) ^ sw)]     = *(uint32_t*)&h0;
        X[r * PWA + (wslotA(k2 + 2) ^ sw)] = *(uint32_t*)&h1;
    }
    __syncthreads();

    run_scale<128, 8>(n0, 0, 0, lg0, lb0, g_Lf[0], g_Lf[1], 0, cb0, fcb, true);
    run_scale<128, 8>(n0, 1, 0, lg0, lb0, g_Lf[0], g_Lf[1], 0, cb0, fcb, false);
    run_scale<64, 8>(n0, 0, 1, lg1, lb1, g_Lf[2], g_Lf[3], 128, cb1, fcb, true);
    run_scale<32, 4>(n0, 0, 3, lg2, lb2, g_Lf[4], g_Lf[5], 192, cb2, fcb, true);

    // ---- fused kB1 ----
    float s = 0.0f, s2 = 0.0f;
    for (int i = tid; i < 448; i += 256) {
        float v = g_h[n0 * 224 + i];
        s += v; s2 += v * v;
    }
#pragma unroll
    for (int o = 16; o; o >>= 1) {
        s  += __shfl_down_sync(0xffffffffu, s, o);
        s2 += __shfl_down_sync(0xffffffffu, s2, o);
    }
    float* scrR = scr + 288;
    int wI = tid >> 5, lI = tid & 31;
    if (lI == 0) { scrR[wI] = s; scrR[8 + wI] = s2; }
    __syncthreads();
    if (tid == 0) {
        float a = 0.0f, b = 0.0f;
#pragma unroll
        for (int i = 0; i < 8; i++) { a += scrR[i]; b += scrR[8 + i]; }
        g_bpart[blockIdx.x] = a;
        g_bpart[2048 + blockIdx.x] = b;
    }
}

// ============================================================================
// phase 2
// ============================================================================
__device__ __forceinline__ void bred2(float& s, float& s2, float* scr) {
#pragma unroll
    for (int o = 16; o > 0; o >>= 1) {
        s  += __shfl_down_sync(0xffffffffu, s, o);
        s2 += __shfl_down_sync(0xffffffffu, s2, o);
    }
    int w = threadIdx.x >> 5, l = threadIdx.x & 31;
    if (l == 0) { scr[w] = s; scr[32 + w] = s2; }
    __syncthreads();
    if (threadIdx.x == 0) {
        float a = 0.f, b = 0.f;
        int nw = (blockDim.x + 31) >> 5;
        for (int i = 0; i < nw; i++) { a += scr[i]; b += scr[32 + i]; }
        scr[0] = a; scr[32] = b;
    }
    __syncthreads();
    s = scr[0]; s2 = scr[32];
}

__global__ void kB2() {
    float s = 0.0f, s2 = 0.0f;
#pragma unroll
    for (int k = 0; k < 8; k++) {
        int i = threadIdx.x + 256 * k;
        s  += g_bpart[i];
        s2 += g_bpart[2048 + i];
    }
    __shared__ float scr[64];
    bred2(s, s2, scr);
    if (threadIdx.x == 0) {
        const float inv = 1.0f / (4096.0f * 224.0f);
        float mu = s * inv;
        float var = s2 * inv - mu * mu;
        g_stats[0] = mu;
        g_stats[1] = rsqrtf(var + 1e-5f);
    }
}

// kC1: grid=256 blocks, 16 n-rows each; M1 tile staged in smem.
__global__ void kC1(const float* __restrict__ M1,
                    const float* __restrict__ slg,
                    const float* __restrict__ slb) {
    __shared__ float sM1[64 * 16];
    int j = threadIdx.x;                // 0..223
    int b = blockIdx.x;                 // 0..255
    int n0 = b * 16;
    for (int i = j; i < 1024; i += 224) {
        int m = i >> 4, nn = i & 15;
        sM1[i] = M1[m * 4096 + n0 + nn];
    }
    __syncthreads();
    float mu = g_stats[0], rinv = g_stats[1];
    float acc[64];
#pragma unroll
    for (int m = 0; m < 64; m++) acc[m] = 0.f;
#pragma unroll 2
    for (int nn = 0; nn < 16; nn++) {
        int off = (n0 + nn) * 224 + j;
        float hn = (g_h[off] - mu) * rinv * slg[off] + slb[off];
#pragma unroll
        for (int m = 0; m < 64; m++) acc[m] += sM1[m * 16 + nn] * hn;
    }
#pragma unroll
    for (int m = 0; m < 64; m++) g_cpart[(b * 64 + m) * 224 + j] = acc[m];
}

// kC2: reduce 256 partials, hardswish, contract with w2
__global__ void kC2(const float* __restrict__ smw_) {
    int m = blockIdx.x, j = threadIdx.x;
    float g = 0.f;
    for (int b = 0; b < 256; b++) g += g_cpart[(b * 64 + m) * 224 + j];
    float v = hswf(g) * smw_[224 + j];
    float dummy = 0.f;
    __shared__ float scr[64];
    bred2(v, dummy, scr);
    if (threadIdx.x == 0) g_gw[m] = v;
}

__global__ void kD(const float* __restrict__ M2,
                   const float* __restrict__ smw_,
                   const float* __restrict__ smb,
                   float* __restrict__ out) {
    int warp = threadIdx.x >> 5, lane = threadIdx.x & 31;
    int n = blockIdx.x * 8 + warp;
    float acc = 0.f;
    for (int j = lane; j < 224; j += 32)
        acc += g_h[n * 224 + j] * (smw_[j] + smw_[224 + j]);
    for (int m = lane; m < 64; m += 32)
        acc += M2[n * 64 + m] * g_gw[m];
#pragma unroll
    for (int o = 16; o > 0; o >>= 1)
        acc += __shfl_down_sync(0xffffffffu, acc, o);
    if (lane == 0) out[n] = acc + smb[0];
}

// ============================================================================
extern "C" void kernel_launch(void* const* d_in, const int* in_sizes, int n_in,
                              void* d_out, int out_size) {
    const float* x   = (const float*)d_in[0];
    const float* cw0 = (const float*)d_in[1];
    const float* cb0 = (const float*)d_in[2];
    const float* lg0 = (const float*)d_in[3];
    const float* lb0 = (const float*)d_in[4];
    const float* L10 = (const float*)d_in[5];
    const float* L20 = (const float*)d_in[6];
    const float* cw1 = (const float*)d_in[7];
    const float* cb1 = (const float*)d_in[8];
    const float* lg1 = (const float*)d_in[9];
    const float* lb1 = (const float*)d_in[10];
    const float* L11 = (const float*)d_in[11];
    const float* L21 = (const float*)d_in[12];
    const float* cw2 = (const float*)d_in[13];
    const float* cb2 = (const float*)d_in[14];
    const float* lg2 = (const float*)d_in[15];
    const float* lb2 = (const float*)d_in[16];
    const float* L12 = (const float*)d_in[17];
    const float* L22 = (const float*)d_in[18];
    const float* fcw = (const float*)d_in[19];
    const float* fcb = (const float*)d_in[20];
    const float* slg = (const float*)d_in[21];
    const float* slb = (const float*)d_in[22];
    const float* M1  = (const float*)d_in[23];
    const float* M2  = (const float*)d_in[24];
    const float* smw = (const float*)d_in[25];
    const float* smb = (const float*)d_in[26];
    float* out = (float*)d_out;

    cudaFuncSetAttribute(kA11, cudaFuncAttributeMaxDynamicSharedMemorySize,
                         SMEM_SZ);

    kW<<<13, 256>>>(cw0, cw1, cw2, L10, L20, L11, L21, L12, L22);
    kA11<<<2048, NTH, SMEM_SZ>>>(x, cb0, lg0, lb0, cb1, lg1, lb1,
                                 cb2, lg2, lb2, fcw, fcb);
    kB2<<<1, 256>>>();
    kC1<<<256, 224>>>(M1, slg, slb);
    kC2<<<64, 224>>>(smw);
    kD<<<512, 256>>>(M2, smw, smb, out);
}